// round 13
// baseline (speedup 1.0000x reference)
#include <cuda_runtime.h>
#include <cuda_fp16.h>
#include <math.h>
#include <stdint.h>

// ---------------- problem constants ----------------
#define Bn   32
#define Cn   256
#define Hn   28
#define Wn   28
#define Pn   784          // H*W
#define NKn  196          // (H/2)*(W/2)
#define HKn  14
#define CMn  1024         // C * R
#define NH   8
#define DKn  32
#define EPSf 1e-5f

// ---------------- scratch (device globals; padded for unguarded tile loads) ----------------
__device__ float   g_x1 [Bn*Cn*Pn + 256];        // LPU out fp32 (O-proj flat residual)
__device__ __half2 g_x1h[Bn*(Cn/2)*Pn + 512];    // LPU out fp16 channel-paired
__device__ __half2 g_kvh[Bn*(Cn/2)*NKn + 512];   // KV downsample fp16 channel-paired
__device__ float   g_x2 [Bn*Cn*Pn + 256];        // attn residual out fp32 (c1 B, c2 residual)
__device__ __half  g_qh [Bn*Pn*Cn + 512];        // Q fp16 row-major [p][oc]
__device__ __half  g_kh [Bn*NKn*Cn + 512];       // K fp16 [nk][256]
__device__ __half  g_vh [Bn*NKn*Cn + 512];       // V fp16 [nk][256]
__device__ __half2 g_attTh[Bn*(Cn/2)*Pn + 512];  // attn out, channel-paired
__device__ __half2 g_t1h  [Bn*(CMn/2)*Pn + 512]; // c1 out, channel-paired
__device__ __half2 g_t2h  [Bn*(CMn/2)*Pn + 512]; // dw2 out, channel-paired
__device__ __half2 g_wqh[(Cn/2)*Cn];             // weights k-paired [k/2][m]
__device__ __half2 g_wkh[(Cn/2)*Cn];
__device__ __half2 g_wvh[(Cn/2)*Cn];
__device__ __half2 g_woh[(Cn/2)*Cn];
__device__ __half2 g_c1h[(Cn/2)*CMn];
__device__ __half2 g_c2h[(CMn/2)*Cn];
__device__ float   g_sq [Cn];                    // rowsum(wq)
__device__ float2  g_partl[Bn*(Cn/2)];           // LN1 partials (per pair-plane)
__device__ float2  g_parto[Bn*7];                // LN2 partials
__device__ float2  g_mr  [Bn];

__device__ __forceinline__ float gelu_f(float v) {
    return 0.5f * v * (1.0f + erff(v * 0.7071067811865475f));
}
__device__ __forceinline__ void mma_f16(float* c, const uint32_t* a, const uint32_t* b) {
    asm volatile(
        "mma.sync.aligned.m16n8k16.row.col.f32.f16.f16.f32 "
        "{%0,%1,%2,%3}, {%4,%5,%6,%7}, {%8,%9}, {%0,%1,%2,%3};"
        : "+f"(c[0]), "+f"(c[1]), "+f"(c[2]), "+f"(c[3])
        : "r"(a[0]), "r"(a[1]), "r"(a[2]), "r"(a[3]), "r"(b[0]), "r"(b[1]));
}
__device__ __forceinline__ uint32_t packh2(float lo, float hi) {
    __half2 h = __floats2half2_rn(lo, hi);
    return *(uint32_t*)&h;
}

// 512-thread GEMM: tile 256(M) x 128(P), 16 warps (4m x 4n of 64x32 warptiles)
#define ASTR 264            // A stage row stride (half2): 264 % 32 == 8 -> conflict-free
#define BSTR 136
#define ASTAGE (16*ASTR)
#define BSTAGE (16*BSTR)
#define STG (ASTAGE+BSTAGE) // 6400 half2 per stage
#define SMEM_MMA (2*STG*4)  // 51200 B
#define KQ 260              // epilogue [p][m] float stride
#define KM 132              // epilogue [m][p] float stride

// ====================== k_mma (512 thr): O-proj / c1 / c2 ======================
// MODE 1: f32 out[p*M+m] = acc + bias + res (flat residual); LN2 partials -> pstat[b*7+bx]
// MODE 2: half2 out[(m/2)*P+p] = gelu(BN(acc + bias)); B = fp32 + LN in loader
// MODE 3: f32 out[m*P+p] = BN(acc + bias) + res
template <int MODE, bool LNB, bool BH>
__global__ void __launch_bounds__(512, 1) k_mma(
    const __half2* __restrict__ Wh, const void* __restrict__ Xv,
    const float* __restrict__ bias,
    const float* __restrict__ bng, const float* __restrict__ bnb,
    const float* __restrict__ bnm, const float* __restrict__ bnv,
    const float2* __restrict__ mr, const float* __restrict__ res,
    float2* __restrict__ pstat,
    void* __restrict__ outv, int M, int K, int P) {
    extern __shared__ float sm[];
    const int tid  = threadIdx.x;
    const int warp = tid >> 5, lane = tid & 31;
    const int gid = lane >> 2, tq = lane & 3;
    const int wm = (warp & 3) * 64;
    const int wn = (warp >> 2) * 32;
    const int b  = blockIdx.z;
    const int m0 = blockIdx.y * 256;
    const int n0 = blockIdx.x * 128;
    const float*   Xf  = BH ? nullptr : (const float*)Xv + (size_t)b * K * P;
    const __half2* Xh2 = BH ? (const __half2*)Xv + (size_t)b * (K >> 1) * P : nullptr;
    float mean = 0.f, rstd = 1.f;
    if (LNB) { float2 v = mr[b]; mean = v.x; rstd = v.y; }

    float acc[4][4][4];
#pragma unroll
    for (int i = 0; i < 4; i++)
#pragma unroll
        for (int j = 0; j < 4; j++)
#pragma unroll
            for (int r = 0; r < 4; r++) acc[i][j][r] = 0.f;

    const int ka = tid >> 5;          // 0..15 A k-pair row
    const int ma = (tid & 31) * 8;    // 0..248 A col
    const int kb = (tid & 255) >> 4;  // 0..15 B k-pair row (tid<256 active)
    const int pq = (tid & 15) * 8;    // 0..120 B col
    const bool bAct = tid < 256;
    uint4 pa0, pa1, pb0, pb1;
    const int T = K >> 5;

    auto load_chunk = [&](int kc0) {
        const uint4* wr = (const uint4*)(Wh + (size_t)((kc0 >> 1) + ka) * M + m0 + ma);
        pa0 = wr[0]; pa1 = wr[1];
        if (bAct) {
            if (BH) {
                const uint4* xr = (const uint4*)(Xh2 + (size_t)((kc0 >> 1) + kb) * P + n0 + pq);
                pb0 = xr[0]; pb1 = xr[1];
            } else {
                const float* xr0 = Xf + (size_t)(kc0 + 2 * kb) * P + n0 + pq;
                const float* xr1 = xr0 + P;
                float4 b0 = *(const float4*)xr0;
                float4 b1 = *(const float4*)(xr0 + 4);
                float4 b2 = *(const float4*)xr1;
                float4 b3 = *(const float4*)(xr1 + 4);
                if (LNB) {
                    b0.x=(b0.x-mean)*rstd; b0.y=(b0.y-mean)*rstd; b0.z=(b0.z-mean)*rstd; b0.w=(b0.w-mean)*rstd;
                    b1.x=(b1.x-mean)*rstd; b1.y=(b1.y-mean)*rstd; b1.z=(b1.z-mean)*rstd; b1.w=(b1.w-mean)*rstd;
                    b2.x=(b2.x-mean)*rstd; b2.y=(b2.y-mean)*rstd; b2.z=(b2.z-mean)*rstd; b2.w=(b2.w-mean)*rstd;
                    b3.x=(b3.x-mean)*rstd; b3.y=(b3.y-mean)*rstd; b3.z=(b3.z-mean)*rstd; b3.w=(b3.w-mean)*rstd;
                }
                pb0 = make_uint4(packh2(b0.x, b2.x), packh2(b0.y, b2.y),
                                 packh2(b0.z, b2.z), packh2(b0.w, b2.w));
                pb1 = make_uint4(packh2(b1.x, b3.x), packh2(b1.y, b3.y),
                                 packh2(b1.z, b3.z), packh2(b1.w, b3.w));
            }
        }
    };
    auto store_chunk = [&](int s) {
        __half2* As2 = (__half2*)sm + s * STG;
        __half2* Bs2 = As2 + ASTAGE;
        *(uint4*)&As2[ka * ASTR + ma]     = pa0;
        *(uint4*)&As2[ka * ASTR + ma + 4] = pa1;
        if (bAct) {
            *(uint4*)&Bs2[kb * BSTR + pq]     = pb0;
            *(uint4*)&Bs2[kb * BSTR + pq + 4] = pb1;
        }
    };

    load_chunk(0);
    store_chunk(0);
    __syncthreads();

    for (int t = 0; t < T; t++) {
        if (t + 1 < T) load_chunk((t + 1) << 5);
        const __half2* As2 = (const __half2*)sm + (t & 1) * STG;
        const __half2* Bs2 = As2 + ASTAGE;
#pragma unroll
        for (int ks = 0; ks < 2; ks++) {
            const int r0 = ks * 8;
            uint32_t af[4][4], bf[4][2];
#pragma unroll
            for (int i = 0; i < 4; i++) {
                int m = wm + i * 16 + gid;
                af[i][0] = *(uint32_t*)&As2[(r0 + tq) * ASTR + m];
                af[i][1] = *(uint32_t*)&As2[(r0 + tq) * ASTR + m + 8];
                af[i][2] = *(uint32_t*)&As2[(r0 + tq + 4) * ASTR + m];
                af[i][3] = *(uint32_t*)&As2[(r0 + tq + 4) * ASTR + m + 8];
            }
#pragma unroll
            for (int j = 0; j < 4; j++) {
                int p = wn + j * 8 + gid;
                bf[j][0] = *(uint32_t*)&Bs2[(r0 + tq) * BSTR + p];
                bf[j][1] = *(uint32_t*)&Bs2[(r0 + tq + 4) * BSTR + p];
            }
#pragma unroll
            for (int i = 0; i < 4; i++)
#pragma unroll
                for (int j = 0; j < 4; j++) mma_f16(acc[i][j], af[i], bf[j]);
        }
        if (t + 1 < T) {
            store_chunk((t + 1) & 1);
            __syncthreads();
        }
    }

    // ---- epilogue: 4 staged passes ----
    float* sD = sm;
    float*   outf  = (MODE == 1 || MODE == 3) ? (float*)outv + (size_t)b * (size_t)M * P : nullptr;
    __half2* outh2 = (MODE == 2) ? (__half2*)outv + (size_t)b * (size_t)(M >> 1) * P : nullptr;
    const float* resb = (MODE == 1 || MODE == 3) ? res + (size_t)b * (size_t)M * P : nullptr;
    float osum = 0.f, osq = 0.f;

#pragma unroll
    for (int pass = 0; pass < 4; pass++) {
        __syncthreads();
        if (MODE == 1) {
            // [p][m] staging: 32 p-rows x 256 m; warps with (warp>>2)==pass own it
            if ((warp >> 2) == pass) {
#pragma unroll
                for (int i = 0; i < 4; i++) {
                    int mrow = wm + i * 16 + gid;
#pragma unroll
                    for (int j = 0; j < 4; j++) {
                        int pc = j * 8 + 2 * tq;
                        sD[pc * KQ + mrow]           = acc[i][j][0];
                        sD[(pc + 1) * KQ + mrow]     = acc[i][j][1];
                        sD[pc * KQ + mrow + 8]       = acc[i][j][2];
                        sD[(pc + 1) * KQ + mrow + 8] = acc[i][j][3];
                    }
                }
            }
        } else {
            // [m][p] staging: 64 m-rows x 128 p; warps with (warp&3)==pass own it
            if ((warp & 3) == pass) {
#pragma unroll
                for (int i = 0; i < 4; i++) {
                    int ml = i * 16 + gid;
#pragma unroll
                    for (int j = 0; j < 4; j++) {
                        int pc = wn + j * 8 + 2 * tq;
                        sD[ml * KM + pc]           = acc[i][j][0];
                        sD[ml * KM + pc + 1]       = acc[i][j][1];
                        sD[(ml + 8) * KM + pc]     = acc[i][j][2];
                        sD[(ml + 8) * KM + pc + 1] = acc[i][j][3];
                    }
                }
            }
        }
        __syncthreads();
        if (MODE == 1) {
            for (int l = tid; l < 32 * 64; l += 512) {
                int rl = l >> 6, cq = (l & 63) * 4;
                int p = n0 + pass * 32 + rl;
                if (p >= P) continue;
                float4 v = *(float4*)&sD[rl * KQ + cq];
                float4 bb = *(const float4*)(bias + m0 + cq);
                v.x += bb.x; v.y += bb.y; v.z += bb.z; v.w += bb.w;
                size_t off = (size_t)p * M + m0 + cq;
                float4 rr = *(const float4*)(resb + off);
                v.x += rr.x; v.y += rr.y; v.z += rr.z; v.w += rr.w;
                *(float4*)(outf + off) = v;
                osum += v.x + v.y + v.z + v.w;
                osq  += v.x * v.x + v.y * v.y + v.z * v.z + v.w * v.w;
            }
        } else if (MODE == 2) {
            for (int l = tid; l < 32 * 32; l += 512) {
                int rp = l >> 5, cq = (l & 31) * 4;
                int m = m0 + pass * 64 + 2 * rp;
                int p = n0 + cq;
                if (p >= P) continue;
                float sc0 = bng[m] * rsqrtf(bnv[m] + EPSf);
                float sh0 = bnb[m] - bnm[m] * sc0 + bias[m] * sc0;
                float sc1 = bng[m + 1] * rsqrtf(bnv[m + 1] + EPSf);
                float sh1 = bnb[m + 1] - bnm[m + 1] * sc1 + bias[m + 1] * sc1;
                float4 v0 = *(float4*)&sD[(2 * rp) * KM + cq];
                float4 v1 = *(float4*)&sD[(2 * rp + 1) * KM + cq];
                v0.x = gelu_f(v0.x * sc0 + sh0); v0.y = gelu_f(v0.y * sc0 + sh0);
                v0.z = gelu_f(v0.z * sc0 + sh0); v0.w = gelu_f(v0.w * sc0 + sh0);
                v1.x = gelu_f(v1.x * sc1 + sh1); v1.y = gelu_f(v1.y * sc1 + sh1);
                v1.z = gelu_f(v1.z * sc1 + sh1); v1.w = gelu_f(v1.w * sc1 + sh1);
                uint4 u = make_uint4(packh2(v0.x, v1.x), packh2(v0.y, v1.y),
                                     packh2(v0.z, v1.z), packh2(v0.w, v1.w));
                *(uint4*)(outh2 + (size_t)(m >> 1) * P + p) = u;
            }
        } else {
            for (int l = tid; l < 64 * 32; l += 512) {
                int rl = l >> 5, cq = (l & 31) * 4;
                int m = m0 + pass * 64 + rl;
                int p = n0 + cq;
                if (p >= P) continue;
                float scale = bng[m] * rsqrtf(bnv[m] + EPSf);
                float shift = bnb[m] - bnm[m] * scale + bias[m] * scale;
                float4 v = *(float4*)&sD[rl * KM + cq];
                v.x = v.x * scale + shift; v.y = v.y * scale + shift;
                v.z = v.z * scale + shift; v.w = v.w * scale + shift;
                size_t off = (size_t)m * P + p;
                float4 rr = *(const float4*)(resb + off);
                v.x += rr.x; v.y += rr.y; v.z += rr.z; v.w += rr.w;
                *(float4*)(outf + off) = v;
            }
        }
    }

    if (MODE == 1) {
        __syncthreads();
        float* r1 = sm;
        float* r2 = sm + 512;
        r1[tid] = osum; r2[tid] = osq;
        __syncthreads();
        for (int st = 256; st > 0; st >>= 1) {
            if (tid < st) { r1[tid] += r1[tid + st]; r2[tid] += r2[tid + st]; }
            __syncthreads();
        }
        if (tid == 0)
            pstat[b * 7 + blockIdx.x] = make_float2(r1[0], r2[0]);
    }
}

// ====================== merged QKV (512 thr, raw fp16 B, LN folded for Q) ======================
__global__ void __launch_bounds__(512, 1) k_qkv(
    const __half2* __restrict__ wqh, const __half2* __restrict__ wkh,
    const __half2* __restrict__ wvh,
    const __half2* __restrict__ x1h, const __half2* __restrict__ kvh,
    const float* __restrict__ bq, const float* __restrict__ bk,
    const float* __restrict__ bv, const float2* __restrict__ mr,
    const float* __restrict__ sq,
    __half* __restrict__ qh, __half* __restrict__ kh, __half* __restrict__ vh) {
    extern __shared__ float sm[];
    const int tid  = threadIdx.x;
    const int warp = tid >> 5, lane = tid & 31;
    const int gid = lane >> 2, tq = lane & 3;
    const int wm = (warp & 3) * 64;
    const int wn = (warp >> 2) * 32;
    const int b  = blockIdx.z;
    const int id = blockIdx.x;  // 0..10

    const __half2* Wh;
    const __half2* Xh2;
    const float* bias;
    __half* outp;
    int P, n0;
    bool isQ = false;
    if (id < 7) {
        Wh = wqh; Xh2 = x1h + (size_t)b * (Cn / 2) * Pn; bias = bq;
        outp = qh + (size_t)b * Pn * Cn;
        P = Pn; isQ = true; n0 = id * 128;
    } else if (id < 9) {
        Wh = wkh; Xh2 = kvh + (size_t)b * (Cn / 2) * NKn; bias = bk;
        outp = kh + (size_t)b * NKn * Cn;
        P = NKn; n0 = (id - 7) * 128;
    } else {
        Wh = wvh; Xh2 = kvh + (size_t)b * (Cn / 2) * NKn; bias = bv;
        outp = vh + (size_t)b * NKn * Cn;
        P = NKn; n0 = (id - 9) * 128;
    }

    float acc[4][4][4];
#pragma unroll
    for (int i = 0; i < 4; i++)
#pragma unroll
        for (int j = 0; j < 4; j++)
#pragma unroll
            for (int r = 0; r < 4; r++) acc[i][j][r] = 0.f;

    const int ka = tid >> 5;
    const int ma = (tid & 31) * 8;
    const int kb = (tid & 255) >> 4;
    const int pq = (tid & 15) * 8;
    const bool bAct = tid < 256;
    uint4 pa0, pa1, pb0, pb1;
    const int T = Cn >> 5;  // 8

    auto load_chunk = [&](int kp0) {
        const uint4* wr = (const uint4*)(Wh + (size_t)(kp0 + ka) * Cn + ma);
        pa0 = wr[0]; pa1 = wr[1];
        if (bAct) {
            const uint4* xr = (const uint4*)(Xh2 + (size_t)(kp0 + kb) * P + n0 + pq);
            pb0 = xr[0]; pb1 = xr[1];
        }
    };
    auto store_chunk = [&](int s) {
        __half2* As2 = (__half2*)sm + s * STG;
        __half2* Bs2 = As2 + ASTAGE;
        *(uint4*)&As2[ka * ASTR + ma]     = pa0;
        *(uint4*)&As2[ka * ASTR + ma + 4] = pa1;
        if (bAct) {
            *(uint4*)&Bs2[kb * BSTR + pq]     = pb0;
            *(uint4*)&Bs2[kb * BSTR + pq + 4] = pb1;
        }
    };

    load_chunk(0);
    store_chunk(0);
    __syncthreads();

    for (int t = 0; t < T; t++) {
        if (t + 1 < T) load_chunk((t + 1) << 4);
        const __half2* As2 = (const __half2*)sm + (t & 1) * STG;
        const __half2* Bs2 = As2 + ASTAGE;
#pragma unroll
        for (int ks = 0; ks < 2; ks++) {
            const int r0 = ks * 8;
            uint32_t af[4][4], bf[4][2];
#pragma unroll
            for (int i = 0; i < 4; i++) {
                int m = wm + i * 16 + gid;
                af[i][0] = *(uint32_t*)&As2[(r0 + tq) * ASTR + m];
                af[i][1] = *(uint32_t*)&As2[(r0 + tq) * ASTR + m + 8];
                af[i][2] = *(uint32_t*)&As2[(r0 + tq + 4) * ASTR + m];
                af[i][3] = *(uint32_t*)&As2[(r0 + tq + 4) * ASTR + m + 8];
            }
#pragma unroll
            for (int j = 0; j < 4; j++) {
                int p = wn + j * 8 + gid;
                bf[j][0] = *(uint32_t*)&Bs2[(r0 + tq) * BSTR + p];
                bf[j][1] = *(uint32_t*)&Bs2[(r0 + tq + 4) * BSTR + p];
            }
#pragma unroll
            for (int i = 0; i < 4; i++)
#pragma unroll
                for (int j = 0; j < 4; j++) mma_f16(acc[i][j], af[i], bf[j]);
        }
        if (t + 1 < T) {
            store_chunk((t + 1) & 1);
            __syncthreads();
        }
    }

    float scl = 1.f, moff = 0.f;
    if (isQ) { float2 v = mr[b]; scl = v.y; moff = -v.x * v.y; }

    float* sD = sm;
#pragma unroll
    for (int pass = 0; pass < 4; pass++) {
        __syncthreads();
        if ((warp >> 2) == pass) {
#pragma unroll
            for (int i = 0; i < 4; i++) {
                int mrow = wm + i * 16 + gid;
#pragma unroll
                for (int j = 0; j < 4; j++) {
                    int pc = j * 8 + 2 * tq;
                    sD[pc * KQ + mrow]           = acc[i][j][0];
                    sD[(pc + 1) * KQ + mrow]     = acc[i][j][1];
                    sD[pc * KQ + mrow + 8]       = acc[i][j][2];
                    sD[(pc + 1) * KQ + mrow + 8] = acc[i][j][3];
                }
            }
        }
        __syncthreads();
        for (int l = tid; l < 32 * 64; l += 512) {
            int rl = l >> 6, cq = (l & 63) * 4;
            int p = n0 + pass * 32 + rl;
            if (p >= P) continue;
            float4 v = *(float4*)&sD[rl * KQ + cq];
            float4 bb = *(const float4*)(bias + cq);
            if (isQ) {
                float4 ss = *(const float4*)(sq + cq);
                v.x = v.x * scl + bb.x + moff * ss.x;
                v.y = v.y * scl + bb.y + moff * ss.y;
                v.z = v.z * scl + bb.z + moff * ss.z;
                v.w = v.w * scl + bb.w + moff * ss.w;
            } else {
                v.x += bb.x; v.y += bb.y; v.z += bb.z; v.w += bb.w;
            }
            __half2 h01 = __floats2half2_rn(v.x, v.y);
            __half2 h23 = __floats2half2_rn(v.z, v.w);
            uint2 u = make_uint2(*(uint32_t*)&h01, *(uint32_t*)&h23);
            *(uint2*)(outp + (size_t)p * Cn + cq) = u;
        }
    }
}

// ---------------- merged weight pack ----------------
__global__ void k_wpack_all(
    const float* __restrict__ wq, const float* __restrict__ wk,
    const float* __restrict__ wv, const float* __restrict__ wo,
    const float* __restrict__ c1w, const float* __restrict__ c2w,
    __half2* __restrict__ oq, __half2* __restrict__ ok,
    __half2* __restrict__ ov, __half2* __restrict__ oo,
    __half2* __restrict__ oc1, __half2* __restrict__ oc2) {
    __shared__ float t[32][33];
    int id = blockIdx.x;
    const float* in;
    __half2* out;
    int M, K, tile;
    if (id < 256) {
        int w = id >> 6; tile = id & 63;
        in  = (w == 0) ? wq : (w == 1) ? wk : (w == 2) ? wv : wo;
        out = (w == 0) ? oq : (w == 1) ? ok : (w == 2) ? ov : oo;
        M = Cn; K = Cn;
    } else if (id < 512) {
        tile = id - 256;
        in = c1w; out = oc1; M = CMn; K = Cn;
    } else {
        tile = id - 512;
        in = c2w; out = oc2; M = Cn; K = CMn;
    }
    int ktiles = K >> 5;
    int m0 = (tile / ktiles) * 32, k0 = (tile % ktiles) * 32;
    int tx = threadIdx.x, ty = threadIdx.y;
#pragma unroll
    for (int q = 0; q < 32; q += 8)
        t[ty + q][tx] = in[(size_t)(m0 + ty + q) * K + k0 + tx];
    __syncthreads();
#pragma unroll
    for (int q = 0; q < 2; q++) {
        int kp = ty + q * 8;
        __half2 val = __floats2half2_rn(t[tx][2 * kp], t[tx][2 * kp + 1]);
        out[(size_t)((k0 >> 1) + kp) * M + m0 + tx] = val;
    }
}

// ---------------- rowsum of wq (deterministic) ----------------
__global__ void k_rowsum_q(const float* __restrict__ wq, float* __restrict__ sq) {
    int w = (blockIdx.x * 256 + threadIdx.x) >> 5;   // 0..255
    int lane = threadIdx.x & 31;
    const float* row = wq + (size_t)w * Cn;
    float s = 0.f;
    for (int i = lane; i < Cn; i += 32) s += row[i];
#pragma unroll
    for (int o = 16; o >= 1; o >>= 1) s += __shfl_down_sync(0xffffffffu, s, o);
    if (lane == 0) sq[w] = s;
}

// ------- fused pair-LPU: conv+res -> x1 fp32 + x1h pairs; KV -> kvh pairs; LN1 partials -------
__global__ void __launch_bounds__(224) k_lpu2(
    const float* __restrict__ X, const float* __restrict__ w,
    const float* __restrict__ bias,
    const float* __restrict__ wkv, const float* __restrict__ bkv,
    float* __restrict__ x1, __half2* __restrict__ x1h,
    __half2* __restrict__ kvh, float2* __restrict__ partl) {
    __shared__ float sp0[900], sp1[900];
    __shared__ float so0[784], so1[784];
    __shared__ float r1[224], r2[224];
    int bc = blockIdx.x;
    int b  = bc >> 7;          // Cn/2 = 128
    int mp = bc & 127;
    int c0 = 2 * mp;
    const float* xin = X + ((size_t)b * Cn + c0) * Pn;
    int tid = threadIdx.x;
    for (int i = tid; i < 900; i += 224) { sp0[i] = 0.f; sp1[i] = 0.f; }
    float wa[9], wb[9];
#pragma unroll
    for (int i = 0; i < 9; i++) { wa[i] = w[c0 * 9 + i]; wb[i] = w[(c0 + 1) * 9 + i]; }
    float bs0 = bias[c0], bs1 = bias[c0 + 1];
    __syncthreads();
    for (int i = tid; i < Pn; i += 224) {
        int o = (i / 28 + 1) * 30 + (i % 28) + 1;
        sp0[o] = xin[i];
        sp1[o] = xin[Pn + i];
    }
    __syncthreads();
    float lsum = 0.f, lsq = 0.f;
    if (tid < 196) {
        int px = tid % 28, sy = (tid / 28) * 4;
        float a0[6][3], a1[6][3];
#pragma unroll
        for (int dr = 0; dr < 6; dr++) {
            int base = (sy + dr) * 30 + px;
            a0[dr][0] = sp0[base]; a0[dr][1] = sp0[base + 1]; a0[dr][2] = sp0[base + 2];
            a1[dr][0] = sp1[base]; a1[dr][1] = sp1[base + 1]; a1[dr][2] = sp1[base + 2];
        }
        float* ob = x1 + ((size_t)b * Cn + c0) * Pn;
        __half2* oh = x1h + ((size_t)b * (Cn / 2) + mp) * Pn;
#pragma unroll
        for (int i = 0; i < 4; i++) {
            float acc0 = bs0
                + wa[0] * a0[i][0]     + wa[1] * a0[i][1]     + wa[2] * a0[i][2]
                + wa[3] * a0[i + 1][0] + wa[4] * a0[i + 1][1] + wa[5] * a0[i + 1][2]
                + wa[6] * a0[i + 2][0] + wa[7] * a0[i + 2][1] + wa[8] * a0[i + 2][2];
            float acc1 = bs1
                + wb[0] * a1[i][0]     + wb[1] * a1[i][1]     + wb[2] * a1[i][2]
                + wb[3] * a1[i + 1][0] + wb[4] * a1[i + 1][1] + wb[5] * a1[i + 1][2]
                + wb[6] * a1[i + 2][0] + wb[7] * a1[i + 2][1] + wb[8] * a1[i + 2][2];
            float y0 = acc0 + a0[i + 1][1];
            float y1 = acc1 + a1[i + 1][1];
            int p = (sy + i) * 28 + px;
            so0[p] = y0; so1[p] = y1;
            ob[p] = y0; ob[Pn + p] = y1;
            oh[p] = __floats2half2_rn(y0, y1);
            lsum += y0 + y1; lsq += y0 * y0 + y1 * y1;
        }
    }
    r1[tid] = lsum; r2[tid] = lsq;
    __syncthreads();
    for (int st = 112; st >= 7; st >>= 1) {
        if (tid < st) { r1[tid] += r1[tid + st]; r2[tid] += r2[tid + st]; }
        __syncthreads();
    }
    if (tid == 0) {
        float s = 0.f, qv = 0.f;
#pragma unroll
        for (int i = 0; i < 7; i++) { s += r1[i]; qv += r2[i]; }
        partl[bc] = make_float2(s, qv);
    }
    if (tid < 196) {
        int oy = tid / HKn, ox = tid % HKn;
        int i00 = (2 * oy) * 28 + 2 * ox;
        float k0 = bkv[c0]
            + wkv[c0 * 4 + 0] * so0[i00]      + wkv[c0 * 4 + 1] * so0[i00 + 1]
            + wkv[c0 * 4 + 2] * so0[i00 + 28] + wkv[c0 * 4 + 3] * so0[i00 + 29];
        float k1 = bkv[c0 + 1]
            + wkv[(c0 + 1) * 4 + 0] * so1[i00]      + wkv[(c0 + 1) * 4 + 1] * so1[i00 + 1]
            + wkv[(c0 + 1) * 4 + 2] * so1[i00 + 28] + wkv[(c0 + 1) * 4 + 3] * so1[i00 + 29];
        kvh[((size_t)b * (Cn / 2) + mp) * NKn + tid] = __floats2half2_rn(k0, k1);
    }
}

// ---------------- LN finishers ----------------
__global__ void k_stats_fin_l(const float2* __restrict__ partl, float2* __restrict__ mr) {
    int b = blockIdx.x, t = threadIdx.x;  // 128 threads
    __shared__ float r1[128], r2[128];
    float2 p = partl[b * (Cn / 2) + t];
    r1[t] = p.x; r2[t] = p.y;
    __syncthreads();
    for (int st = 64; st > 0; st >>= 1) {
        if (t < st) { r1[t] += r1[t + st]; r2[t] += r2[t + st]; }
        __syncthreads();
    }
    if (t == 0) {
        const float n = (float)(Cn * Pn);
        float m  = r1[0] / n;
        float vv = r2[0] / n - m * m;
        mr[b] = make_float2(m, rsqrtf(vv + EPSf));
    }
}

__global__ void k_stats_fin_o(const float2* __restrict__ parto, float2* __restrict__ mr) {
    int b = blockIdx.x, t = threadIdx.x;  // 32 threads
    float2 p = (t < 7) ? parto[b * 7 + t] : make_float2(0.f, 0.f);
#pragma unroll
    for (int o = 16; o >= 1; o >>= 1) {
        p.x += __shfl_down_sync(0xffffffffu, p.x, o);
        p.y += __shfl_down_sync(0xffffffffu, p.y, o);
    }
    if (t == 0) {
        const float n = (float)(Cn * Pn);
        float m  = p.x / n;
        float vv = p.y / n - m * m;
        mr[b] = make_float2(m, rsqrtf(vv + EPSf));
    }
}

// ---------------- dw2: channel-pair fp16 in/out ----------------
__global__ void __launch_bounds__(224) k_dw2pair(
    const __half2* __restrict__ X2, const float* __restrict__ w,
    const float* __restrict__ bias,
    const float* __restrict__ bng, const float* __restrict__ bnb,
    const float* __restrict__ bnm, const float* __restrict__ bnv,
    __half2* __restrict__ out2) {
    __shared__ float sp0[900], sp1[900];
    int bc = blockIdx.x;
    int b  = bc >> 9;
    int mp = bc & 511;
    int c0 = 2 * mp;
    const __half2* x0 = X2 + ((size_t)b * (CMn / 2) + mp) * Pn;
    int tid = threadIdx.x;
    for (int i = tid; i < 900; i += 224) { sp0[i] = 0.f; sp1[i] = 0.f; }
    float wa[9], wb[9];
#pragma unroll
    for (int i = 0; i < 9; i++) { wa[i] = w[c0 * 9 + i]; wb[i] = w[(c0 + 1) * 9 + i]; }
    float bs0 = bias[c0], bs1 = bias[c0 + 1];
    float sc0 = bng[c0] * rsqrtf(bnv[c0] + EPSf);
    float sh0 = bnb[c0] - bnm[c0] * sc0;
    float sc1 = bng[c0 + 1] * rsqrtf(bnv[c0 + 1] + EPSf);
    float sh1 = bnb[c0 + 1] - bnm[c0 + 1] * sc1;
    __syncthreads();
    for (int i = tid; i < Pn; i += 224) {
        int o = (i / 28 + 1) * 30 + (i % 28) + 1;
        float2 f = __half22float2(x0[i]);
        sp0[o] = f.x;
        sp1[o] = f.y;
    }
    __syncthreads();
    if (tid < 196) {
        int px = tid % 28, sy = (tid / 28) * 4;
        float a0[6][3], a1[6][3];
#pragma unroll
        for (int dr = 0; dr < 6; dr++) {
            int base = (sy + dr) * 30 + px;
            a0[dr][0] = sp0[base]; a0[dr][1] = sp0[base + 1]; a0[dr][2] = sp0[base + 2];
            a1[dr][0] = sp1[base]; a1[dr][1] = sp1[base + 1]; a1[dr][2] = sp1[base + 2];
        }
        __half2* ob = out2 + ((size_t)b * (CMn / 2) + mp) * Pn;
#pragma unroll
        for (int i = 0; i < 4; i++) {
            float acc0 = bs0
                + wa[0] * a0[i][0]     + wa[1] * a0[i][1]     + wa[2] * a0[i][2]
                + wa[3] * a0[i + 1][0] + wa[4] * a0[i + 1][1] + wa[5] * a0[i + 1][2]
                + wa[6] * a0[i + 2][0] + wa[7] * a0[i + 2][1] + wa[8] * a0[i + 2][2];
            float acc1 = bs1
                + wb[0] * a1[i][0]     + wb[1] * a1[i][1]     + wb[2] * a1[i][2]
                + wb[3] * a1[i + 1][0] + wb[4] * a1[i + 1][1] + wb[5] * a1[i + 1][2]
                + wb[6] * a1[i + 2][0] + wb[7] * a1[i + 2][1] + wb[8] * a1[i + 2][2];
            float y0 = gelu_f(acc0 * sc0 + sh0);
            float y1 = gelu_f(acc1 * sc1 + sh1);
            ob[(sy + i) * 28 + px] = __floats2half2_rn(y0, y1);
        }
    }
}

// ================= fp16 mma attention =================
#define KP_STR 20
#define VP_STR 40

__global__ void __launch_bounds__(224, 1) k_attn_mma(
    const __half* __restrict__ q, const __half* __restrict__ k,
    const __half* __restrict__ v, const float* __restrict__ pos,
    __half2* __restrict__ outT2) {
    __shared__ __half2 Kp[208 * KP_STR];
    __shared__ __half2 Vp[104 * VP_STR];
    const int tid = threadIdx.x;
    const int warp = tid >> 5, lane = tid & 31;
    const int gid = lane >> 2, tq = lane & 3;
    const int qt = blockIdx.x;
    const int h  = blockIdx.y;
    const int b  = blockIdx.z;
    const int hoff = h * DKn;

    for (int idx = tid; idx < 208 * 16; idx += 224) {
        int key = idx >> 4, e = idx & 15;
        __half2 val = __floats2half2_rn(0.f, 0.f);
        if (key < NKn)
            val = *(const __half2*)(k + ((size_t)(b * NKn + key)) * Cn + hoff + 2 * e);
        Kp[key * KP_STR + e] = val;
    }
    for (int idx = tid; idx < 104 * 32; idx += 224) {
        int kp = idx >> 5, dv = idx & 31;
        int k0 = 2 * kp, k1 = 2 * kp + 1;
        __half f0 = (k0 < NKn) ? v[((size_t)(b * NKn + k0)) * Cn + hoff + dv] : __float2half(0.f);
        __half f1 = (k1 < NKn) ? v[((size_t)(b * NKn + k1)) * Cn + hoff + dv] : __float2half(0.f);
        Vp[kp * VP_STR + dv] = __halves2half2(f0, f1);
    }
    __syncthreads();

    const int iA = qt * 112 + warp * 16 + gid;

    uint32_t aq[2][4];
    {
        const __half* q0 = q + ((size_t)(b * Pn + iA)) * Cn + hoff;
        const __half* q1 = q0 + 8 * Cn;
#pragma unroll
        for (int kt = 0; kt < 2; kt++) {
            aq[kt][0] = *(const uint32_t*)(q0 + 16 * kt + 2 * tq);
            aq[kt][1] = *(const uint32_t*)(q1 + 16 * kt + 2 * tq);
            aq[kt][2] = *(const uint32_t*)(q0 + 16 * kt + 8 + 2 * tq);
            aq[kt][3] = *(const uint32_t*)(q1 + 16 * kt + 8 + 2 * tq);
        }
    }

    float accS[26][4];
#pragma unroll
    for (int jt = 0; jt < 26; jt++)
#pragma unroll
        for (int r = 0; r < 4; r++) accS[jt][r] = 0.f;
#pragma unroll
    for (int jt = 0; jt < 26; jt++) {
#pragma unroll
        for (int kt = 0; kt < 2; kt++) {
            uint32_t bf[2];
            bf[0] = *(uint32_t*)&Kp[(8 * jt + gid) * KP_STR + 8 * kt + tq];
            bf[1] = *(uint32_t*)&Kp[(8 * jt + gid) * KP_STR + 8 * kt + 4 + tq];
            mma_f16(accS[jt], aq[kt], bf);
        }
    }

    const float scale = 0.17677669529663687f;
    const float* posA = pos + ((size_t)(h * Pn + iA)) * NKn;
    const float* posB = posA + 8 * NKn;
    float mA = -1e30f, mB = -1e30f;
#pragma unroll
    for (int jt = 0; jt < 26; jt++) {
        int col = 8 * jt + 2 * tq;
        if (col < NKn) {
            float2 pA = *(const float2*)(posA + col);
            float2 pB = *(const float2*)(posB + col);
            accS[jt][0] = accS[jt][0] * scale + pA.x;
            accS[jt][1] = accS[jt][1] * scale + pA.y;
            accS[jt][2] = accS[jt][2] * scale + pB.x;
            accS[jt][3] = accS[jt][3] * scale + pB.y;
            mA = fmaxf(mA, fmaxf(accS[jt][0], accS[jt][1]));
            mB = fmaxf(mB, fmaxf(accS[jt][2], accS[jt][3]));
        } else {
            accS[jt][0] = -1e30f; accS[jt][1] = -1e30f;
            accS[jt][2] = -1e30f; accS[jt][3] = -1e30f;
        }
    }
    mA = fmaxf(mA, __shfl_xor_sync(0xffffffffu, mA, 1));
    mA = fmaxf(mA, __shfl_xor_sync(0xffffffffu, mA, 2));
    mB = fmaxf(mB, __shfl_xor_sync(0xffffffffu, mB, 1));
    mB = fmaxf(mB, __shfl_xor_sync(0xffffffffu, mB, 2));
    float lA = 0.f, lB = 0.f;
#pragma unroll
    for (int jt = 0; jt < 26; jt++) {
        accS[jt][0] = __expf(accS[jt][0] - mA);
        accS[jt][1] = __expf(accS[jt][1] - mA);
        accS[jt][2] = __expf(accS[jt][2] - mB);
        accS[jt][3] = __expf(accS[jt][3] - mB);
        lA += accS[jt][0] + accS[jt][1];
        lB += accS[jt][2] + accS[jt][3];
    }
    lA += __shfl_xor_sync(0xffffffffu, lA, 1);
    lA += __shfl_xor_sync(0xffffffffu, lA, 2);
    lB += __shfl_xor_sync(0xffffffffu, lB, 1);
    lB += __shfl_xor_sync(0xffffffffu, lB, 2);

    float accO[4][4];
#pragma unroll
    for (int nt = 0; nt < 4; nt++)
#pragma unroll
        for (int r = 0; r < 4; r++) accO[nt][r] = 0.f;
#pragma unroll
    for (int kt = 0; kt < 13; kt++) {
        uint32_t pa[4];
        pa[0] = packh2(accS[2 * kt][0],     accS[2 * kt][1]);
        pa[1] = packh2(accS[2 * kt][2],     accS[2 * kt][3]);
        pa[2] = packh2(accS[2 * kt + 1][0], accS[2 * kt + 1][1]);
        pa[3] = packh2(accS[2 * kt + 1][2], accS[2 * kt + 1][3]);
#pragma unroll
        for (int nt = 0; nt < 4; nt++) {
            uint32_t bf[2];
            bf[0] = *(uint32_t*)&Vp[(8 * kt + tq) * VP_STR + 8 * nt + gid];
            bf[1] = *(uint32_t*)&Vp[(8 * kt + 4 + tq) * VP_STR + 8 * nt + gid];
            mma_f16(accO[nt], pa, bf);
        }
    }
    float invA = 1.f / lA, invB = 1.f / lB;
    __half2* ob = outT2 + ((size_t)(b * (Cn / 2) + (hoff >> 1))) * Pn;
#pragma unroll
    for (int nt = 0; nt < 4; nt++) {
        int dvp = 4 * nt + tq;
        ob[(size_t)dvp * Pn + iA]     = __floats2half2_rn(accO[nt][0] * invA, accO[nt][1] * invA);
        ob[(size_t)dvp * Pn + iA + 8] = __floats2half2_rn(accO[nt][2] * invB, accO[nt][3] * invB);
    }
}

// ---------------- host launch ----------------
static void* sym_addr(const void* symbol) {
    void* p = nullptr;
    cudaGetSymbolAddress(&p, symbol);
    return p;
}

extern "C" void kernel_launch(void* const* d_in, const int* in_sizes, int n_in,
                              void* d_out, int out_size) {
    const float* x     = (const float*)d_in[0];
    const float* lpu_w = (const float*)d_in[1];
    const float* lpu_b = (const float*)d_in[2];
    const float* dw_w  = (const float*)d_in[3];
    const float* dw_b  = (const float*)d_in[4];
    const float* wq    = (const float*)d_in[5];
    const float* bq    = (const float*)d_in[6];
    const float* wk    = (const float*)d_in[7];
    const float* bk    = (const float*)d_in[8];
    const float* wv    = (const float*)d_in[9];
    const float* bv    = (const float*)d_in[10];
    const float* wo    = (const float*)d_in[11];
    const float* bo    = (const float*)d_in[12];
    const float* pos_b = (const float*)d_in[13];
    const float* c1_w  = (const float*)d_in[14];
    const float* c1_b  = (const float*)d_in[15];
    const float* bn1_g = (const float*)d_in[16];
    const float* bn1_b = (const float*)d_in[17];
    const float* bn1_m = (const float*)d_in[18];
    const float* bn1_v = (const float*)d_in[19];
    const float* dw2_w = (const float*)d_in[20];
    const float* dw2_b = (const float*)d_in[21];
    const float* bn2_g = (const float*)d_in[22];
    const float* bn2_b = (const float*)d_in[23];
    const float* bn2_m = (const float*)d_in[24];
    const float* bn2_v = (const float*)d_in[25];
    const float* c2_w  = (const float*)d_in[26];
    const float* c2_b  = (const float*)d_in[27];
    const float* bn3_g = (const float*)d_in[28];
    const float* bn3_b = (const float*)d_in[29];
    const float* bn3_m = (const float*)d_in[30];
    const float* bn3_v = (const float*)d_in[31];
    float* out = (float*)d_out;

    float*   x1    = (float*)sym_addr(g_x1);
    __half2* x1h   = (__half2*)sym_addr(g_x1h);
    __half2* kvh   = (__half2*)sym_addr(g_kvh);
    float*   x2    = (float*)sym_addr(g_x2);
    __half*  qh    = (__half*)sym_addr(g_qh);
    __half*  kh    = (__half*)sym_addr(g_kh);
    __half*  vh    = (__half*)sym_addr(g_vh);
    __half2* attTh = (__half2*)sym_addr(g_attTh);
    __half2* t1h   = (__half2*)sym_addr(g_t1h);
    __half2* t2h   = (__half2*)sym_addr(g_t2h);
    __half2* wqh   = (__half2*)sym_addr(g_wqh);
    __half2* wkh   = (__half2*)sym_addr(g_wkh);
    __half2* wvh   = (__half2*)sym_addr(g_wvh);
    __half2* woh   = (__half2*)sym_addr(g_woh);
    __half2* c1h   = (__half2*)sym_addr(g_c1h);
    __half2* c2h   = (__half2*)sym_addr(g_c2h);
    float*   sq    = (float*)sym_addr(g_sq);
    float2*  partl = (float2*)sym_addr(g_partl);
    float2*  parto = (float2*)sym_addr(g_parto);
    float2*  mr    = (float2*)sym_addr(g_mr);

    cudaFuncSetAttribute(k_mma<1, false, true>,
                         cudaFuncAttributeMaxDynamicSharedMemorySize, SMEM_MMA);
    cudaFuncSetAttribute(k_mma<2, true, false>,
                         cudaFuncAttributeMaxDynamicSharedMemorySize, SMEM_MMA);
    cudaFuncSetAttribute(k_mma<3, false, true>,
                         cudaFuncAttributeMaxDynamicSharedMemorySize, SMEM_MMA);
    cudaFuncSetAttribute(k_qkv,
                         cudaFuncAttributeMaxDynamicSharedMemorySize, SMEM_MMA);

    dim3 tb(32, 8);
    // 1. weight packs + rowsum(wq)
    k_wpack_all<<<768, tb>>>(wq, wk, wv, wo, c1_w, c2_w, wqh, wkh, wvh, woh, c1h, c2h);
    k_rowsum_q<<<32, 256>>>(wq, sq);
    // 2. fused pair-LPU (+KV fp16 +LN1 partials +x1h)
    k_lpu2<<<Bn * (Cn / 2), 224>>>(x, lpu_w, lpu_b, dw_w, dw_b, x1, x1h, kvh, partl);
    k_stats_fin_l<<<Bn, 128>>>(partl, mr);
    // 3. merged Q/K/V projections (512-thr, 256x128 tiles)
    k_qkv<<<dim3(11, 1, Bn), 512, SMEM_MMA>>>(
        wqh, wkh, wvh, x1h, kvh, bq, bk, bv, mr, sq, qh, kh, vh);
    // 4. attention -> attTh
    k_attn_mma<<<dim3(7, NH, Bn), 224>>>(qh, kh, vh, pos_b, attTh);
    // 5. O projection + flat residual -> x2 fp32 (+LN2 partials)
    k_mma<1, false, true><<<dim3(7, 1, Bn), 512, SMEM_MMA>>>(
        woh, attTh, bo, nullptr, nullptr, nullptr, nullptr, nullptr, x1, parto, x2, Cn, Cn, Pn);
    k_stats_fin_o<<<Bn, 32>>>(parto, mr);
    // 6. c1 + BN1 + GELU (fp32 B with LN in loader) -> t1h
    k_mma<2, true, false><<<dim3(7, 4, Bn), 512, SMEM_MMA>>>(
        c1h, x2, c1_b, bn1_g, bn1_b, bn1_m, bn1_v, mr, nullptr, nullptr, t1h, CMn, Cn, Pn);
    // 7. dw2 + BN2 + GELU -> t2h
    k_dw2pair<<<Bn * (CMn / 2), 224>>>(t1h, dw2_w, dw2_b, bn2_g, bn2_b, bn2_m, bn2_v, t2h);
    // 8. c2 + BN3 + channel-major residual -> d_out
    k_mma<3, false, true><<<dim3(7, 1, Bn), 512, SMEM_MMA>>>(
        c2h, t2h, c2_b, bn3_g, bn3_b, bn3_m, bn3_v, nullptr, x2, nullptr, out, Cn, CMn, Pn);
}

// round 14
// speedup vs baseline: 1.0995x; 1.0995x over previous
#include <cuda_runtime.h>
#include <cuda_fp16.h>
#include <math.h>
#include <stdint.h>

// ---------------- problem constants ----------------
#define Bn   32
#define Cn   256
#define Hn   28
#define Wn   28
#define Pn   784          // H*W
#define NKn  196          // (H/2)*(W/2)
#define HKn  14
#define CMn  1024         // C * R
#define NH   8
#define DKn  32
#define EPSf 1e-5f

// ---------------- scratch (device globals; padded for unguarded tile loads) ----------------
__device__ float   g_x1 [Bn*Cn*Pn + 256];        // LPU out fp32 (O-proj flat residual)
__device__ __half2 g_x1h[Bn*(Cn/2)*Pn + 512];    // LPU out fp16 channel-paired
__device__ __half2 g_kvh[Bn*(Cn/2)*NKn + 512];   // KV downsample fp16 channel-paired
__device__ float   g_x2 [Bn*Cn*Pn + 256];        // attn residual fp32 (c2 residual, LN2)
__device__ __half  g_x2h[Bn*Cn*Pn + 1024];       // flat fp16 mirror of x2 (c1 B)
__device__ __half  g_qh [Bn*Pn*Cn + 512];        // Q fp16 row-major [p][oc]
__device__ __half  g_kh [Bn*NKn*Cn + 512];       // K fp16 [nk][256]
__device__ __half  g_vh [Bn*NKn*Cn + 512];       // V fp16 [nk][256]
__device__ __half2 g_attTh[Bn*(Cn/2)*Pn + 512];  // attn out, channel-paired
__device__ __half2 g_t1h  [Bn*(CMn/2)*Pn + 512]; // c1 out, channel-paired
__device__ __half2 g_t2h  [Bn*(CMn/2)*Pn + 512]; // dw2 out, channel-paired
__device__ __half2 g_wqh[(Cn/2)*Cn];             // weights k-paired [k/2][m]
__device__ __half2 g_wkh[(Cn/2)*Cn];
__device__ __half2 g_wvh[(Cn/2)*Cn];
__device__ __half2 g_woh[(Cn/2)*Cn];
__device__ __half2 g_c1h[(Cn/2)*CMn];
__device__ __half2 g_c2h[(CMn/2)*Cn];
__device__ float   g_sq [Cn];                    // rowsum(wq)
__device__ float   g_sc1[CMn];                   // rowsum(c1_w)
__device__ float2  g_partl[Bn*(Cn/2)];           // LN1 partials (per pair-plane)
__device__ float2  g_parto[Bn*14];               // LN2 partials
__device__ float2  g_mr  [Bn];

__device__ __forceinline__ float gelu_f(float v) {
    return 0.5f * v * (1.0f + erff(v * 0.7071067811865475f));
}
__device__ __forceinline__ void mma_f16(float* c, const uint32_t* a, const uint32_t* b) {
    asm volatile(
        "mma.sync.aligned.m16n8k16.row.col.f32.f16.f16.f32 "
        "{%0,%1,%2,%3}, {%4,%5,%6,%7}, {%8,%9}, {%0,%1,%2,%3};"
        : "+f"(c[0]), "+f"(c[1]), "+f"(c[2]), "+f"(c[3])
        : "r"(a[0]), "r"(a[1]), "r"(a[2]), "r"(a[3]), "r"(b[0]), "r"(b[1]));
}
__device__ __forceinline__ uint32_t packh2(float lo, float hi) {
    __half2 h = __floats2half2_rn(lo, hi);
    return *(uint32_t*)&h;
}

#define H2STR 136
#define KSTR  132
#define STAGE (32*H2STR)
#define SMEM_MMA (2*STAGE*4)   // 34816 B

// ====================== k_mma (256 thr, 128x128 — proven config) ======================
// BK 1: B = half2 k-paired [k/2][P] raw
// BK 2: B = flat __half [k][P] (channel rows), interleave via byte_perm
// MODE 1: f32 out[p*M+m] = acc + bias + res; +flat fp16 mirror xmir; LN2 partials
// MODE 2: half2 out[(m/2)*P+p] = gelu(BN(acc*rstd + cb - mean*rstd*S))   (LN fold)
// MODE 3: f32 out[m*P+p] = BN(acc + bias) + res
template <int MODE, int BK>
__global__ void __launch_bounds__(256, 2) k_mma(
    const __half2* __restrict__ Wh, const void* __restrict__ Xv,
    const float* __restrict__ bias,
    const float* __restrict__ bng, const float* __restrict__ bnb,
    const float* __restrict__ bnm, const float* __restrict__ bnv,
    const float2* __restrict__ mr, const float* __restrict__ rsum,
    const float* __restrict__ res, float2* __restrict__ pstat,
    __half* __restrict__ xmir,
    void* __restrict__ outv, int M, int K, int P) {
    extern __shared__ float sm[];
    const int tid  = threadIdx.x;
    const int warp = tid >> 5, lane = tid & 31;
    const int gid = lane >> 2, tq = lane & 3;
    const int wm = (warp & 1) * 64;
    const int wn = (warp >> 1) * 32;
    const int b  = blockIdx.z;
    const int m0 = blockIdx.y * 128;
    const int n0 = blockIdx.x * 128;
    const __half2* Xh2 = (BK == 1) ? (const __half2*)Xv + (size_t)b * (K >> 1) * P : nullptr;
    const __half*  Xhf = (BK == 2) ? (const __half*)Xv + (size_t)b * K * P : nullptr;

    float acc[4][4][4];
#pragma unroll
    for (int i = 0; i < 4; i++)
#pragma unroll
        for (int j = 0; j < 4; j++)
#pragma unroll
            for (int r = 0; r < 4; r++) acc[i][j][r] = 0.f;

    const int kk = tid >> 4;
    const int mq = (tid & 15) * 8;
    uint4 pa0, pa1, pb0, pb1;
    const int T = K >> 5;

    auto load_chunk = [&](int kc0) {
        const uint4* wr = (const uint4*)(Wh + (size_t)((kc0 >> 1) + kk) * M + m0 + mq);
        pa0 = wr[0]; pa1 = wr[1];
        if (BK == 1) {
            const uint4* xr = (const uint4*)(Xh2 + (size_t)((kc0 >> 1) + kk) * P + n0 + mq);
            pb0 = xr[0]; pb1 = xr[1];
        } else {
            // flat half rows 2kk, 2kk+1; interleave into channel-pair half2s
            const uint4 r0 = *(const uint4*)(Xhf + (size_t)(kc0 + 2 * kk) * P + n0 + mq);
            const uint4 r1 = *(const uint4*)(Xhf + (size_t)(kc0 + 2 * kk + 1) * P + n0 + mq);
            pb0 = make_uint4(__byte_perm(r0.x, r1.x, 0x5410), __byte_perm(r0.x, r1.x, 0x7632),
                             __byte_perm(r0.y, r1.y, 0x5410), __byte_perm(r0.y, r1.y, 0x7632));
            pb1 = make_uint4(__byte_perm(r0.z, r1.z, 0x5410), __byte_perm(r0.z, r1.z, 0x7632),
                             __byte_perm(r0.w, r1.w, 0x5410), __byte_perm(r0.w, r1.w, 0x7632));
        }
    };
    auto store_chunk = [&](int s) {
        __half2* As2 = (__half2*)sm + s * STAGE;
        __half2* Bs2 = As2 + 16 * H2STR;
        *(uint4*)&As2[kk * H2STR + mq]     = pa0;
        *(uint4*)&As2[kk * H2STR + mq + 4] = pa1;
        *(uint4*)&Bs2[kk * H2STR + mq]     = pb0;
        *(uint4*)&Bs2[kk * H2STR + mq + 4] = pb1;
    };

    load_chunk(0);
    store_chunk(0);
    __syncthreads();

    for (int t = 0; t < T; t++) {
        if (t + 1 < T) load_chunk((t + 1) << 5);
        const __half2* As2 = (const __half2*)sm + (t & 1) * STAGE;
        const __half2* Bs2 = As2 + 16 * H2STR;
#pragma unroll
        for (int ks = 0; ks < 2; ks++) {
            const int r0 = ks * 8;
            uint32_t af[4][4], bf[4][2];
#pragma unroll
            for (int i = 0; i < 4; i++) {
                int m = wm + i * 16 + gid;
                af[i][0] = *(uint32_t*)&As2[(r0 + tq) * H2STR + m];
                af[i][1] = *(uint32_t*)&As2[(r0 + tq) * H2STR + m + 8];
                af[i][2] = *(uint32_t*)&As2[(r0 + tq + 4) * H2STR + m];
                af[i][3] = *(uint32_t*)&As2[(r0 + tq + 4) * H2STR + m + 8];
            }
#pragma unroll
            for (int j = 0; j < 4; j++) {
                int p = wn + j * 8 + gid;
                bf[j][0] = *(uint32_t*)&Bs2[(r0 + tq) * H2STR + p];
                bf[j][1] = *(uint32_t*)&Bs2[(r0 + tq + 4) * H2STR + p];
            }
#pragma unroll
            for (int i = 0; i < 4; i++)
#pragma unroll
                for (int j = 0; j < 4; j++) mma_f16(acc[i][j], af[i], bf[j]);
        }
        if (t + 1 < T) {
            store_chunk((t + 1) & 1);
            __syncthreads();
        }
    }

    // LN scalars for MODE 2 fold
    float mean = 0.f, rstd = 1.f;
    if (MODE == 2) { float2 v = mr[b]; mean = v.x; rstd = v.y; }

    // ---- epilogue: two 64-row passes staged through smem ----
    float* sD = sm;
    float*   outf  = (MODE == 1 || MODE == 3) ? (float*)outv + (size_t)b * (size_t)M * P : nullptr;
    __half2* outh2 = (MODE == 2) ? (__half2*)outv + (size_t)b * (size_t)(M >> 1) * P : nullptr;
    __half*  xmb   = (MODE == 1) ? xmir + (size_t)b * (size_t)M * P : nullptr;
    const float* resb = (MODE == 1 || MODE == 3) ? res + (size_t)b * (size_t)M * P : nullptr;
    float osum = 0.f, osq = 0.f;

#pragma unroll
    for (int pass = 0; pass < 2; pass++) {
        __syncthreads();
        if (MODE == 1) {
            if ((wn >> 6) == pass) {
#pragma unroll
                for (int i = 0; i < 4; i++) {
                    int mrow = wm + i * 16 + gid;
#pragma unroll
                    for (int j = 0; j < 4; j++) {
                        int pc = (wn & 63) + j * 8 + 2 * tq;
                        sD[pc * KSTR + mrow]           = acc[i][j][0];
                        sD[(pc + 1) * KSTR + mrow]     = acc[i][j][1];
                        sD[pc * KSTR + mrow + 8]       = acc[i][j][2];
                        sD[(pc + 1) * KSTR + mrow + 8] = acc[i][j][3];
                    }
                }
            }
        } else {
            if ((wm >> 6) == pass) {
#pragma unroll
                for (int i = 0; i < 4; i++) {
                    int ml = (wm & 63) + i * 16 + gid;
#pragma unroll
                    for (int j = 0; j < 4; j++) {
                        int pc = wn + j * 8 + 2 * tq;
                        sD[ml * KSTR + pc]           = acc[i][j][0];
                        sD[ml * KSTR + pc + 1]       = acc[i][j][1];
                        sD[(ml + 8) * KSTR + pc]     = acc[i][j][2];
                        sD[(ml + 8) * KSTR + pc + 1] = acc[i][j][3];
                    }
                }
            }
        }
        __syncthreads();
        if (MODE == 1) {
            for (int l = tid; l < 64 * 32; l += 256) {
                int rl = l >> 5, cq = (l & 31) * 4;
                int p = n0 + pass * 64 + rl;
                if (p >= P) continue;
                float4 v = *(float4*)&sD[rl * KSTR + cq];
                float4 bb = *(const float4*)(bias + m0 + cq);
                v.x += bb.x; v.y += bb.y; v.z += bb.z; v.w += bb.w;
                size_t off = (size_t)p * M + m0 + cq;
                float4 rr = *(const float4*)(resb + off);
                v.x += rr.x; v.y += rr.y; v.z += rr.z; v.w += rr.w;
                *(float4*)(outf + off) = v;
                __half2 h01 = __floats2half2_rn(v.x, v.y);
                __half2 h23 = __floats2half2_rn(v.z, v.w);
                *(uint2*)(xmb + off) = make_uint2(*(uint32_t*)&h01, *(uint32_t*)&h23);
                osum += v.x + v.y + v.z + v.w;
                osq  += v.x * v.x + v.y * v.y + v.z * v.z + v.w * v.w;
            }
        } else if (MODE == 2) {
            for (int l = tid; l < 32 * 32; l += 256) {
                int rp = l >> 5, cq = (l & 31) * 4;
                int m = m0 + pass * 64 + 2 * rp;
                int p = n0 + cq;
                if (p >= P) continue;
                float sc0 = bng[m] * rsqrtf(bnv[m] + EPSf);
                float sh0 = bnb[m] - bnm[m] * sc0
                          + (bias[m] - mean * rstd * rsum[m]) * sc0;
                float a0 = rstd * sc0;
                float sc1 = bng[m + 1] * rsqrtf(bnv[m + 1] + EPSf);
                float sh1 = bnb[m + 1] - bnm[m + 1] * sc1
                          + (bias[m + 1] - mean * rstd * rsum[m + 1]) * sc1;
                float a1 = rstd * sc1;
                float4 v0 = *(float4*)&sD[(2 * rp) * KSTR + cq];
                float4 v1 = *(float4*)&sD[(2 * rp + 1) * KSTR + cq];
                v0.x = gelu_f(v0.x * a0 + sh0); v0.y = gelu_f(v0.y * a0 + sh0);
                v0.z = gelu_f(v0.z * a0 + sh0); v0.w = gelu_f(v0.w * a0 + sh0);
                v1.x = gelu_f(v1.x * a1 + sh1); v1.y = gelu_f(v1.y * a1 + sh1);
                v1.z = gelu_f(v1.z * a1 + sh1); v1.w = gelu_f(v1.w * a1 + sh1);
                uint4 u = make_uint4(packh2(v0.x, v1.x), packh2(v0.y, v1.y),
                                     packh2(v0.z, v1.z), packh2(v0.w, v1.w));
                *(uint4*)(outh2 + (size_t)(m >> 1) * P + p) = u;
            }
        } else {
            for (int l = tid; l < 64 * 32; l += 256) {
                int rl = l >> 5, cq = (l & 31) * 4;
                int m = m0 + pass * 64 + rl;
                int p = n0 + cq;
                if (p >= P) continue;
                float scale = bng[m] * rsqrtf(bnv[m] + EPSf);
                float shift = bnb[m] - bnm[m] * scale + bias[m] * scale;
                float4 v = *(float4*)&sD[rl * KSTR + cq];
                v.x = v.x * scale + shift; v.y = v.y * scale + shift;
                v.z = v.z * scale + shift; v.w = v.w * scale + shift;
                size_t off = (size_t)m * P + p;
                float4 rr = *(const float4*)(resb + off);
                v.x += rr.x; v.y += rr.y; v.z += rr.z; v.w += rr.w;
                *(float4*)(outf + off) = v;
            }
        }
    }

    if (MODE == 1) {
        __syncthreads();
        float* r1 = sm;
        float* r2 = sm + 256;
        r1[tid] = osum; r2[tid] = osq;
        __syncthreads();
        for (int st = 128; st > 0; st >>= 1) {
            if (tid < st) { r1[tid] += r1[tid + st]; r2[tid] += r2[tid + st]; }
            __syncthreads();
        }
        if (tid == 0)
            pstat[b * 14 + blockIdx.y * gridDim.x + blockIdx.x] = make_float2(r1[0], r2[0]);
    }
}

// ====================== merged QKV (256 thr, raw fp16 B, LN folded for Q) ======================
__global__ void __launch_bounds__(256, 2) k_qkv(
    const __half2* __restrict__ wqh, const __half2* __restrict__ wkh,
    const __half2* __restrict__ wvh,
    const __half2* __restrict__ x1h, const __half2* __restrict__ kvh,
    const float* __restrict__ bq, const float* __restrict__ bk,
    const float* __restrict__ bv, const float2* __restrict__ mr,
    const float* __restrict__ sq,
    __half* __restrict__ qh, __half* __restrict__ kh, __half* __restrict__ vh) {
    extern __shared__ float sm[];
    const int tid  = threadIdx.x;
    const int warp = tid >> 5, lane = tid & 31;
    const int gid = lane >> 2, tq = lane & 3;
    const int wm = (warp & 1) * 64;
    const int wn = (warp >> 1) * 32;
    const int b  = blockIdx.z;
    const int id = blockIdx.x;  // 0..21

    const __half2* Wh;
    const __half2* Xh2;
    const float* bias;
    __half* outp;
    int P, m0, n0;
    bool isQ = false;
    if (id < 14) {
        Wh = wqh; Xh2 = x1h + (size_t)b * (Cn / 2) * Pn; bias = bq;
        outp = qh + (size_t)b * Pn * Cn;
        P = Pn; isQ = true; m0 = (id / 7) * 128; n0 = (id % 7) * 128;
    } else if (id < 18) {
        int t = id - 14;
        Wh = wkh; Xh2 = kvh + (size_t)b * (Cn / 2) * NKn; bias = bk;
        outp = kh + (size_t)b * NKn * Cn;
        P = NKn; m0 = (t >> 1) * 128; n0 = (t & 1) * 128;
    } else {
        int t = id - 18;
        Wh = wvh; Xh2 = kvh + (size_t)b * (Cn / 2) * NKn; bias = bv;
        outp = vh + (size_t)b * NKn * Cn;
        P = NKn; m0 = (t >> 1) * 128; n0 = (t & 1) * 128;
    }

    float acc[4][4][4];
#pragma unroll
    for (int i = 0; i < 4; i++)
#pragma unroll
        for (int j = 0; j < 4; j++)
#pragma unroll
            for (int r = 0; r < 4; r++) acc[i][j][r] = 0.f;

    const int kk = tid >> 4;
    const int mq = (tid & 15) * 8;
    uint4 pa0, pa1, pb0, pb1;
    const int T = Cn >> 5;  // 8

    auto load_chunk = [&](int kp0) {
        const uint4* wr = (const uint4*)(Wh + (size_t)(kp0 + kk) * Cn + m0 + mq);
        pa0 = wr[0]; pa1 = wr[1];
        const uint4* xr = (const uint4*)(Xh2 + (size_t)(kp0 + kk) * P + n0 + mq);
        pb0 = xr[0]; pb1 = xr[1];
    };
    auto store_chunk = [&](int s) {
        __half2* As2 = (__half2*)sm + s * STAGE;
        __half2* Bs2 = As2 + 16 * H2STR;
        *(uint4*)&As2[kk * H2STR + mq]     = pa0;
        *(uint4*)&As2[kk * H2STR + mq + 4] = pa1;
        *(uint4*)&Bs2[kk * H2STR + mq]     = pb0;
        *(uint4*)&Bs2[kk * H2STR + mq + 4] = pb1;
    };

    load_chunk(0);
    store_chunk(0);
    __syncthreads();

    for (int t = 0; t < T; t++) {
        if (t + 1 < T) load_chunk((t + 1) << 4);
        const __half2* As2 = (const __half2*)sm + (t & 1) * STAGE;
        const __half2* Bs2 = As2 + 16 * H2STR;
#pragma unroll
        for (int ks = 0; ks < 2; ks++) {
            const int r0 = ks * 8;
            uint32_t af[4][4], bf[4][2];
#pragma unroll
            for (int i = 0; i < 4; i++) {
                int m = wm + i * 16 + gid;
                af[i][0] = *(uint32_t*)&As2[(r0 + tq) * H2STR + m];
                af[i][1] = *(uint32_t*)&As2[(r0 + tq) * H2STR + m + 8];
                af[i][2] = *(uint32_t*)&As2[(r0 + tq + 4) * H2STR + m];
                af[i][3] = *(uint32_t*)&As2[(r0 + tq + 4) * H2STR + m + 8];
            }
#pragma unroll
            for (int j = 0; j < 4; j++) {
                int p = wn + j * 8 + gid;
                bf[j][0] = *(uint32_t*)&Bs2[(r0 + tq) * H2STR + p];
                bf[j][1] = *(uint32_t*)&Bs2[(r0 + tq + 4) * H2STR + p];
            }
#pragma unroll
            for (int i = 0; i < 4; i++)
#pragma unroll
                for (int j = 0; j < 4; j++) mma_f16(acc[i][j], af[i], bf[j]);
        }
        if (t + 1 < T) {
            store_chunk((t + 1) & 1);
            __syncthreads();
        }
    }

    float scl = 1.f, moff = 0.f;
    if (isQ) { float2 v = mr[b]; scl = v.y; moff = -v.x * v.y; }

    float* sD = sm;
#pragma unroll
    for (int pass = 0; pass < 2; pass++) {
        __syncthreads();
        if ((wn >> 6) == pass) {
#pragma unroll
            for (int i = 0; i < 4; i++) {
                int mrow = wm + i * 16 + gid;
#pragma unroll
                for (int j = 0; j < 4; j++) {
                    int pc = (wn & 63) + j * 8 + 2 * tq;
                    sD[pc * KSTR + mrow]           = acc[i][j][0];
                    sD[(pc + 1) * KSTR + mrow]     = acc[i][j][1];
                    sD[pc * KSTR + mrow + 8]       = acc[i][j][2];
                    sD[(pc + 1) * KSTR + mrow + 8] = acc[i][j][3];
                }
            }
        }
        __syncthreads();
        for (int l = tid; l < 64 * 32; l += 256) {
            int rl = l >> 5, cq = (l & 31) * 4;
            int p = n0 + pass * 64 + rl;
            if (p >= P) continue;
            float4 v = *(float4*)&sD[rl * KSTR + cq];
            float4 bb = *(const float4*)(bias + m0 + cq);
            if (isQ) {
                float4 ss = *(const float4*)(sq + m0 + cq);
                v.x = v.x * scl + bb.x + moff * ss.x;
                v.y = v.y * scl + bb.y + moff * ss.y;
                v.z = v.z * scl + bb.z + moff * ss.z;
                v.w = v.w * scl + bb.w + moff * ss.w;
            } else {
                v.x += bb.x; v.y += bb.y; v.z += bb.z; v.w += bb.w;
            }
            __half2 h01 = __floats2half2_rn(v.x, v.y);
            __half2 h23 = __floats2half2_rn(v.z, v.w);
            uint2 u = make_uint2(*(uint32_t*)&h01, *(uint32_t*)&h23);
            *(uint2*)(outp + (size_t)p * Cn + m0 + cq) = u;
        }
    }
}

// ---------------- merged weight pack ----------------
__global__ void k_wpack_all(
    const float* __restrict__ wq, const float* __restrict__ wk,
    const float* __restrict__ wv, const float* __restrict__ wo,
    const float* __restrict__ c1w, const float* __restrict__ c2w,
    __half2* __restrict__ oq, __half2* __restrict__ ok,
    __half2* __restrict__ ov, __half2* __restrict__ oo,
    __half2* __restrict__ oc1, __half2* __restrict__ oc2) {
    __shared__ float t[32][33];
    int id = blockIdx.x;
    const float* in;
    __half2* out;
    int M, K, tile;
    if (id < 256) {
        int w = id >> 6; tile = id & 63;
        in  = (w == 0) ? wq : (w == 1) ? wk : (w == 2) ? wv : wo;
        out = (w == 0) ? oq : (w == 1) ? ok : (w == 2) ? ov : oo;
        M = Cn; K = Cn;
    } else if (id < 512) {
        tile = id - 256;
        in = c1w; out = oc1; M = CMn; K = Cn;
    } else {
        tile = id - 512;
        in = c2w; out = oc2; M = Cn; K = CMn;
    }
    int ktiles = K >> 5;
    int m0 = (tile / ktiles) * 32, k0 = (tile % ktiles) * 32;
    int tx = threadIdx.x, ty = threadIdx.y;
#pragma unroll
    for (int q = 0; q < 32; q += 8)
        t[ty + q][tx] = in[(size_t)(m0 + ty + q) * K + k0 + tx];
    __syncthreads();
#pragma unroll
    for (int q = 0; q < 2; q++) {
        int kp = ty + q * 8;
        __half2 val = __floats2half2_rn(t[tx][2 * kp], t[tx][2 * kp + 1]);
        out[(size_t)((k0 >> 1) + kp) * M + m0 + tx] = val;
    }
}

// ---------------- rowsums of wq and c1_w (deterministic) ----------------
__global__ void k_rowsum(const float* __restrict__ wq, const float* __restrict__ c1w,
                         float* __restrict__ sq, float* __restrict__ sc1) {
    int w = (blockIdx.x * 256 + threadIdx.x) >> 5;   // 0..1279
    int lane = threadIdx.x & 31;
    const float* row;
    float* out;
    if (w < Cn) { row = wq + (size_t)w * Cn; out = sq + w; }
    else        { row = c1w + (size_t)(w - Cn) * Cn; out = sc1 + (w - Cn); }
    float s = 0.f;
    for (int i = lane; i < Cn; i += 32) s += row[i];
#pragma unroll
    for (int o = 16; o >= 1; o >>= 1) s += __shfl_down_sync(0xffffffffu, s, o);
    if (lane == 0) *out = s;
}

// ------- fused pair-LPU: conv+res -> x1 fp32 + x1h pairs; KV -> kvh pairs; LN1 partials -------
__global__ void __launch_bounds__(224) k_lpu2(
    const float* __restrict__ X, const float* __restrict__ w,
    const float* __restrict__ bias,
    const float* __restrict__ wkv, const float* __restrict__ bkv,
    float* __restrict__ x1, __half2* __restrict__ x1h,
    __half2* __restrict__ kvh, float2* __restrict__ partl) {
    __shared__ float sp0[900], sp1[900];
    __shared__ float so0[784], so1[784];
    __shared__ float r1[224], r2[224];
    int bc = blockIdx.x;
    int b  = bc >> 7;          // Cn/2 = 128
    int mp = bc & 127;
    int c0 = 2 * mp;
    const float* xin = X + ((size_t)b * Cn + c0) * Pn;
    int tid = threadIdx.x;
    for (int i = tid; i < 900; i += 224) { sp0[i] = 0.f; sp1[i] = 0.f; }
    float wa[9], wb[9];
#pragma unroll
    for (int i = 0; i < 9; i++) { wa[i] = w[c0 * 9 + i]; wb[i] = w[(c0 + 1) * 9 + i]; }
    float bs0 = bias[c0], bs1 = bias[c0 + 1];
    __syncthreads();
    for (int i = tid; i < Pn; i += 224) {
        int o = (i / 28 + 1) * 30 + (i % 28) + 1;
        sp0[o] = xin[i];
        sp1[o] = xin[Pn + i];
    }
    __syncthreads();
    float lsum = 0.f, lsq = 0.f;
    if (tid < 196) {
        int px = tid % 28, sy = (tid / 28) * 4;
        float a0[6][3], a1[6][3];
#pragma unroll
        for (int dr = 0; dr < 6; dr++) {
            int base = (sy + dr) * 30 + px;
            a0[dr][0] = sp0[base]; a0[dr][1] = sp0[base + 1]; a0[dr][2] = sp0[base + 2];
            a1[dr][0] = sp1[base]; a1[dr][1] = sp1[base + 1]; a1[dr][2] = sp1[base + 2];
        }
        float* ob = x1 + ((size_t)b * Cn + c0) * Pn;
        __half2* oh = x1h + ((size_t)b * (Cn / 2) + mp) * Pn;
#pragma unroll
        for (int i = 0; i < 4; i++) {
            float acc0 = bs0
                + wa[0] * a0[i][0]     + wa[1] * a0[i][1]     + wa[2] * a0[i][2]
                + wa[3] * a0[i + 1][0] + wa[4] * a0[i + 1][1] + wa[5] * a0[i + 1][2]
                + wa[6] * a0[i + 2][0] + wa[7] * a0[i + 2][1] + wa[8] * a0[i + 2][2];
            float acc1 = bs1
                + wb[0] * a1[i][0]     + wb[1] * a1[i][1]     + wb[2] * a1[i][2]
                + wb[3] * a1[i + 1][0] + wb[4] * a1[i + 1][1] + wb[5] * a1[i + 1][2]
                + wb[6] * a1[i + 2][0] + wb[7] * a1[i + 2][1] + wb[8] * a1[i + 2][2];
            float y0 = acc0 + a0[i + 1][1];
            float y1 = acc1 + a1[i + 1][1];
            int p = (sy + i) * 28 + px;
            so0[p] = y0; so1[p] = y1;
            ob[p] = y0; ob[Pn + p] = y1;
            oh[p] = __floats2half2_rn(y0, y1);
            lsum += y0 + y1; lsq += y0 * y0 + y1 * y1;
        }
    }
    r1[tid] = lsum; r2[tid] = lsq;
    __syncthreads();
    for (int st = 112; st >= 7; st >>= 1) {
        if (tid < st) { r1[tid] += r1[tid + st]; r2[tid] += r2[tid + st]; }
        __syncthreads();
    }
    if (tid == 0) {
        float s = 0.f, qv = 0.f;
#pragma unroll
        for (int i = 0; i < 7; i++) { s += r1[i]; qv += r2[i]; }
        partl[bc] = make_float2(s, qv);
    }
    if (tid < 196) {
        int oy = tid / HKn, ox = tid % HKn;
        int i00 = (2 * oy) * 28 + 2 * ox;
        float k0 = bkv[c0]
            + wkv[c0 * 4 + 0] * so0[i00]      + wkv[c0 * 4 + 1] * so0[i00 + 1]
            + wkv[c0 * 4 + 2] * so0[i00 + 28] + wkv[c0 * 4 + 3] * so0[i00 + 29];
        float k1 = bkv[c0 + 1]
            + wkv[(c0 + 1) * 4 + 0] * so1[i00]      + wkv[(c0 + 1) * 4 + 1] * so1[i00 + 1]
            + wkv[(c0 + 1) * 4 + 2] * so1[i00 + 28] + wkv[(c0 + 1) * 4 + 3] * so1[i00 + 29];
        kvh[((size_t)b * (Cn / 2) + mp) * NKn + tid] = __floats2half2_rn(k0, k1);
    }
}

// ---------------- LN finishers ----------------
__global__ void k_stats_fin_l(const float2* __restrict__ partl, float2* __restrict__ mr) {
    int b = blockIdx.x, t = threadIdx.x;  // 128 threads
    __shared__ float r1[128], r2[128];
    float2 p = partl[b * (Cn / 2) + t];
    r1[t] = p.x; r2[t] = p.y;
    __syncthreads();
    for (int st = 64; st > 0; st >>= 1) {
        if (t < st) { r1[t] += r1[t + st]; r2[t] += r2[t + st]; }
        __syncthreads();
    }
    if (t == 0) {
        const float n = (float)(Cn * Pn);
        float m  = r1[0] / n;
        float vv = r2[0] / n - m * m;
        mr[b] = make_float2(m, rsqrtf(vv + EPSf));
    }
}

__global__ void k_stats_fin_o(const float2* __restrict__ parto, float2* __restrict__ mr) {
    int b = blockIdx.x, t = threadIdx.x;  // 32 threads
    float2 p = (t < 14) ? parto[b * 14 + t] : make_float2(0.f, 0.f);
#pragma unroll
    for (int o = 16; o >= 1; o >>= 1) {
        p.x += __shfl_down_sync(0xffffffffu, p.x, o);
        p.y += __shfl_down_sync(0xffffffffu, p.y, o);
    }
    if (t == 0) {
        const float n = (float)(Cn * Pn);
        float m  = p.x / n;
        float vv = p.y / n - m * m;
        mr[b] = make_float2(m, rsqrtf(vv + EPSf));
    }
}

// ---------------- dw2: channel-pair fp16 in/out ----------------
__global__ void __launch_bounds__(224) k_dw2pair(
    const __half2* __restrict__ X2, const float* __restrict__ w,
    const float* __restrict__ bias,
    const float* __restrict__ bng, const float* __restrict__ bnb,
    const float* __restrict__ bnm, const float* __restrict__ bnv,
    __half2* __restrict__ out2) {
    __shared__ float sp0[900], sp1[900];
    int bc = blockIdx.x;
    int b  = bc >> 9;
    int mp = bc & 511;
    int c0 = 2 * mp;
    const __half2* x0 = X2 + ((size_t)b * (CMn / 2) + mp) * Pn;
    int tid = threadIdx.x;
    for (int i = tid; i < 900; i += 224) { sp0[i] = 0.f; sp1[i] = 0.f; }
    float wa[9], wb[9];
#pragma unroll
    for (int i = 0; i < 9; i++) { wa[i] = w[c0 * 9 + i]; wb[i] = w[(c0 + 1) * 9 + i]; }
    float bs0 = bias[c0], bs1 = bias[c0 + 1];
    float sc0 = bng[c0] * rsqrtf(bnv[c0] + EPSf);
    float sh0 = bnb[c0] - bnm[c0] * sc0;
    float sc1 = bng[c0 + 1] * rsqrtf(bnv[c0 + 1] + EPSf);
    float sh1 = bnb[c0 + 1] - bnm[c0 + 1] * sc1;
    __syncthreads();
    for (int i = tid; i < Pn; i += 224) {
        int o = (i / 28 + 1) * 30 + (i % 28) + 1;
        float2 f = __half22float2(x0[i]);
        sp0[o] = f.x;
        sp1[o] = f.y;
    }
    __syncthreads();
    if (tid < 196) {
        int px = tid % 28, sy = (tid / 28) * 4;
        float a0[6][3], a1[6][3];
#pragma unroll
        for (int dr = 0; dr < 6; dr++) {
            int base = (sy + dr) * 30 + px;
            a0[dr][0] = sp0[base]; a0[dr][1] = sp0[base + 1]; a0[dr][2] = sp0[base + 2];
            a1[dr][0] = sp1[base]; a1[dr][1] = sp1[base + 1]; a1[dr][2] = sp1[base + 2];
        }
        __half2* ob = out2 + ((size_t)b * (CMn / 2) + mp) * Pn;
#pragma unroll
        for (int i = 0; i < 4; i++) {
            float acc0 = bs0
                + wa[0] * a0[i][0]     + wa[1] * a0[i][1]     + wa[2] * a0[i][2]
                + wa[3] * a0[i + 1][0] + wa[4] * a0[i + 1][1] + wa[5] * a0[i + 1][2]
                + wa[6] * a0[i + 2][0] + wa[7] * a0[i + 2][1] + wa[8] * a0[i + 2][2];
            float acc1 = bs1
                + wb[0] * a1[i][0]     + wb[1] * a1[i][1]     + wb[2] * a1[i][2]
                + wb[3] * a1[i + 1][0] + wb[4] * a1[i + 1][1] + wb[5] * a1[i + 1][2]
                + wb[6] * a1[i + 2][0] + wb[7] * a1[i + 2][1] + wb[8] * a1[i + 2][2];
            float y0 = gelu_f(acc0 * sc0 + sh0);
            float y1 = gelu_f(acc1 * sc1 + sh1);
            ob[(sy + i) * 28 + px] = __floats2half2_rn(y0, y1);
        }
    }
}

// ================= fp16 mma attention =================
#define KP_STR 20
#define VP_STR 40

__global__ void __launch_bounds__(224, 1) k_attn_mma(
    const __half* __restrict__ q, const __half* __restrict__ k,
    const __half* __restrict__ v, const float* __restrict__ pos,
    __half2* __restrict__ outT2) {
    __shared__ __half2 Kp[208 * KP_STR];
    __shared__ __half2 Vp[104 * VP_STR];
    const int tid = threadIdx.x;
    const int warp = tid >> 5, lane = tid & 31;
    const int gid = lane >> 2, tq = lane & 3;
    const int qt = blockIdx.x;
    const int h  = blockIdx.y;
    const int b  = blockIdx.z;
    const int hoff = h * DKn;

    for (int idx = tid; idx < 208 * 16; idx += 224) {
        int key = idx >> 4, e = idx & 15;
        __half2 val = __floats2half2_rn(0.f, 0.f);
        if (key < NKn)
            val = *(const __half2*)(k + ((size_t)(b * NKn + key)) * Cn + hoff + 2 * e);
        Kp[key * KP_STR + e] = val;
    }
    for (int idx = tid; idx < 104 * 32; idx += 224) {
        int kp = idx >> 5, dv = idx & 31;
        int k0 = 2 * kp, k1 = 2 * kp + 1;
        __half f0 = (k0 < NKn) ? v[((size_t)(b * NKn + k0)) * Cn + hoff + dv] : __float2half(0.f);
        __half f1 = (k1 < NKn) ? v[((size_t)(b * NKn + k1)) * Cn + hoff + dv] : __float2half(0.f);
        Vp[kp * VP_STR + dv] = __halves2half2(f0, f1);
    }
    __syncthreads();

    const int iA = qt * 112 + warp * 16 + gid;

    uint32_t aq[2][4];
    {
        const __half* q0 = q + ((size_t)(b * Pn + iA)) * Cn + hoff;
        const __half* q1 = q0 + 8 * Cn;
#pragma unroll
        for (int kt = 0; kt < 2; kt++) {
            aq[kt][0] = *(const uint32_t*)(q0 + 16 * kt + 2 * tq);
            aq[kt][1] = *(const uint32_t*)(q1 + 16 * kt + 2 * tq);
            aq[kt][2] = *(const uint32_t*)(q0 + 16 * kt + 8 + 2 * tq);
            aq[kt][3] = *(const uint32_t*)(q1 + 16 * kt + 8 + 2 * tq);
        }
    }

    float accS[26][4];
#pragma unroll
    for (int jt = 0; jt < 26; jt++)
#pragma unroll
        for (int r = 0; r < 4; r++) accS[jt][r] = 0.f;
#pragma unroll
    for (int jt = 0; jt < 26; jt++) {
#pragma unroll
        for (int kt = 0; kt < 2; kt++) {
            uint32_t bf[2];
            bf[0] = *(uint32_t*)&Kp[(8 * jt + gid) * KP_STR + 8 * kt + tq];
            bf[1] = *(uint32_t*)&Kp[(8 * jt + gid) * KP_STR + 8 * kt + 4 + tq];
            mma_f16(accS[jt], aq[kt], bf);
        }
    }

    const float scale = 0.17677669529663687f;
    const float* posA = pos + ((size_t)(h * Pn + iA)) * NKn;
    const float* posB = posA + 8 * NKn;
    float mA = -1e30f, mB = -1e30f;
#pragma unroll
    for (int jt = 0; jt < 26; jt++) {
        int col = 8 * jt + 2 * tq;
        if (col < NKn) {
            float2 pA = *(const float2*)(posA + col);
            float2 pB = *(const float2*)(posB + col);
            accS[jt][0] = accS[jt][0] * scale + pA.x;
            accS[jt][1] = accS[jt][1] * scale + pA.y;
            accS[jt][2] = accS[jt][2] * scale + pB.x;
            accS[jt][3] = accS[jt][3] * scale + pB.y;
            mA = fmaxf(mA, fmaxf(accS[jt][0], accS[jt][1]));
            mB = fmaxf(mB, fmaxf(accS[jt][2], accS[jt][3]));
        } else {
            accS[jt][0] = -1e30f; accS[jt][1] = -1e30f;
            accS[jt][2] = -1e30f; accS[jt][3] = -1e30f;
        }
    }
    mA = fmaxf(mA, __shfl_xor_sync(0xffffffffu, mA, 1));
    mA = fmaxf(mA, __shfl_xor_sync(0xffffffffu, mA, 2));
    mB = fmaxf(mB, __shfl_xor_sync(0xffffffffu, mB, 1));
    mB = fmaxf(mB, __shfl_xor_sync(0xffffffffu, mB, 2));
    float lA = 0.f, lB = 0.f;
#pragma unroll
    for (int jt = 0; jt < 26; jt++) {
        accS[jt][0] = __expf(accS[jt][0] - mA);
        accS[jt][1] = __expf(accS[jt][1] - mA);
        accS[jt][2] = __expf(accS[jt][2] - mB);
        accS[jt][3] = __expf(accS[jt][3] - mB);
        lA += accS[jt][0] + accS[jt][1];
        lB += accS[jt][2] + accS[jt][3];
    }
    lA += __shfl_xor_sync(0xffffffffu, lA, 1);
    lA += __shfl_xor_sync(0xffffffffu, lA, 2);
    lB += __shfl_xor_sync(0xffffffffu, lB, 1);
    lB += __shfl_xor_sync(0xffffffffu, lB, 2);

    float accO[4][4];
#pragma unroll
    for (int nt = 0; nt < 4; nt++)
#pragma unroll
        for (int r = 0; r < 4; r++) accO[nt][r] = 0.f;
#pragma unroll
    for (int kt = 0; kt < 13; kt++) {
        uint32_t pa[4];
        pa[0] = packh2(accS[2 * kt][0],     accS[2 * kt][1]);
        pa[1] = packh2(accS[2 * kt][2],     accS[2 * kt][3]);
        pa[2] = packh2(accS[2 * kt + 1][0], accS[2 * kt + 1][1]);
        pa[3] = packh2(accS[2 * kt + 1][2], accS[2 * kt + 1][3]);
#pragma unroll
        for (int nt = 0; nt < 4; nt++) {
            uint32_t bf[2];
            bf[0] = *(uint32_t*)&Vp[(8 * kt + tq) * VP_STR + 8 * nt + gid];
            bf[1] = *(uint32_t*)&Vp[(8 * kt + 4 + tq) * VP_STR + 8 * nt + gid];
            mma_f16(accO[nt], pa, bf);
        }
    }
    float invA = 1.f / lA, invB = 1.f / lB;
    __half2* ob = outT2 + ((size_t)(b * (Cn / 2) + (hoff >> 1))) * Pn;
#pragma unroll
    for (int nt = 0; nt < 4; nt++) {
        int dvp = 4 * nt + tq;
        ob[(size_t)dvp * Pn + iA]     = __floats2half2_rn(accO[nt][0] * invA, accO[nt][1] * invA);
        ob[(size_t)dvp * Pn + iA + 8] = __floats2half2_rn(accO[nt][2] * invB, accO[nt][3] * invB);
    }
}

// ---------------- host launch ----------------
static void* sym_addr(const void* symbol) {
    void* p = nullptr;
    cudaGetSymbolAddress(&p, symbol);
    return p;
}

extern "C" void kernel_launch(void* const* d_in, const int* in_sizes, int n_in,
                              void* d_out, int out_size) {
    const float* x     = (const float*)d_in[0];
    const float* lpu_w = (const float*)d_in[1];
    const float* lpu_b = (const float*)d_in[2];
    const float* dw_w  = (const float*)d_in[3];
    const float* dw_b  = (const float*)d_in[4];
    const float* wq    = (const float*)d_in[5];
    const float* bq    = (const float*)d_in[6];
    const float* wk    = (const float*)d_in[7];
    const float* bk    = (const float*)d_in[8];
    const float* wv    = (const float*)d_in[9];
    const float* bv    = (const float*)d_in[10];
    const float* wo    = (const float*)d_in[11];
    const float* bo    = (const float*)d_in[12];
    const float* pos_b = (const float*)d_in[13];
    const float* c1_w  = (const float*)d_in[14];
    const float* c1_b  = (const float*)d_in[15];
    const float* bn1_g = (const float*)d_in[16];
    const float* bn1_b = (const float*)d_in[17];
    const float* bn1_m = (const float*)d_in[18];
    const float* bn1_v = (const float*)d_in[19];
    const float* dw2_w = (const float*)d_in[20];
    const float* dw2_b = (const float*)d_in[21];
    const float* bn2_g = (const float*)d_in[22];
    const float* bn2_b = (const float*)d_in[23];
    const float* bn2_m = (const float*)d_in[24];
    const float* bn2_v = (const float*)d_in[25];
    const float* c2_w  = (const float*)d_in[26];
    const float* c2_b  = (const float*)d_in[27];
    const float* bn3_g = (const float*)d_in[28];
    const float* bn3_b = (const float*)d_in[29];
    const float* bn3_m = (const float*)d_in[30];
    const float* bn3_v = (const float*)d_in[31];
    float* out = (float*)d_out;

    float*   x1    = (float*)sym_addr(g_x1);
    __half2* x1h   = (__half2*)sym_addr(g_x1h);
    __half2* kvh   = (__half2*)sym_addr(g_kvh);
    float*   x2    = (float*)sym_addr(g_x2);
    __half*  x2h   = (__half*)sym_addr(g_x2h);
    __half*  qh    = (__half*)sym_addr(g_qh);
    __half*  kh    = (__half*)sym_addr(g_kh);
    __half*  vh    = (__half*)sym_addr(g_vh);
    __half2* attTh = (__half2*)sym_addr(g_attTh);
    __half2* t1h   = (__half2*)sym_addr(g_t1h);
    __half2* t2h   = (__half2*)sym_addr(g_t2h);
    __half2* wqh   = (__half2*)sym_addr(g_wqh);
    __half2* wkh   = (__half2*)sym_addr(g_wkh);
    __half2* wvh   = (__half2*)sym_addr(g_wvh);
    __half2* woh   = (__half2*)sym_addr(g_woh);
    __half2* c1h   = (__half2*)sym_addr(g_c1h);
    __half2* c2h   = (__half2*)sym_addr(g_c2h);
    float*   sq    = (float*)sym_addr(g_sq);
    float*   sc1   = (float*)sym_addr(g_sc1);
    float2*  partl = (float2*)sym_addr(g_partl);
    float2*  parto = (float2*)sym_addr(g_parto);
    float2*  mr    = (float2*)sym_addr(g_mr);

    dim3 tb(32, 8);
    // 1. weight packs + rowsums
    k_wpack_all<<<768, tb>>>(wq, wk, wv, wo, c1_w, c2_w, wqh, wkh, wvh, woh, c1h, c2h);
    k_rowsum<<<160, 256>>>(wq, c1_w, sq, sc1);
    // 2. fused pair-LPU (+KV fp16 +LN1 partials +x1h)
    k_lpu2<<<Bn * (Cn / 2), 224>>>(x, lpu_w, lpu_b, dw_w, dw_b, x1, x1h, kvh, partl);
    k_stats_fin_l<<<Bn, 128>>>(partl, mr);
    // 3. merged Q/K/V projections (raw fp16 B; LN folded into Q epilogue)
    k_qkv<<<dim3(22, 1, Bn), 256, SMEM_MMA>>>(
        wqh, wkh, wvh, x1h, kvh, bq, bk, bv, mr, sq, qh, kh, vh);
    // 4. attention -> attTh
    k_attn_mma<<<dim3(7, NH, Bn), 224>>>(qh, kh, vh, pos_b, attTh);
    // 5. O projection + flat residual -> x2 fp32 + x2h flat fp16 mirror (+LN2 partials)
    k_mma<1, 1><<<dim3(7, 2, Bn), 256, SMEM_MMA>>>(
        woh, attTh, bo, nullptr, nullptr, nullptr, nullptr, nullptr, nullptr,
        x1, parto, x2h, x2, Cn, Cn, Pn);
    k_stats_fin_o<<<Bn, 32>>>(parto, mr);
    // 6. c1 + BN1 + GELU (raw flat fp16 B; LN folded into epilogue via rowsum) -> t1h
    k_mma<2, 2><<<dim3(7, 8, Bn), 256, SMEM_MMA>>>(
        c1h, x2h, c1_b, bn1_g, bn1_b, bn1_m, bn1_v, mr, sc1,
        nullptr, nullptr, nullptr, t1h, CMn, Cn, Pn);
    // 7. dw2 + BN2 + GELU -> t2h
    k_dw2pair<<<Bn * (CMn / 2), 224>>>(t1h, dw2_w, dw2_b, bn2_g, bn2_b, bn2_m, bn2_v, t2h);
    // 8. c2 + BN3 + channel-major residual -> d_out
    k_mma<3, 1><<<dim3(7, 2, Bn), 256, SMEM_MMA>>>(
        c2h, t2h, c2_b, bn3_g, bn3_b, bn3_m, bn3_v, nullptr, nullptr,
        x2, nullptr, nullptr, out, Cn, CMn, Pn);
}

// round 15
// speedup vs baseline: 1.1094x; 1.0090x over previous
#include <cuda_runtime.h>
#include <cuda_fp16.h>
#include <math.h>
#include <stdint.h>

// ---------------- problem constants ----------------
#define Bn   32
#define Cn   256
#define Hn   28
#define Wn   28
#define Pn   784          // H*W
#define NKn  196          // (H/2)*(W/2)
#define HKn  14
#define CMn  1024         // C * R
#define NH   8
#define DKn  32
#define EPSf 1e-5f

// ---------------- scratch (device globals; padded for unguarded tile loads) ----------------
__device__ float   g_x1 [Bn*Cn*Pn + 256];        // LPU out fp32 (O-proj flat residual)
__device__ __half2 g_x1h[Bn*(Cn/2)*Pn + 512];    // LPU out fp16 channel-paired
__device__ __half2 g_kvh[Bn*(Cn/2)*NKn + 512];   // KV downsample fp16 channel-paired
__device__ float   g_x2 [Bn*Cn*Pn + 256];        // attn residual fp32 (c2 residual, LN2)
__device__ __half  g_x2h[Bn*Cn*Pn + 1024];       // flat fp16 mirror of x2 (c1 B)
__device__ __half  g_qh [Bn*Pn*Cn + 512];        // Q fp16 row-major [p][oc]
__device__ __half  g_kh [Bn*NKn*Cn + 512];       // K fp16 [nk][256]
__device__ __half  g_vh [Bn*NKn*Cn + 512];       // V fp16 [nk][256]
__device__ __half2 g_attTh[Bn*(Cn/2)*Pn + 512];  // attn out, channel-paired
__device__ __half2 g_t1h  [Bn*(CMn/2)*Pn + 512]; // c1 out, channel-paired
__device__ __half2 g_t2h  [Bn*(CMn/2)*Pn + 512]; // dw2 out, channel-paired
__device__ __half2 g_wqh[(Cn/2)*Cn];             // weights k-paired [k/2][m]
__device__ __half2 g_wkh[(Cn/2)*Cn];
__device__ __half2 g_wvh[(Cn/2)*Cn];
__device__ __half2 g_woh[(Cn/2)*Cn];
__device__ __half2 g_c1h[(Cn/2)*CMn];
__device__ __half2 g_c2h[(CMn/2)*Cn];
__device__ float   g_sq [Cn];                    // rowsum(wq)
__device__ float   g_sc1[CMn];                   // rowsum(c1_w)
__device__ float2  g_partl[Bn*(Cn/2)];           // LN1 partials (per pair-plane)
__device__ float2  g_parto[Bn*14];               // LN2 partials

__device__ __forceinline__ float gelu_f(float v) {
    return 0.5f * v * (1.0f + erff(v * 0.7071067811865475f));
}
__device__ __forceinline__ void mma_f16(float* c, const uint32_t* a, const uint32_t* b) {
    asm volatile(
        "mma.sync.aligned.m16n8k16.row.col.f32.f16.f16.f32 "
        "{%0,%1,%2,%3}, {%4,%5,%6,%7}, {%8,%9}, {%0,%1,%2,%3};"
        : "+f"(c[0]), "+f"(c[1]), "+f"(c[2]), "+f"(c[3])
        : "r"(a[0]), "r"(a[1]), "r"(a[2]), "r"(a[3]), "r"(b[0]), "r"(b[1]));
}
__device__ __forceinline__ uint32_t packh2(float lo, float hi) {
    __half2 h = __floats2half2_rn(lo, hi);
    return *(uint32_t*)&h;
}

#define H2STR 136
#define KSTR  132
#define STAGE (32*H2STR)
#define SMEM_MMA (2*STAGE*4)   // 34816 B

// ====================== k_mma (256 thr, 128x128 — proven config) ======================
// BK 1: B = half2 k-paired [k/2][P] raw
// BK 2: B = flat __half [k][P] (channel rows), interleave via byte_perm
// MODE 1: f32 out[p*M+m] = acc + bias + res; +flat fp16 mirror xmir; LN2 partials -> pstat
// MODE 2: half2 out[(m/2)*P+p] = gelu(BN(acc*rstd + cb - mean*rstd*S)) ; mean/rstd reduced
//         in-kernel from pstat (14 partials per batch)
// MODE 3: f32 out[m*P+p] = BN(acc + bias) + res
template <int MODE, int BK>
__global__ void __launch_bounds__(256, 2) k_mma(
    const __half2* __restrict__ Wh, const void* __restrict__ Xv,
    const float* __restrict__ bias,
    const float* __restrict__ bng, const float* __restrict__ bnb,
    const float* __restrict__ bnm, const float* __restrict__ bnv,
    const float* __restrict__ rsum,
    const float* __restrict__ res, float2* __restrict__ pstat,
    __half* __restrict__ xmir,
    void* __restrict__ outv, int M, int K, int P) {
    extern __shared__ float sm[];
    const int tid  = threadIdx.x;
    const int warp = tid >> 5, lane = tid & 31;
    const int gid = lane >> 2, tq = lane & 3;
    const int wm = (warp & 1) * 64;
    const int wn = (warp >> 1) * 32;
    const int b  = blockIdx.z;
    const int m0 = blockIdx.y * 128;
    const int n0 = blockIdx.x * 128;
    const __half2* Xh2 = (BK == 1) ? (const __half2*)Xv + (size_t)b * (K >> 1) * P : nullptr;
    const __half*  Xhf = (BK == 2) ? (const __half*)Xv + (size_t)b * K * P : nullptr;

    float acc[4][4][4];
#pragma unroll
    for (int i = 0; i < 4; i++)
#pragma unroll
        for (int j = 0; j < 4; j++)
#pragma unroll
            for (int r = 0; r < 4; r++) acc[i][j][r] = 0.f;

    const int kk = tid >> 4;
    const int mq = (tid & 15) * 8;
    uint4 pa0, pa1, pb0, pb1;
    const int T = K >> 5;

    auto load_chunk = [&](int kc0) {
        const uint4* wr = (const uint4*)(Wh + (size_t)((kc0 >> 1) + kk) * M + m0 + mq);
        pa0 = wr[0]; pa1 = wr[1];
        if (BK == 1) {
            const uint4* xr = (const uint4*)(Xh2 + (size_t)((kc0 >> 1) + kk) * P + n0 + mq);
            pb0 = xr[0]; pb1 = xr[1];
        } else {
            const uint4 r0 = *(const uint4*)(Xhf + (size_t)(kc0 + 2 * kk) * P + n0 + mq);
            const uint4 r1 = *(const uint4*)(Xhf + (size_t)(kc0 + 2 * kk + 1) * P + n0 + mq);
            pb0 = make_uint4(__byte_perm(r0.x, r1.x, 0x5410), __byte_perm(r0.x, r1.x, 0x7632),
                             __byte_perm(r0.y, r1.y, 0x5410), __byte_perm(r0.y, r1.y, 0x7632));
            pb1 = make_uint4(__byte_perm(r0.z, r1.z, 0x5410), __byte_perm(r0.z, r1.z, 0x7632),
                             __byte_perm(r0.w, r1.w, 0x5410), __byte_perm(r0.w, r1.w, 0x7632));
        }
    };
    auto store_chunk = [&](int s) {
        __half2* As2 = (__half2*)sm + s * STAGE;
        __half2* Bs2 = As2 + 16 * H2STR;
        *(uint4*)&As2[kk * H2STR + mq]     = pa0;
        *(uint4*)&As2[kk * H2STR + mq + 4] = pa1;
        *(uint4*)&Bs2[kk * H2STR + mq]     = pb0;
        *(uint4*)&Bs2[kk * H2STR + mq + 4] = pb1;
    };

    load_chunk(0);
    store_chunk(0);
    __syncthreads();

    for (int t = 0; t < T; t++) {
        if (t + 1 < T) load_chunk((t + 1) << 5);
        const __half2* As2 = (const __half2*)sm + (t & 1) * STAGE;
        const __half2* Bs2 = As2 + 16 * H2STR;
#pragma unroll
        for (int ks = 0; ks < 2; ks++) {
            const int r0 = ks * 8;
            uint32_t af[4][4], bf[4][2];
#pragma unroll
            for (int i = 0; i < 4; i++) {
                int m = wm + i * 16 + gid;
                af[i][0] = *(uint32_t*)&As2[(r0 + tq) * H2STR + m];
                af[i][1] = *(uint32_t*)&As2[(r0 + tq) * H2STR + m + 8];
                af[i][2] = *(uint32_t*)&As2[(r0 + tq + 4) * H2STR + m];
                af[i][3] = *(uint32_t*)&As2[(r0 + tq + 4) * H2STR + m + 8];
            }
#pragma unroll
            for (int j = 0; j < 4; j++) {
                int p = wn + j * 8 + gid;
                bf[j][0] = *(uint32_t*)&Bs2[(r0 + tq) * H2STR + p];
                bf[j][1] = *(uint32_t*)&Bs2[(r0 + tq + 4) * H2STR + p];
            }
#pragma unroll
            for (int i = 0; i < 4; i++)
#pragma unroll
                for (int j = 0; j < 4; j++) mma_f16(acc[i][j], af[i], bf[j]);
        }
        if (t + 1 < T) {
            store_chunk((t + 1) & 1);
            __syncthreads();
        }
    }

    // LN scalars for MODE 2: reduce the 14 per-batch partials in-kernel (fixed tree)
    float mean = 0.f, rstd = 1.f;
    if (MODE == 2) {
        __syncthreads();
        if (tid < 32) {
            float2 p = (tid < 14) ? pstat[b * 14 + tid] : make_float2(0.f, 0.f);
#pragma unroll
            for (int o = 16; o >= 1; o >>= 1) {
                p.x += __shfl_down_sync(0xffffffffu, p.x, o);
                p.y += __shfl_down_sync(0xffffffffu, p.y, o);
            }
            if (tid == 0) {
                const float n = (float)(Cn * Pn);
                float m  = p.x / n;
                float vv = p.y / n - m * m;
                sm[0] = m;
                sm[1] = rsqrtf(vv + EPSf);
            }
        }
        __syncthreads();
        mean = sm[0]; rstd = sm[1];
    }

    // ---- epilogue: two 64-row passes staged through smem ----
    float* sD = sm;
    float*   outf  = (MODE == 1 || MODE == 3) ? (float*)outv + (size_t)b * (size_t)M * P : nullptr;
    __half2* outh2 = (MODE == 2) ? (__half2*)outv + (size_t)b * (size_t)(M >> 1) * P : nullptr;
    __half*  xmb   = (MODE == 1) ? xmir + (size_t)b * (size_t)M * P : nullptr;
    const float* resb = (MODE == 1 || MODE == 3) ? res + (size_t)b * (size_t)M * P : nullptr;
    float osum = 0.f, osq = 0.f;

#pragma unroll
    for (int pass = 0; pass < 2; pass++) {
        __syncthreads();
        if (MODE == 1) {
            if ((wn >> 6) == pass) {
#pragma unroll
                for (int i = 0; i < 4; i++) {
                    int mrow = wm + i * 16 + gid;
#pragma unroll
                    for (int j = 0; j < 4; j++) {
                        int pc = (wn & 63) + j * 8 + 2 * tq;
                        sD[pc * KSTR + mrow]           = acc[i][j][0];
                        sD[(pc + 1) * KSTR + mrow]     = acc[i][j][1];
                        sD[pc * KSTR + mrow + 8]       = acc[i][j][2];
                        sD[(pc + 1) * KSTR + mrow + 8] = acc[i][j][3];
                    }
                }
            }
        } else {
            if ((wm >> 6) == pass) {
#pragma unroll
                for (int i = 0; i < 4; i++) {
                    int ml = (wm & 63) + i * 16 + gid;
#pragma unroll
                    for (int j = 0; j < 4; j++) {
                        int pc = wn + j * 8 + 2 * tq;
                        sD[ml * KSTR + pc]           = acc[i][j][0];
                        sD[ml * KSTR + pc + 1]       = acc[i][j][1];
                        sD[(ml + 8) * KSTR + pc]     = acc[i][j][2];
                        sD[(ml + 8) * KSTR + pc + 1] = acc[i][j][3];
                    }
                }
            }
        }
        __syncthreads();
        if (MODE == 1) {
            for (int l = tid; l < 64 * 32; l += 256) {
                int rl = l >> 5, cq = (l & 31) * 4;
                int p = n0 + pass * 64 + rl;
                if (p >= P) continue;
                float4 v = *(float4*)&sD[rl * KSTR + cq];
                float4 bb = *(const float4*)(bias + m0 + cq);
                v.x += bb.x; v.y += bb.y; v.z += bb.z; v.w += bb.w;
                size_t off = (size_t)p * M + m0 + cq;
                float4 rr = *(const float4*)(resb + off);
                v.x += rr.x; v.y += rr.y; v.z += rr.z; v.w += rr.w;
                *(float4*)(outf + off) = v;
                __half2 h01 = __floats2half2_rn(v.x, v.y);
                __half2 h23 = __floats2half2_rn(v.z, v.w);
                *(uint2*)(xmb + off) = make_uint2(*(uint32_t*)&h01, *(uint32_t*)&h23);
                osum += v.x + v.y + v.z + v.w;
                osq  += v.x * v.x + v.y * v.y + v.z * v.z + v.w * v.w;
            }
        } else if (MODE == 2) {
            for (int l = tid; l < 32 * 32; l += 256) {
                int rp = l >> 5, cq = (l & 31) * 4;
                int m = m0 + pass * 64 + 2 * rp;
                int p = n0 + cq;
                if (p >= P) continue;
                float sc0 = bng[m] * rsqrtf(bnv[m] + EPSf);
                float sh0 = bnb[m] - bnm[m] * sc0
                          + (bias[m] - mean * rstd * rsum[m]) * sc0;
                float a0 = rstd * sc0;
                float sc1 = bng[m + 1] * rsqrtf(bnv[m + 1] + EPSf);
                float sh1 = bnb[m + 1] - bnm[m + 1] * sc1
                          + (bias[m + 1] - mean * rstd * rsum[m + 1]) * sc1;
                float a1 = rstd * sc1;
                float4 v0 = *(float4*)&sD[(2 * rp) * KSTR + cq];
                float4 v1 = *(float4*)&sD[(2 * rp + 1) * KSTR + cq];
                v0.x = gelu_f(v0.x * a0 + sh0); v0.y = gelu_f(v0.y * a0 + sh0);
                v0.z = gelu_f(v0.z * a0 + sh0); v0.w = gelu_f(v0.w * a0 + sh0);
                v1.x = gelu_f(v1.x * a1 + sh1); v1.y = gelu_f(v1.y * a1 + sh1);
                v1.z = gelu_f(v1.z * a1 + sh1); v1.w = gelu_f(v1.w * a1 + sh1);
                uint4 u = make_uint4(packh2(v0.x, v1.x), packh2(v0.y, v1.y),
                                     packh2(v0.z, v1.z), packh2(v0.w, v1.w));
                *(uint4*)(outh2 + (size_t)(m >> 1) * P + p) = u;
            }
        } else {
            for (int l = tid; l < 64 * 32; l += 256) {
                int rl = l >> 5, cq = (l & 31) * 4;
                int m = m0 + pass * 64 + rl;
                int p = n0 + cq;
                if (p >= P) continue;
                float scale = bng[m] * rsqrtf(bnv[m] + EPSf);
                float shift = bnb[m] - bnm[m] * scale + bias[m] * scale;
                float4 v = *(float4*)&sD[rl * KSTR + cq];
                v.x = v.x * scale + shift; v.y = v.y * scale + shift;
                v.z = v.z * scale + shift; v.w = v.w * scale + shift;
                size_t off = (size_t)m * P + p;
                float4 rr = *(const float4*)(resb + off);
                v.x += rr.x; v.y += rr.y; v.z += rr.z; v.w += rr.w;
                *(float4*)(outf + off) = v;
            }
        }
    }

    if (MODE == 1) {
        __syncthreads();
        float* r1 = sm;
        float* r2 = sm + 256;
        r1[tid] = osum; r2[tid] = osq;
        __syncthreads();
        for (int st = 128; st > 0; st >>= 1) {
            if (tid < st) { r1[tid] += r1[tid + st]; r2[tid] += r2[tid + st]; }
            __syncthreads();
        }
        if (tid == 0)
            pstat[b * 14 + blockIdx.y * gridDim.x + blockIdx.x] = make_float2(r1[0], r2[0]);
    }
}

// ====================== merged QKV (256 thr; LN1 finisher folded into Q epilogue) ======================
__global__ void __launch_bounds__(256, 2) k_qkv(
    const __half2* __restrict__ wqh, const __half2* __restrict__ wkh,
    const __half2* __restrict__ wvh,
    const __half2* __restrict__ x1h, const __half2* __restrict__ kvh,
    const float* __restrict__ bq, const float* __restrict__ bk,
    const float* __restrict__ bv, const float2* __restrict__ partl,
    const float* __restrict__ sq,
    __half* __restrict__ qh, __half* __restrict__ kh, __half* __restrict__ vh) {
    extern __shared__ float sm[];
    const int tid  = threadIdx.x;
    const int warp = tid >> 5, lane = tid & 31;
    const int gid = lane >> 2, tq = lane & 3;
    const int wm = (warp & 1) * 64;
    const int wn = (warp >> 1) * 32;
    const int b  = blockIdx.z;
    const int id = blockIdx.x;  // 0..21

    const __half2* Wh;
    const __half2* Xh2;
    const float* bias;
    __half* outp;
    int P, m0, n0;
    bool isQ = false;
    if (id < 14) {
        Wh = wqh; Xh2 = x1h + (size_t)b * (Cn / 2) * Pn; bias = bq;
        outp = qh + (size_t)b * Pn * Cn;
        P = Pn; isQ = true; m0 = (id / 7) * 128; n0 = (id % 7) * 128;
    } else if (id < 18) {
        int t = id - 14;
        Wh = wkh; Xh2 = kvh + (size_t)b * (Cn / 2) * NKn; bias = bk;
        outp = kh + (size_t)b * NKn * Cn;
        P = NKn; m0 = (t >> 1) * 128; n0 = (t & 1) * 128;
    } else {
        int t = id - 18;
        Wh = wvh; Xh2 = kvh + (size_t)b * (Cn / 2) * NKn; bias = bv;
        outp = vh + (size_t)b * NKn * Cn;
        P = NKn; m0 = (t >> 1) * 128; n0 = (t & 1) * 128;
    }

    float acc[4][4][4];
#pragma unroll
    for (int i = 0; i < 4; i++)
#pragma unroll
        for (int j = 0; j < 4; j++)
#pragma unroll
            for (int r = 0; r < 4; r++) acc[i][j][r] = 0.f;

    const int kk = tid >> 4;
    const int mq = (tid & 15) * 8;
    uint4 pa0, pa1, pb0, pb1;
    const int T = Cn >> 5;  // 8

    auto load_chunk = [&](int kp0) {
        const uint4* wr = (const uint4*)(Wh + (size_t)(kp0 + kk) * Cn + m0 + mq);
        pa0 = wr[0]; pa1 = wr[1];
        const uint4* xr = (const uint4*)(Xh2 + (size_t)(kp0 + kk) * P + n0 + mq);
        pb0 = xr[0]; pb1 = xr[1];
    };
    auto store_chunk = [&](int s) {
        __half2* As2 = (__half2*)sm + s * STAGE;
        __half2* Bs2 = As2 + 16 * H2STR;
        *(uint4*)&As2[kk * H2STR + mq]     = pa0;
        *(uint4*)&As2[kk * H2STR + mq + 4] = pa1;
        *(uint4*)&Bs2[kk * H2STR + mq]     = pb0;
        *(uint4*)&Bs2[kk * H2STR + mq + 4] = pb1;
    };

    load_chunk(0);
    store_chunk(0);
    __syncthreads();

    for (int t = 0; t < T; t++) {
        if (t + 1 < T) load_chunk((t + 1) << 4);
        const __half2* As2 = (const __half2*)sm + (t & 1) * STAGE;
        const __half2* Bs2 = As2 + 16 * H2STR;
#pragma unroll
        for (int ks = 0; ks < 2; ks++) {
            const int r0 = ks * 8;
            uint32_t af[4][4], bf[4][2];
#pragma unroll
            for (int i = 0; i < 4; i++) {
                int m = wm + i * 16 + gid;
                af[i][0] = *(uint32_t*)&As2[(r0 + tq) * H2STR + m];
                af[i][1] = *(uint32_t*)&As2[(r0 + tq) * H2STR + m + 8];
                af[i][2] = *(uint32_t*)&As2[(r0 + tq + 4) * H2STR + m];
                af[i][3] = *(uint32_t*)&As2[(r0 + tq + 4) * H2STR + m + 8];
            }
#pragma unroll
            for (int j = 0; j < 4; j++) {
                int p = wn + j * 8 + gid;
                bf[j][0] = *(uint32_t*)&Bs2[(r0 + tq) * H2STR + p];
                bf[j][1] = *(uint32_t*)&Bs2[(r0 + tq + 4) * H2STR + p];
            }
#pragma unroll
            for (int i = 0; i < 4; i++)
#pragma unroll
                for (int j = 0; j < 4; j++) mma_f16(acc[i][j], af[i], bf[j]);
        }
        if (t + 1 < T) {
            store_chunk((t + 1) & 1);
            __syncthreads();
        }
    }

    // LN1 finisher folded in: reduce 128 partials (fixed tree, deterministic)
    float scl = 1.f, moff = 0.f;
    if (isQ) {
        __syncthreads();
        if (tid < 128) {
            float2 p = partl[b * 128 + tid];
            sm[tid] = p.x;
            sm[128 + tid] = p.y;
        }
        __syncthreads();
        for (int st = 64; st > 0; st >>= 1) {
            if (tid < st) { sm[tid] += sm[tid + st]; sm[128 + tid] += sm[128 + tid + st]; }
            __syncthreads();
        }
        if (tid == 0) {
            const float n = (float)(Cn * Pn);
            float m  = sm[0] / n;
            float vv = sm[128] / n - m * m;
            sm[0] = m;
            sm[1] = rsqrtf(vv + EPSf);
        }
        __syncthreads();
        float mn = sm[0], rs = sm[1];
        scl = rs; moff = -mn * rs;
    }

    float* sD = sm;
#pragma unroll
    for (int pass = 0; pass < 2; pass++) {
        __syncthreads();
        if ((wn >> 6) == pass) {
#pragma unroll
            for (int i = 0; i < 4; i++) {
                int mrow = wm + i * 16 + gid;
#pragma unroll
                for (int j = 0; j < 4; j++) {
                    int pc = (wn & 63) + j * 8 + 2 * tq;
                    sD[pc * KSTR + mrow]           = acc[i][j][0];
                    sD[(pc + 1) * KSTR + mrow]     = acc[i][j][1];
                    sD[pc * KSTR + mrow + 8]       = acc[i][j][2];
                    sD[(pc + 1) * KSTR + mrow + 8] = acc[i][j][3];
                }
            }
        }
        __syncthreads();
        for (int l = tid; l < 64 * 32; l += 256) {
            int rl = l >> 5, cq = (l & 31) * 4;
            int p = n0 + pass * 64 + rl;
            if (p >= P) continue;
            float4 v = *(float4*)&sD[rl * KSTR + cq];
            float4 bb = *(const float4*)(bias + m0 + cq);
            if (isQ) {
                float4 ss = *(const float4*)(sq + m0 + cq);
                v.x = v.x * scl + bb.x + moff * ss.x;
                v.y = v.y * scl + bb.y + moff * ss.y;
                v.z = v.z * scl + bb.z + moff * ss.z;
                v.w = v.w * scl + bb.w + moff * ss.w;
            } else {
                v.x += bb.x; v.y += bb.y; v.z += bb.z; v.w += bb.w;
            }
            __half2 h01 = __floats2half2_rn(v.x, v.y);
            __half2 h23 = __floats2half2_rn(v.z, v.w);
            uint2 u = make_uint2(*(uint32_t*)&h01, *(uint32_t*)&h23);
            *(uint2*)(outp + (size_t)p * Cn + m0 + cq) = u;
        }
    }
}

// ---------------- merged weight pack + rowsums (one launch) ----------------
__global__ void k_wpack_all(
    const float* __restrict__ wq, const float* __restrict__ wk,
    const float* __restrict__ wv, const float* __restrict__ wo,
    const float* __restrict__ c1w, const float* __restrict__ c2w,
    __half2* __restrict__ oq, __half2* __restrict__ ok,
    __half2* __restrict__ ov, __half2* __restrict__ oo,
    __half2* __restrict__ oc1, __half2* __restrict__ oc2,
    float* __restrict__ sq, float* __restrict__ sc1) {
    __shared__ float t[32][33];
    int id = blockIdx.x;
    int tx = threadIdx.x, ty = threadIdx.y;
    if (id >= 768) {
        // rowsum blocks (ids 768..927): 8 rows per block, 1 warp per row
        int tt = ty * 32 + tx;
        int w = ((id - 768) * 256 + tt) >> 5;    // 0..1279
        int lane = tt & 31;
        const float* row;
        float* outr;
        if (w < Cn) { row = wq + (size_t)w * Cn; outr = sq + w; }
        else        { row = c1w + (size_t)(w - Cn) * Cn; outr = sc1 + (w - Cn); }
        float s = 0.f;
        for (int i = lane; i < Cn; i += 32) s += row[i];
#pragma unroll
        for (int o = 16; o >= 1; o >>= 1) s += __shfl_down_sync(0xffffffffu, s, o);
        if (lane == 0) *outr = s;
        return;
    }
    const float* in;
    __half2* out;
    int M, K, tile;
    if (id < 256) {
        int w = id >> 6; tile = id & 63;
        in  = (w == 0) ? wq : (w == 1) ? wk : (w == 2) ? wv : wo;
        out = (w == 0) ? oq : (w == 1) ? ok : (w == 2) ? ov : oo;
        M = Cn; K = Cn;
    } else if (id < 512) {
        tile = id - 256;
        in = c1w; out = oc1; M = CMn; K = Cn;
    } else {
        tile = id - 512;
        in = c2w; out = oc2; M = Cn; K = CMn;
    }
    int ktiles = K >> 5;
    int m0 = (tile / ktiles) * 32, k0 = (tile % ktiles) * 32;
#pragma unroll
    for (int q = 0; q < 32; q += 8)
        t[ty + q][tx] = in[(size_t)(m0 + ty + q) * K + k0 + tx];
    __syncthreads();
#pragma unroll
    for (int q = 0; q < 2; q++) {
        int kp = ty + q * 8;
        __half2 val = __floats2half2_rn(t[tx][2 * kp], t[tx][2 * kp + 1]);
        out[(size_t)((k0 >> 1) + kp) * M + m0 + tx] = val;
    }
}

// ------- fused pair-LPU: conv+res -> x1 fp32 + x1h pairs; KV -> kvh pairs; LN1 partials -------
__global__ void __launch_bounds__(224) k_lpu2(
    const float* __restrict__ X, const float* __restrict__ w,
    const float* __restrict__ bias,
    const float* __restrict__ wkv, const float* __restrict__ bkv,
    float* __restrict__ x1, __half2* __restrict__ x1h,
    __half2* __restrict__ kvh, float2* __restrict__ partl) {
    __shared__ float sp0[900], sp1[900];
    __shared__ float so0[784], so1[784];
    __shared__ float r1[224], r2[224];
    int bc = blockIdx.x;
    int b  = bc >> 7;          // Cn/2 = 128
    int mp = bc & 127;
    int c0 = 2 * mp;
    const float* xin = X + ((size_t)b * Cn + c0) * Pn;
    int tid = threadIdx.x;
    for (int i = tid; i < 900; i += 224) { sp0[i] = 0.f; sp1[i] = 0.f; }
    float wa[9], wb[9];
#pragma unroll
    for (int i = 0; i < 9; i++) { wa[i] = w[c0 * 9 + i]; wb[i] = w[(c0 + 1) * 9 + i]; }
    float bs0 = bias[c0], bs1 = bias[c0 + 1];
    __syncthreads();
    for (int i = tid; i < Pn; i += 224) {
        int o = (i / 28 + 1) * 30 + (i % 28) + 1;
        sp0[o] = xin[i];
        sp1[o] = xin[Pn + i];
    }
    __syncthreads();
    float lsum = 0.f, lsq = 0.f;
    if (tid < 196) {
        int px = tid % 28, sy = (tid / 28) * 4;
        float a0[6][3], a1[6][3];
#pragma unroll
        for (int dr = 0; dr < 6; dr++) {
            int base = (sy + dr) * 30 + px;
            a0[dr][0] = sp0[base]; a0[dr][1] = sp0[base + 1]; a0[dr][2] = sp0[base + 2];
            a1[dr][0] = sp1[base]; a1[dr][1] = sp1[base + 1]; a1[dr][2] = sp1[base + 2];
        }
        float* ob = x1 + ((size_t)b * Cn + c0) * Pn;
        __half2* oh = x1h + ((size_t)b * (Cn / 2) + mp) * Pn;
#pragma unroll
        for (int i = 0; i < 4; i++) {
            float acc0 = bs0
                + wa[0] * a0[i][0]     + wa[1] * a0[i][1]     + wa[2] * a0[i][2]
                + wa[3] * a0[i + 1][0] + wa[4] * a0[i + 1][1] + wa[5] * a0[i + 1][2]
                + wa[6] * a0[i + 2][0] + wa[7] * a0[i + 2][1] + wa[8] * a0[i + 2][2];
            float acc1 = bs1
                + wb[0] * a1[i][0]     + wb[1] * a1[i][1]     + wb[2] * a1[i][2]
                + wb[3] * a1[i + 1][0] + wb[4] * a1[i + 1][1] + wb[5] * a1[i + 1][2]
                + wb[6] * a1[i + 2][0] + wb[7] * a1[i + 2][1] + wb[8] * a1[i + 2][2];
            float y0 = acc0 + a0[i + 1][1];
            float y1 = acc1 + a1[i + 1][1];
            int p = (sy + i) * 28 + px;
            so0[p] = y0; so1[p] = y1;
            ob[p] = y0; ob[Pn + p] = y1;
            oh[p] = __floats2half2_rn(y0, y1);
            lsum += y0 + y1; lsq += y0 * y0 + y1 * y1;
        }
    }
    r1[tid] = lsum; r2[tid] = lsq;
    __syncthreads();
    for (int st = 112; st >= 7; st >>= 1) {
        if (tid < st) { r1[tid] += r1[tid + st]; r2[tid] += r2[tid + st]; }
        __syncthreads();
    }
    if (tid == 0) {
        float s = 0.f, qv = 0.f;
#pragma unroll
        for (int i = 0; i < 7; i++) { s += r1[i]; qv += r2[i]; }
        partl[bc] = make_float2(s, qv);
    }
    if (tid < 196) {
        int oy = tid / HKn, ox = tid % HKn;
        int i00 = (2 * oy) * 28 + 2 * ox;
        float k0 = bkv[c0]
            + wkv[c0 * 4 + 0] * so0[i00]      + wkv[c0 * 4 + 1] * so0[i00 + 1]
            + wkv[c0 * 4 + 2] * so0[i00 + 28] + wkv[c0 * 4 + 3] * so0[i00 + 29];
        float k1 = bkv[c0 + 1]
            + wkv[(c0 + 1) * 4 + 0] * so1[i00]      + wkv[(c0 + 1) * 4 + 1] * so1[i00 + 1]
            + wkv[(c0 + 1) * 4 + 2] * so1[i00 + 28] + wkv[(c0 + 1) * 4 + 3] * so1[i00 + 29];
        kvh[((size_t)b * (Cn / 2) + mp) * NKn + tid] = __floats2half2_rn(k0, k1);
    }
}

// ---------------- dw2: channel-pair fp16 in/out ----------------
__global__ void __launch_bounds__(224) k_dw2pair(
    const __half2* __restrict__ X2, const float* __restrict__ w,
    const float* __restrict__ bias,
    const float* __restrict__ bng, const float* __restrict__ bnb,
    const float* __restrict__ bnm, const float* __restrict__ bnv,
    __half2* __restrict__ out2) {
    __shared__ float sp0[900], sp1[900];
    int bc = blockIdx.x;
    int b  = bc >> 9;
    int mp = bc & 511;
    int c0 = 2 * mp;
    const __half2* x0 = X2 + ((size_t)b * (CMn / 2) + mp) * Pn;
    int tid = threadIdx.x;
    for (int i = tid; i < 900; i += 224) { sp0[i] = 0.f; sp1[i] = 0.f; }
    float wa[9], wb[9];
#pragma unroll
    for (int i = 0; i < 9; i++) { wa[i] = w[c0 * 9 + i]; wb[i] = w[(c0 + 1) * 9 + i]; }
    float bs0 = bias[c0], bs1 = bias[c0 + 1];
    float sc0 = bng[c0] * rsqrtf(bnv[c0] + EPSf);
    float sh0 = bnb[c0] - bnm[c0] * sc0;
    float sc1 = bng[c0 + 1] * rsqrtf(bnv[c0 + 1] + EPSf);
    float sh1 = bnb[c0 + 1] - bnm[c0 + 1] * sc1;
    __syncthreads();
    for (int i = tid; i < Pn; i += 224) {
        int o = (i / 28 + 1) * 30 + (i % 28) + 1;
        float2 f = __half22float2(x0[i]);
        sp0[o] = f.x;
        sp1[o] = f.y;
    }
    __syncthreads();
    if (tid < 196) {
        int px = tid % 28, sy = (tid / 28) * 4;
        float a0[6][3], a1[6][3];
#pragma unroll
        for (int dr = 0; dr < 6; dr++) {
            int base = (sy + dr) * 30 + px;
            a0[dr][0] = sp0[base]; a0[dr][1] = sp0[base + 1]; a0[dr][2] = sp0[base + 2];
            a1[dr][0] = sp1[base]; a1[dr][1] = sp1[base + 1]; a1[dr][2] = sp1[base + 2];
        }
        __half2* ob = out2 + ((size_t)b * (CMn / 2) + mp) * Pn;
#pragma unroll
        for (int i = 0; i < 4; i++) {
            float acc0 = bs0
                + wa[0] * a0[i][0]     + wa[1] * a0[i][1]     + wa[2] * a0[i][2]
                + wa[3] * a0[i + 1][0] + wa[4] * a0[i + 1][1] + wa[5] * a0[i + 1][2]
                + wa[6] * a0[i + 2][0] + wa[7] * a0[i + 2][1] + wa[8] * a0[i + 2][2];
            float acc1 = bs1
                + wb[0] * a1[i][0]     + wb[1] * a1[i][1]     + wb[2] * a1[i][2]
                + wb[3] * a1[i + 1][0] + wb[4] * a1[i + 1][1] + wb[5] * a1[i + 1][2]
                + wb[6] * a1[i + 2][0] + wb[7] * a1[i + 2][1] + wb[8] * a1[i + 2][2];
            float y0 = gelu_f(acc0 * sc0 + sh0);
            float y1 = gelu_f(acc1 * sc1 + sh1);
            ob[(sy + i) * 28 + px] = __floats2half2_rn(y0, y1);
        }
    }
}

// ================= fp16 mma attention =================
#define KP_STR 20
#define VP_STR 40

__global__ void __launch_bounds__(224, 1) k_attn_mma(
    const __half* __restrict__ q, const __half* __restrict__ k,
    const __half* __restrict__ v, const float* __restrict__ pos,
    __half2* __restrict__ outT2) {
    __shared__ __half2 Kp[208 * KP_STR];
    __shared__ __half2 Vp[104 * VP_STR];
    const int tid = threadIdx.x;
    const int warp = tid >> 5, lane = tid & 31;
    const int gid = lane >> 2, tq = lane & 3;
    const int qt = blockIdx.x;
    const int h  = blockIdx.y;
    const int b  = blockIdx.z;
    const int hoff = h * DKn;

    for (int idx = tid; idx < 208 * 16; idx += 224) {
        int key = idx >> 4, e = idx & 15;
        __half2 val = __floats2half2_rn(0.f, 0.f);
        if (key < NKn)
            val = *(const __half2*)(k + ((size_t)(b * NKn + key)) * Cn + hoff + 2 * e);
        Kp[key * KP_STR + e] = val;
    }
    for (int idx = tid; idx < 104 * 32; idx += 224) {
        int kp = idx >> 5, dv = idx & 31;
        int k0 = 2 * kp, k1 = 2 * kp + 1;
        __half f0 = (k0 < NKn) ? v[((size_t)(b * NKn + k0)) * Cn + hoff + dv] : __float2half(0.f);
        __half f1 = (k1 < NKn) ? v[((size_t)(b * NKn + k1)) * Cn + hoff + dv] : __float2half(0.f);
        Vp[kp * VP_STR + dv] = __halves2half2(f0, f1);
    }
    __syncthreads();

    const int iA = qt * 112 + warp * 16 + gid;

    uint32_t aq[2][4];
    {
        const __half* q0 = q + ((size_t)(b * Pn + iA)) * Cn + hoff;
        const __half* q1 = q0 + 8 * Cn;
#pragma unroll
        for (int kt = 0; kt < 2; kt++) {
            aq[kt][0] = *(const uint32_t*)(q0 + 16 * kt + 2 * tq);
            aq[kt][1] = *(const uint32_t*)(q1 + 16 * kt + 2 * tq);
            aq[kt][2] = *(const uint32_t*)(q0 + 16 * kt + 8 + 2 * tq);
            aq[kt][3] = *(const uint32_t*)(q1 + 16 * kt + 8 + 2 * tq);
        }
    }

    float accS[26][4];
#pragma unroll
    for (int jt = 0; jt < 26; jt++)
#pragma unroll
        for (int r = 0; r < 4; r++) accS[jt][r] = 0.f;
#pragma unroll
    for (int jt = 0; jt < 26; jt++) {
#pragma unroll
        for (int kt = 0; kt < 2; kt++) {
            uint32_t bf[2];
            bf[0] = *(uint32_t*)&Kp[(8 * jt + gid) * KP_STR + 8 * kt + tq];
            bf[1] = *(uint32_t*)&Kp[(8 * jt + gid) * KP_STR + 8 * kt + 4 + tq];
            mma_f16(accS[jt], aq[kt], bf);
        }
    }

    const float scale = 0.17677669529663687f;
    const float* posA = pos + ((size_t)(h * Pn + iA)) * NKn;
    const float* posB = posA + 8 * NKn;
    float mA = -1e30f, mB = -1e30f;
#pragma unroll
    for (int jt = 0; jt < 26; jt++) {
        int col = 8 * jt + 2 * tq;
        if (col < NKn) {
            float2 pA = *(const float2*)(posA + col);
            float2 pB = *(const float2*)(posB + col);
            accS[jt][0] = accS[jt][0] * scale + pA.x;
            accS[jt][1] = accS[jt][1] * scale + pA.y;
            accS[jt][2] = accS[jt][2] * scale + pB.x;
            accS[jt][3] = accS[jt][3] * scale + pB.y;
            mA = fmaxf(mA, fmaxf(accS[jt][0], accS[jt][1]));
            mB = fmaxf(mB, fmaxf(accS[jt][2], accS[jt][3]));
        } else {
            accS[jt][0] = -1e30f; accS[jt][1] = -1e30f;
            accS[jt][2] = -1e30f; accS[jt][3] = -1e30f;
        }
    }
    mA = fmaxf(mA, __shfl_xor_sync(0xffffffffu, mA, 1));
    mA = fmaxf(mA, __shfl_xor_sync(0xffffffffu, mA, 2));
    mB = fmaxf(mB, __shfl_xor_sync(0xffffffffu, mB, 1));
    mB = fmaxf(mB, __shfl_xor_sync(0xffffffffu, mB, 2));
    float lA = 0.f, lB = 0.f;
#pragma unroll
    for (int jt = 0; jt < 26; jt++) {
        accS[jt][0] = __expf(accS[jt][0] - mA);
        accS[jt][1] = __expf(accS[jt][1] - mA);
        accS[jt][2] = __expf(accS[jt][2] - mB);
        accS[jt][3] = __expf(accS[jt][3] - mB);
        lA += accS[jt][0] + accS[jt][1];
        lB += accS[jt][2] + accS[jt][3];
    }
    lA += __shfl_xor_sync(0xffffffffu, lA, 1);
    lA += __shfl_xor_sync(0xffffffffu, lA, 2);
    lB += __shfl_xor_sync(0xffffffffu, lB, 1);
    lB += __shfl_xor_sync(0xffffffffu, lB, 2);

    float accO[4][4];
#pragma unroll
    for (int nt = 0; nt < 4; nt++)
#pragma unroll
        for (int r = 0; r < 4; r++) accO[nt][r] = 0.f;
#pragma unroll
    for (int kt = 0; kt < 13; kt++) {
        uint32_t pa[4];
        pa[0] = packh2(accS[2 * kt][0],     accS[2 * kt][1]);
        pa[1] = packh2(accS[2 * kt][2],     accS[2 * kt][3]);
        pa[2] = packh2(accS[2 * kt + 1][0], accS[2 * kt + 1][1]);
        pa[3] = packh2(accS[2 * kt + 1][2], accS[2 * kt + 1][3]);
#pragma unroll
        for (int nt = 0; nt < 4; nt++) {
            uint32_t bf[2];
            bf[0] = *(uint32_t*)&Vp[(8 * kt + tq) * VP_STR + 8 * nt + gid];
            bf[1] = *(uint32_t*)&Vp[(8 * kt + 4 + tq) * VP_STR + 8 * nt + gid];
            mma_f16(accO[nt], pa, bf);
        }
    }
    float invA = 1.f / lA, invB = 1.f / lB;
    __half2* ob = outT2 + ((size_t)(b * (Cn / 2) + (hoff >> 1))) * Pn;
#pragma unroll
    for (int nt = 0; nt < 4; nt++) {
        int dvp = 4 * nt + tq;
        ob[(size_t)dvp * Pn + iA]     = __floats2half2_rn(accO[nt][0] * invA, accO[nt][1] * invA);
        ob[(size_t)dvp * Pn + iA + 8] = __floats2half2_rn(accO[nt][2] * invB, accO[nt][3] * invB);
    }
}

// ---------------- host launch ----------------
static void* sym_addr(const void* symbol) {
    void* p = nullptr;
    cudaGetSymbolAddress(&p, symbol);
    return p;
}

extern "C" void kernel_launch(void* const* d_in, const int* in_sizes, int n_in,
                              void* d_out, int out_size) {
    const float* x     = (const float*)d_in[0];
    const float* lpu_w = (const float*)d_in[1];
    const float* lpu_b = (const float*)d_in[2];
    const float* dw_w  = (const float*)d_in[3];
    const float* dw_b  = (const float*)d_in[4];
    const float* wq    = (const float*)d_in[5];
    const float* bq    = (const float*)d_in[6];
    const float* wk    = (const float*)d_in[7];
    const float* bk    = (const float*)d_in[8];
    const float* wv    = (const float*)d_in[9];
    const float* bv    = (const float*)d_in[10];
    const float* wo    = (const float*)d_in[11];
    const float* bo    = (const float*)d_in[12];
    const float* pos_b = (const float*)d_in[13];
    const float* c1_w  = (const float*)d_in[14];
    const float* c1_b  = (const float*)d_in[15];
    const float* bn1_g = (const float*)d_in[16];
    const float* bn1_b = (const float*)d_in[17];
    const float* bn1_m = (const float*)d_in[18];
    const float* bn1_v = (const float*)d_in[19];
    const float* dw2_w = (const float*)d_in[20];
    const float* dw2_b = (const float*)d_in[21];
    const float* bn2_g = (const float*)d_in[22];
    const float* bn2_b = (const float*)d_in[23];
    const float* bn2_m = (const float*)d_in[24];
    const float* bn2_v = (const float*)d_in[25];
    const float* c2_w  = (const float*)d_in[26];
    const float* c2_b  = (const float*)d_in[27];
    const float* bn3_g = (const float*)d_in[28];
    const float* bn3_b = (const float*)d_in[29];
    const float* bn3_m = (const float*)d_in[30];
    const float* bn3_v = (const float*)d_in[31];
    float* out = (float*)d_out;

    float*   x1    = (float*)sym_addr(g_x1);
    __half2* x1h   = (__half2*)sym_addr(g_x1h);
    __half2* kvh   = (__half2*)sym_addr(g_kvh);
    float*   x2    = (float*)sym_addr(g_x2);
    __half*  x2h   = (__half*)sym_addr(g_x2h);
    __half*  qh    = (__half*)sym_addr(g_qh);
    __half*  kh    = (__half*)sym_addr(g_kh);
    __half*  vh    = (__half*)sym_addr(g_vh);
    __half2* attTh = (__half2*)sym_addr(g_attTh);
    __half2* t1h   = (__half2*)sym_addr(g_t1h);
    __half2* t2h   = (__half2*)sym_addr(g_t2h);
    __half2* wqh   = (__half2*)sym_addr(g_wqh);
    __half2* wkh   = (__half2*)sym_addr(g_wkh);
    __half2* wvh   = (__half2*)sym_addr(g_wvh);
    __half2* woh   = (__half2*)sym_addr(g_woh);
    __half2* c1h   = (__half2*)sym_addr(g_c1h);
    __half2* c2h   = (__half2*)sym_addr(g_c2h);
    float*   sq    = (float*)sym_addr(g_sq);
    float*   sc1   = (float*)sym_addr(g_sc1);
    float2*  partl = (float2*)sym_addr(g_partl);
    float2*  parto = (float2*)sym_addr(g_parto);

    dim3 tb(32, 8);
    // 1. weight packs + rowsums (one launch)
    k_wpack_all<<<928, tb>>>(wq, wk, wv, wo, c1_w, c2_w,
                             wqh, wkh, wvh, woh, c1h, c2h, sq, sc1);
    // 2. fused pair-LPU (+KV fp16 +LN1 partials +x1h)
    k_lpu2<<<Bn * (Cn / 2), 224>>>(x, lpu_w, lpu_b, dw_w, dw_b, x1, x1h, kvh, partl);
    // 3. merged Q/K/V projections (LN1 finisher folded into Q epilogue)
    k_qkv<<<dim3(22, 1, Bn), 256, SMEM_MMA>>>(
        wqh, wkh, wvh, x1h, kvh, bq, bk, bv, partl, sq, qh, kh, vh);
    // 4. attention -> attTh
    k_attn_mma<<<dim3(7, NH, Bn), 224>>>(qh, kh, vh, pos_b, attTh);
    // 5. O projection + flat residual -> x2 fp32 + x2h mirror (+LN2 partials)
    k_mma<1, 1><<<dim3(7, 2, Bn), 256, SMEM_MMA>>>(
        woh, attTh, bo, nullptr, nullptr, nullptr, nullptr, nullptr,
        x1, parto, x2h, x2, Cn, Cn, Pn);
    // 6. c1 + BN1 + GELU (LN2 finisher folded in; LN via rowsum fold) -> t1h
    k_mma<2, 2><<<dim3(7, 8, Bn), 256, SMEM_MMA>>>(
        c1h, x2h, c1_b, bn1_g, bn1_b, bn1_m, bn1_v, sc1,
        nullptr, parto, nullptr, t1h, CMn, Cn, Pn);
    // 7. dw2 + BN2 + GELU -> t2h
    k_dw2pair<<<Bn * (CMn / 2), 224>>>(t1h, dw2_w, dw2_b, bn2_g, bn2_b, bn2_m, bn2_v, t2h);
    // 8. c2 + BN3 + channel-major residual -> d_out
    k_mma<3, 1><<<dim3(7, 2, Bn), 256, SMEM_MMA>>>(
        c2h, t2h, c2_b, bn3_g, bn3_b, bn3_m, bn3_v, nullptr,
        x2, nullptr, nullptr, out, Cn, CMn, Pn);
}

// round 16
// speedup vs baseline: 1.2349x; 1.1131x over previous
#include <cuda_runtime.h>
#include <cuda_fp16.h>
#include <math.h>
#include <stdint.h>

// ---------------- problem constants ----------------
#define Bn   32
#define Cn   256
#define Hn   28
#define Wn   28
#define Pn   784          // H*W
#define NKn  196          // (H/2)*(W/2)
#define HKn  14
#define CMn  1024         // C * R
#define NH   8
#define DKn  32
#define EPSf 1e-5f

// ---------------- scratch (device globals; padded for unguarded tile loads) ----------------
__device__ float   g_x1 [Bn*Cn*Pn + 256];        // LPU out fp32 (O-proj flat residual)
__device__ __half2 g_x1h[Bn*(Cn/2)*Pn + 512];    // LPU out fp16 channel-paired
__device__ __half2 g_kvh[Bn*(Cn/2)*NKn + 512];   // KV downsample fp16 channel-paired
__device__ float   g_x2 [Bn*Cn*Pn + 256];        // attn residual fp32 (c2 residual, LN2)
__device__ __half  g_x2h[Bn*Cn*Pn + 1024];       // flat fp16 mirror of x2 (c1 B)
__device__ __half  g_qh [Bn*Pn*Cn + 512];        // Q fp16 row-major [p][oc]
__device__ __half  g_kh [Bn*NKn*Cn + 512];       // K fp16 [nk][256]
__device__ __half  g_vh [Bn*NKn*Cn + 512];       // V fp16 [nk][256]
__device__ __half2 g_attTh[Bn*(Cn/2)*Pn + 512];  // attn out, channel-paired
__device__ __half2 g_t1h  [Bn*(CMn/2)*Pn + 512]; // c1 out, channel-paired
__device__ __half2 g_t2h  [Bn*(CMn/2)*Pn + 512]; // dw2 out, channel-paired
__device__ __half2 g_wqh[(Cn/2)*Cn];             // weights k-paired [k/2][m]
__device__ __half2 g_wkh[(Cn/2)*Cn];
__device__ __half2 g_wvh[(Cn/2)*Cn];
__device__ __half2 g_woh[(Cn/2)*Cn];
__device__ __half2 g_c1h[(Cn/2)*CMn];
__device__ __half2 g_c2h[(CMn/2)*Cn];
__device__ float   g_sq [Cn];                    // rowsum(wq)
__device__ float   g_sc1[CMn];                   // rowsum(c1_w)
__device__ float2  g_partl[Bn*(Cn/2)];           // LN1 partials (per pair-plane)
__device__ float2  g_parto[Bn*14];               // LN2 partials

__device__ __forceinline__ float gelu_f(float v) {
    return 0.5f * v * (1.0f + erff(v * 0.7071067811865475f));
}
__device__ __forceinline__ void mma_f16(float* c, const uint32_t* a, const uint32_t* b) {
    asm volatile(
        "mma.sync.aligned.m16n8k16.row.col.f32.f16.f16.f32 "
        "{%0,%1,%2,%3}, {%4,%5,%6,%7}, {%8,%9}, {%0,%1,%2,%3};"
        : "+f"(c[0]), "+f"(c[1]), "+f"(c[2]), "+f"(c[3])
        : "r"(a[0]), "r"(a[1]), "r"(a[2]), "r"(a[3]), "r"(b[0]), "r"(b[1]));
}
__device__ __forceinline__ uint32_t packh2(float lo, float hi) {
    __half2 h = __floats2half2_rn(lo, hi);
    return *(uint32_t*)&h;
}

#define H2STR 136
#define KSTR  132
#define STAGE (32*H2STR)
#define SMEM_MMA (2*STAGE*4)   // 34816 B

// ====================== k_mma (256 thr, 128x128 — proven config) ======================
// BK 1: B = half2 k-paired [k/2][P] raw
// BK 2: B = flat __half [k][P] (channel rows), interleave via byte_perm
// MODE 1: f32 out[p*M+m] = acc + bias + res; +flat fp16 mirror xmir; LN2 partials -> pstat
// MODE 2: half2 out[(m/2)*P+p] = gelu(BN(acc*rstd + cb - mean*rstd*S)); mean/rstd reduced
//         in-kernel from pstat (14 partials per batch)
// MODE 3: f32 out[m*P+p] = BN(acc + bias) + res
template <int MODE, int BK>
__global__ void __launch_bounds__(256, 2) k_mma(
    const __half2* __restrict__ Wh, const void* __restrict__ Xv,
    const float* __restrict__ bias,
    const float* __restrict__ bng, const float* __restrict__ bnb,
    const float* __restrict__ bnm, const float* __restrict__ bnv,
    const float* __restrict__ rsum,
    const float* __restrict__ res, float2* __restrict__ pstat,
    __half* __restrict__ xmir,
    void* __restrict__ outv, int M, int K, int P) {
    extern __shared__ float sm[];
    const int tid  = threadIdx.x;
    const int warp = tid >> 5, lane = tid & 31;
    const int gid = lane >> 2, tq = lane & 3;
    const int wm = (warp & 1) * 64;
    const int wn = (warp >> 1) * 32;
    const int b  = blockIdx.z;
    const int m0 = blockIdx.y * 128;
    const int n0 = blockIdx.x * 128;
    const __half2* Xh2 = (BK == 1) ? (const __half2*)Xv + (size_t)b * (K >> 1) * P : nullptr;
    const __half*  Xhf = (BK == 2) ? (const __half*)Xv + (size_t)b * K * P : nullptr;

    float acc[4][4][4];
#pragma unroll
    for (int i = 0; i < 4; i++)
#pragma unroll
        for (int j = 0; j < 4; j++)
#pragma unroll
            for (int r = 0; r < 4; r++) acc[i][j][r] = 0.f;

    const int kk = tid >> 4;
    const int mq = (tid & 15) * 8;
    uint4 pa0, pa1, pb0, pb1;
    const int T = K >> 5;

    auto load_chunk = [&](int kc0) {
        const uint4* wr = (const uint4*)(Wh + (size_t)((kc0 >> 1) + kk) * M + m0 + mq);
        pa0 = wr[0]; pa1 = wr[1];
        if (BK == 1) {
            const uint4* xr = (const uint4*)(Xh2 + (size_t)((kc0 >> 1) + kk) * P + n0 + mq);
            pb0 = xr[0]; pb1 = xr[1];
        } else {
            const uint4 r0 = *(const uint4*)(Xhf + (size_t)(kc0 + 2 * kk) * P + n0 + mq);
            const uint4 r1 = *(const uint4*)(Xhf + (size_t)(kc0 + 2 * kk + 1) * P + n0 + mq);
            pb0 = make_uint4(__byte_perm(r0.x, r1.x, 0x5410), __byte_perm(r0.x, r1.x, 0x7632),
                             __byte_perm(r0.y, r1.y, 0x5410), __byte_perm(r0.y, r1.y, 0x7632));
            pb1 = make_uint4(__byte_perm(r0.z, r1.z, 0x5410), __byte_perm(r0.z, r1.z, 0x7632),
                             __byte_perm(r0.w, r1.w, 0x5410), __byte_perm(r0.w, r1.w, 0x7632));
        }
    };
    auto store_chunk = [&](int s) {
        __half2* As2 = (__half2*)sm + s * STAGE;
        __half2* Bs2 = As2 + 16 * H2STR;
        *(uint4*)&As2[kk * H2STR + mq]     = pa0;
        *(uint4*)&As2[kk * H2STR + mq + 4] = pa1;
        *(uint4*)&Bs2[kk * H2STR + mq]     = pb0;
        *(uint4*)&Bs2[kk * H2STR + mq + 4] = pb1;
    };

    load_chunk(0);
    store_chunk(0);
    __syncthreads();

    for (int t = 0; t < T; t++) {
        if (t + 1 < T) load_chunk((t + 1) << 5);
        const __half2* As2 = (const __half2*)sm + (t & 1) * STAGE;
        const __half2* Bs2 = As2 + 16 * H2STR;
#pragma unroll
        for (int ks = 0; ks < 2; ks++) {
            const int r0 = ks * 8;
            uint32_t af[4][4], bf[4][2];
#pragma unroll
            for (int i = 0; i < 4; i++) {
                int m = wm + i * 16 + gid;
                af[i][0] = *(uint32_t*)&As2[(r0 + tq) * H2STR + m];
                af[i][1] = *(uint32_t*)&As2[(r0 + tq) * H2STR + m + 8];
                af[i][2] = *(uint32_t*)&As2[(r0 + tq + 4) * H2STR + m];
                af[i][3] = *(uint32_t*)&As2[(r0 + tq + 4) * H2STR + m + 8];
            }
#pragma unroll
            for (int j = 0; j < 4; j++) {
                int p = wn + j * 8 + gid;
                bf[j][0] = *(uint32_t*)&Bs2[(r0 + tq) * H2STR + p];
                bf[j][1] = *(uint32_t*)&Bs2[(r0 + tq + 4) * H2STR + p];
            }
#pragma unroll
            for (int i = 0; i < 4; i++)
#pragma unroll
                for (int j = 0; j < 4; j++) mma_f16(acc[i][j], af[i], bf[j]);
        }
        if (t + 1 < T) {
            store_chunk((t + 1) & 1);
            __syncthreads();
        }
    }

    // LN scalars for MODE 2: reduce the 14 per-batch partials in-kernel (fixed tree)
    float mean = 0.f, rstd = 1.f;
    if (MODE == 2) {
        __syncthreads();
        if (tid < 32) {
            float2 p = (tid < 14) ? pstat[b * 14 + tid] : make_float2(0.f, 0.f);
#pragma unroll
            for (int o = 16; o >= 1; o >>= 1) {
                p.x += __shfl_down_sync(0xffffffffu, p.x, o);
                p.y += __shfl_down_sync(0xffffffffu, p.y, o);
            }
            if (tid == 0) {
                const float n = (float)(Cn * Pn);
                float m  = p.x / n;
                float vv = p.y / n - m * m;
                sm[0] = m;
                sm[1] = rsqrtf(vv + EPSf);
            }
        }
        __syncthreads();
        mean = sm[0]; rstd = sm[1];
    }

    // ---- epilogue: two 64-row passes staged through smem ----
    float* sD = sm;
    float*   outf  = (MODE == 1 || MODE == 3) ? (float*)outv + (size_t)b * (size_t)M * P : nullptr;
    __half2* outh2 = (MODE == 2) ? (__half2*)outv + (size_t)b * (size_t)(M >> 1) * P : nullptr;
    __half*  xmb   = (MODE == 1) ? xmir + (size_t)b * (size_t)M * P : nullptr;
    const float* resb = (MODE == 1 || MODE == 3) ? res + (size_t)b * (size_t)M * P : nullptr;
    float osum = 0.f, osq = 0.f;

#pragma unroll
    for (int pass = 0; pass < 2; pass++) {
        __syncthreads();
        if (MODE == 1) {
            if ((wn >> 6) == pass) {
#pragma unroll
                for (int i = 0; i < 4; i++) {
                    int mrow = wm + i * 16 + gid;
#pragma unroll
                    for (int j = 0; j < 4; j++) {
                        int pc = (wn & 63) + j * 8 + 2 * tq;
                        sD[pc * KSTR + mrow]           = acc[i][j][0];
                        sD[(pc + 1) * KSTR + mrow]     = acc[i][j][1];
                        sD[pc * KSTR + mrow + 8]       = acc[i][j][2];
                        sD[(pc + 1) * KSTR + mrow + 8] = acc[i][j][3];
                    }
                }
            }
        } else {
            if ((wm >> 6) == pass) {
#pragma unroll
                for (int i = 0; i < 4; i++) {
                    int ml = (wm & 63) + i * 16 + gid;
#pragma unroll
                    for (int j = 0; j < 4; j++) {
                        int pc = wn + j * 8 + 2 * tq;
                        sD[ml * KSTR + pc]           = acc[i][j][0];
                        sD[ml * KSTR + pc + 1]       = acc[i][j][1];
                        sD[(ml + 8) * KSTR + pc]     = acc[i][j][2];
                        sD[(ml + 8) * KSTR + pc + 1] = acc[i][j][3];
                    }
                }
            }
        }
        __syncthreads();
        if (MODE == 1) {
            for (int l = tid; l < 64 * 32; l += 256) {
                int rl = l >> 5, cq = (l & 31) * 4;
                int p = n0 + pass * 64 + rl;
                if (p >= P) continue;
                float4 v = *(float4*)&sD[rl * KSTR + cq];
                float4 bb = *(const float4*)(bias + m0 + cq);
                v.x += bb.x; v.y += bb.y; v.z += bb.z; v.w += bb.w;
                size_t off = (size_t)p * M + m0 + cq;
                float4 rr = *(const float4*)(resb + off);
                v.x += rr.x; v.y += rr.y; v.z += rr.z; v.w += rr.w;
                *(float4*)(outf + off) = v;
                __half2 h01 = __floats2half2_rn(v.x, v.y);
                __half2 h23 = __floats2half2_rn(v.z, v.w);
                *(uint2*)(xmb + off) = make_uint2(*(uint32_t*)&h01, *(uint32_t*)&h23);
                osum += v.x + v.y + v.z + v.w;
                osq  += v.x * v.x + v.y * v.y + v.z * v.z + v.w * v.w;
            }
        } else if (MODE == 2) {
            for (int l = tid; l < 32 * 32; l += 256) {
                int rp = l >> 5, cq = (l & 31) * 4;
                int m = m0 + pass * 64 + 2 * rp;
                int p = n0 + cq;
                if (p >= P) continue;
                float sc0 = bng[m] * rsqrtf(bnv[m] + EPSf);
                float sh0 = bnb[m] - bnm[m] * sc0
                          + (bias[m] - mean * rstd * rsum[m]) * sc0;
                float a0 = rstd * sc0;
                float sc1 = bng[m + 1] * rsqrtf(bnv[m + 1] + EPSf);
                float sh1 = bnb[m + 1] - bnm[m + 1] * sc1
                          + (bias[m + 1] - mean * rstd * rsum[m + 1]) * sc1;
                float a1 = rstd * sc1;
                float4 v0 = *(float4*)&sD[(2 * rp) * KSTR + cq];
                float4 v1 = *(float4*)&sD[(2 * rp + 1) * KSTR + cq];
                v0.x = gelu_f(v0.x * a0 + sh0); v0.y = gelu_f(v0.y * a0 + sh0);
                v0.z = gelu_f(v0.z * a0 + sh0); v0.w = gelu_f(v0.w * a0 + sh0);
                v1.x = gelu_f(v1.x * a1 + sh1); v1.y = gelu_f(v1.y * a1 + sh1);
                v1.z = gelu_f(v1.z * a1 + sh1); v1.w = gelu_f(v1.w * a1 + sh1);
                uint4 u = make_uint4(packh2(v0.x, v1.x), packh2(v0.y, v1.y),
                                     packh2(v0.z, v1.z), packh2(v0.w, v1.w));
                *(uint4*)(outh2 + (size_t)(m >> 1) * P + p) = u;
            }
        } else {
            for (int l = tid; l < 64 * 32; l += 256) {
                int rl = l >> 5, cq = (l & 31) * 4;
                int m = m0 + pass * 64 + rl;
                int p = n0 + cq;
                if (p >= P) continue;
                float scale = bng[m] * rsqrtf(bnv[m] + EPSf);
                float shift = bnb[m] - bnm[m] * scale + bias[m] * scale;
                float4 v = *(float4*)&sD[rl * KSTR + cq];
                v.x = v.x * scale + shift; v.y = v.y * scale + shift;
                v.z = v.z * scale + shift; v.w = v.w * scale + shift;
                size_t off = (size_t)m * P + p;
                float4 rr = *(const float4*)(resb + off);
                v.x += rr.x; v.y += rr.y; v.z += rr.z; v.w += rr.w;
                *(float4*)(outf + off) = v;
            }
        }
    }

    if (MODE == 1) {
        __syncthreads();
        float* r1 = sm;
        float* r2 = sm + 256;
        r1[tid] = osum; r2[tid] = osq;
        __syncthreads();
        for (int st = 128; st > 0; st >>= 1) {
            if (tid < st) { r1[tid] += r1[tid + st]; r2[tid] += r2[tid + st]; }
            __syncthreads();
        }
        if (tid == 0)
            pstat[b * 14 + blockIdx.y * gridDim.x + blockIdx.x] = make_float2(r1[0], r2[0]);
    }
}

// ====================== merged QKV (256 thr; LN1 finisher folded into Q epilogue) ======================
__global__ void __launch_bounds__(256, 2) k_qkv(
    const __half2* __restrict__ wqh, const __half2* __restrict__ wkh,
    const __half2* __restrict__ wvh,
    const __half2* __restrict__ x1h, const __half2* __restrict__ kvh,
    const float* __restrict__ bq, const float* __restrict__ bk,
    const float* __restrict__ bv, const float2* __restrict__ partl,
    const float* __restrict__ sq,
    __half* __restrict__ qh, __half* __restrict__ kh, __half* __restrict__ vh) {
    extern __shared__ float sm[];
    const int tid  = threadIdx.x;
    const int warp = tid >> 5, lane = tid & 31;
    const int gid = lane >> 2, tq = lane & 3;
    const int wm = (warp & 1) * 64;
    const int wn = (warp >> 1) * 32;
    const int b  = blockIdx.z;
    const int id = blockIdx.x;  // 0..21

    const __half2* Wh;
    const __half2* Xh2;
    const float* bias;
    __half* outp;
    int P, m0, n0;
    bool isQ = false;
    if (id < 14) {
        Wh = wqh; Xh2 = x1h + (size_t)b * (Cn / 2) * Pn; bias = bq;
        outp = qh + (size_t)b * Pn * Cn;
        P = Pn; isQ = true; m0 = (id / 7) * 128; n0 = (id % 7) * 128;
    } else if (id < 18) {
        int t = id - 14;
        Wh = wkh; Xh2 = kvh + (size_t)b * (Cn / 2) * NKn; bias = bk;
        outp = kh + (size_t)b * NKn * Cn;
        P = NKn; m0 = (t >> 1) * 128; n0 = (t & 1) * 128;
    } else {
        int t = id - 18;
        Wh = wvh; Xh2 = kvh + (size_t)b * (Cn / 2) * NKn; bias = bv;
        outp = vh + (size_t)b * NKn * Cn;
        P = NKn; m0 = (t >> 1) * 128; n0 = (t & 1) * 128;
    }

    float acc[4][4][4];
#pragma unroll
    for (int i = 0; i < 4; i++)
#pragma unroll
        for (int j = 0; j < 4; j++)
#pragma unroll
            for (int r = 0; r < 4; r++) acc[i][j][r] = 0.f;

    const int kk = tid >> 4;
    const int mq = (tid & 15) * 8;
    uint4 pa0, pa1, pb0, pb1;
    const int T = Cn >> 5;  // 8

    auto load_chunk = [&](int kp0) {
        const uint4* wr = (const uint4*)(Wh + (size_t)(kp0 + kk) * Cn + m0 + mq);
        pa0 = wr[0]; pa1 = wr[1];
        const uint4* xr = (const uint4*)(Xh2 + (size_t)(kp0 + kk) * P + n0 + mq);
        pb0 = xr[0]; pb1 = xr[1];
    };
    auto store_chunk = [&](int s) {
        __half2* As2 = (__half2*)sm + s * STAGE;
        __half2* Bs2 = As2 + 16 * H2STR;
        *(uint4*)&As2[kk * H2STR + mq]     = pa0;
        *(uint4*)&As2[kk * H2STR + mq + 4] = pa1;
        *(uint4*)&Bs2[kk * H2STR + mq]     = pb0;
        *(uint4*)&Bs2[kk * H2STR + mq + 4] = pb1;
    };

    load_chunk(0);
    store_chunk(0);
    __syncthreads();

    for (int t = 0; t < T; t++) {
        if (t + 1 < T) load_chunk((t + 1) << 4);
        const __half2* As2 = (const __half2*)sm + (t & 1) * STAGE;
        const __half2* Bs2 = As2 + 16 * H2STR;
#pragma unroll
        for (int ks = 0; ks < 2; ks++) {
            const int r0 = ks * 8;
            uint32_t af[4][4], bf[4][2];
#pragma unroll
            for (int i = 0; i < 4; i++) {
                int m = wm + i * 16 + gid;
                af[i][0] = *(uint32_t*)&As2[(r0 + tq) * H2STR + m];
                af[i][1] = *(uint32_t*)&As2[(r0 + tq) * H2STR + m + 8];
                af[i][2] = *(uint32_t*)&As2[(r0 + tq + 4) * H2STR + m];
                af[i][3] = *(uint32_t*)&As2[(r0 + tq + 4) * H2STR + m + 8];
            }
#pragma unroll
            for (int j = 0; j < 4; j++) {
                int p = wn + j * 8 + gid;
                bf[j][0] = *(uint32_t*)&Bs2[(r0 + tq) * H2STR + p];
                bf[j][1] = *(uint32_t*)&Bs2[(r0 + tq + 4) * H2STR + p];
            }
#pragma unroll
            for (int i = 0; i < 4; i++)
#pragma unroll
                for (int j = 0; j < 4; j++) mma_f16(acc[i][j], af[i], bf[j]);
        }
        if (t + 1 < T) {
            store_chunk((t + 1) & 1);
            __syncthreads();
        }
    }

    // LN1 finisher folded in: reduce 128 partials (fixed tree, deterministic)
    float scl = 1.f, moff = 0.f;
    if (isQ) {
        __syncthreads();
        if (tid < 128) {
            float2 p = partl[b * 128 + tid];
            sm[tid] = p.x;
            sm[128 + tid] = p.y;
        }
        __syncthreads();
        for (int st = 64; st > 0; st >>= 1) {
            if (tid < st) { sm[tid] += sm[tid + st]; sm[128 + tid] += sm[128 + tid + st]; }
            __syncthreads();
        }
        if (tid == 0) {
            const float n = (float)(Cn * Pn);
            float m  = sm[0] / n;
            float vv = sm[128] / n - m * m;
            sm[0] = m;
            sm[1] = rsqrtf(vv + EPSf);
        }
        __syncthreads();
        float mn = sm[0], rs = sm[1];
        scl = rs; moff = -mn * rs;
    }

    float* sD = sm;
#pragma unroll
    for (int pass = 0; pass < 2; pass++) {
        __syncthreads();
        if ((wn >> 6) == pass) {
#pragma unroll
            for (int i = 0; i < 4; i++) {
                int mrow = wm + i * 16 + gid;
#pragma unroll
                for (int j = 0; j < 4; j++) {
                    int pc = (wn & 63) + j * 8 + 2 * tq;
                    sD[pc * KSTR + mrow]           = acc[i][j][0];
                    sD[(pc + 1) * KSTR + mrow]     = acc[i][j][1];
                    sD[pc * KSTR + mrow + 8]       = acc[i][j][2];
                    sD[(pc + 1) * KSTR + mrow + 8] = acc[i][j][3];
                }
            }
        }
        __syncthreads();
        for (int l = tid; l < 64 * 32; l += 256) {
            int rl = l >> 5, cq = (l & 31) * 4;
            int p = n0 + pass * 64 + rl;
            if (p >= P) continue;
            float4 v = *(float4*)&sD[rl * KSTR + cq];
            float4 bb = *(const float4*)(bias + m0 + cq);
            if (isQ) {
                float4 ss = *(const float4*)(sq + m0 + cq);
                v.x = v.x * scl + bb.x + moff * ss.x;
                v.y = v.y * scl + bb.y + moff * ss.y;
                v.z = v.z * scl + bb.z + moff * ss.z;
                v.w = v.w * scl + bb.w + moff * ss.w;
            } else {
                v.x += bb.x; v.y += bb.y; v.z += bb.z; v.w += bb.w;
            }
            __half2 h01 = __floats2half2_rn(v.x, v.y);
            __half2 h23 = __floats2half2_rn(v.z, v.w);
            uint2 u = make_uint2(*(uint32_t*)&h01, *(uint32_t*)&h23);
            *(uint2*)(outp + (size_t)p * Cn + m0 + cq) = u;
        }
    }
}

// ---------------- merged weight pack + rowsums (one launch) ----------------
__global__ void k_wpack_all(
    const float* __restrict__ wq, const float* __restrict__ wk,
    const float* __restrict__ wv, const float* __restrict__ wo,
    const float* __restrict__ c1w, const float* __restrict__ c2w,
    __half2* __restrict__ oq, __half2* __restrict__ ok,
    __half2* __restrict__ ov, __half2* __restrict__ oo,
    __half2* __restrict__ oc1, __half2* __restrict__ oc2,
    float* __restrict__ sq, float* __restrict__ sc1) {
    __shared__ float t[32][33];
    int id = blockIdx.x;
    int tx = threadIdx.x, ty = threadIdx.y;
    if (id >= 768) {
        int tt = ty * 32 + tx;
        int w = ((id - 768) * 256 + tt) >> 5;    // 0..1279
        int lane = tt & 31;
        const float* row;
        float* outr;
        if (w < Cn) { row = wq + (size_t)w * Cn; outr = sq + w; }
        else        { row = c1w + (size_t)(w - Cn) * Cn; outr = sc1 + (w - Cn); }
        float s = 0.f;
        for (int i = lane; i < Cn; i += 32) s += row[i];
#pragma unroll
        for (int o = 16; o >= 1; o >>= 1) s += __shfl_down_sync(0xffffffffu, s, o);
        if (lane == 0) *outr = s;
        return;
    }
    const float* in;
    __half2* out;
    int M, K, tile;
    if (id < 256) {
        int w = id >> 6; tile = id & 63;
        in  = (w == 0) ? wq : (w == 1) ? wk : (w == 2) ? wv : wo;
        out = (w == 0) ? oq : (w == 1) ? ok : (w == 2) ? ov : oo;
        M = Cn; K = Cn;
    } else if (id < 512) {
        tile = id - 256;
        in = c1w; out = oc1; M = CMn; K = Cn;
    } else {
        tile = id - 512;
        in = c2w; out = oc2; M = Cn; K = CMn;
    }
    int ktiles = K >> 5;
    int m0 = (tile / ktiles) * 32, k0 = (tile % ktiles) * 32;
#pragma unroll
    for (int q = 0; q < 32; q += 8)
        t[ty + q][tx] = in[(size_t)(m0 + ty + q) * K + k0 + tx];
    __syncthreads();
#pragma unroll
    for (int q = 0; q < 2; q++) {
        int kp = ty + q * 8;
        __half2 val = __floats2half2_rn(t[tx][2 * kp], t[tx][2 * kp + 1]);
        out[(size_t)((k0 >> 1) + kp) * M + m0 + tx] = val;
    }
}

// ------- fused pair-LPU: conv+res -> x1 fp32 + x1h pairs; KV -> kvh pairs; LN1 partials -------
__global__ void __launch_bounds__(224) k_lpu2(
    const float* __restrict__ X, const float* __restrict__ w,
    const float* __restrict__ bias,
    const float* __restrict__ wkv, const float* __restrict__ bkv,
    float* __restrict__ x1, __half2* __restrict__ x1h,
    __half2* __restrict__ kvh, float2* __restrict__ partl) {
    __shared__ float sp0[900], sp1[900];
    __shared__ float so0[784], so1[784];
    __shared__ float r1[224], r2[224];
    int bc = blockIdx.x;
    int b  = bc >> 7;          // Cn/2 = 128
    int mp = bc & 127;
    int c0 = 2 * mp;
    const float* xin = X + ((size_t)b * Cn + c0) * Pn;
    int tid = threadIdx.x;
    for (int i = tid; i < 900; i += 224) { sp0[i] = 0.f; sp1[i] = 0.f; }
    float wa[9], wb[9];
#pragma unroll
    for (int i = 0; i < 9; i++) { wa[i] = w[c0 * 9 + i]; wb[i] = w[(c0 + 1) * 9 + i]; }
    float bs0 = bias[c0], bs1 = bias[c0 + 1];
    __syncthreads();
    for (int i = tid; i < Pn; i += 224) {
        int o = (i / 28 + 1) * 30 + (i % 28) + 1;
        sp0[o] = xin[i];
        sp1[o] = xin[Pn + i];
    }
    __syncthreads();
    float lsum = 0.f, lsq = 0.f;
    if (tid < 196) {
        int px = tid % 28, sy = (tid / 28) * 4;
        float a0[6][3], a1[6][3];
#pragma unroll
        for (int dr = 0; dr < 6; dr++) {
            int base = (sy + dr) * 30 + px;
            a0[dr][0] = sp0[base]; a0[dr][1] = sp0[base + 1]; a0[dr][2] = sp0[base + 2];
            a1[dr][0] = sp1[base]; a1[dr][1] = sp1[base + 1]; a1[dr][2] = sp1[base + 2];
        }
        float* ob = x1 + ((size_t)b * Cn + c0) * Pn;
        __half2* oh = x1h + ((size_t)b * (Cn / 2) + mp) * Pn;
#pragma unroll
        for (int i = 0; i < 4; i++) {
            float acc0 = bs0
                + wa[0] * a0[i][0]     + wa[1] * a0[i][1]     + wa[2] * a0[i][2]
                + wa[3] * a0[i + 1][0] + wa[4] * a0[i + 1][1] + wa[5] * a0[i + 1][2]
                + wa[6] * a0[i + 2][0] + wa[7] * a0[i + 2][1] + wa[8] * a0[i + 2][2];
            float acc1 = bs1
                + wb[0] * a1[i][0]     + wb[1] * a1[i][1]     + wb[2] * a1[i][2]
                + wb[3] * a1[i + 1][0] + wb[4] * a1[i + 1][1] + wb[5] * a1[i + 1][2]
                + wb[6] * a1[i + 2][0] + wb[7] * a1[i + 2][1] + wb[8] * a1[i + 2][2];
            float y0 = acc0 + a0[i + 1][1];
            float y1 = acc1 + a1[i + 1][1];
            int p = (sy + i) * 28 + px;
            so0[p] = y0; so1[p] = y1;
            ob[p] = y0; ob[Pn + p] = y1;
            oh[p] = __floats2half2_rn(y0, y1);
            lsum += y0 + y1; lsq += y0 * y0 + y1 * y1;
        }
    }
    r1[tid] = lsum; r2[tid] = lsq;
    __syncthreads();
    for (int st = 112; st >= 7; st >>= 1) {
        if (tid < st) { r1[tid] += r1[tid + st]; r2[tid] += r2[tid + st]; }
        __syncthreads();
    }
    if (tid == 0) {
        float s = 0.f, qv = 0.f;
#pragma unroll
        for (int i = 0; i < 7; i++) { s += r1[i]; qv += r2[i]; }
        partl[bc] = make_float2(s, qv);
    }
    if (tid < 196) {
        int oy = tid / HKn, ox = tid % HKn;
        int i00 = (2 * oy) * 28 + 2 * ox;
        float k0 = bkv[c0]
            + wkv[c0 * 4 + 0] * so0[i00]      + wkv[c0 * 4 + 1] * so0[i00 + 1]
            + wkv[c0 * 4 + 2] * so0[i00 + 28] + wkv[c0 * 4 + 3] * so0[i00 + 29];
        float k1 = bkv[c0 + 1]
            + wkv[(c0 + 1) * 4 + 0] * so1[i00]      + wkv[(c0 + 1) * 4 + 1] * so1[i00 + 1]
            + wkv[(c0 + 1) * 4 + 2] * so1[i00 + 28] + wkv[(c0 + 1) * 4 + 3] * so1[i00 + 29];
        kvh[((size_t)b * (Cn / 2) + mp) * NKn + tid] = __floats2half2_rn(k0, k1);
    }
}

// ---------------- dw2: channel-pair fp16 in/out ----------------
__global__ void __launch_bounds__(224) k_dw2pair(
    const __half2* __restrict__ X2, const float* __restrict__ w,
    const float* __restrict__ bias,
    const float* __restrict__ bng, const float* __restrict__ bnb,
    const float* __restrict__ bnm, const float* __restrict__ bnv,
    __half2* __restrict__ out2) {
    __shared__ float sp0[900], sp1[900];
    int bc = blockIdx.x;
    int b  = bc >> 9;
    int mp = bc & 511;
    int c0 = 2 * mp;
    const __half2* x0 = X2 + ((size_t)b * (CMn / 2) + mp) * Pn;
    int tid = threadIdx.x;
    for (int i = tid; i < 900; i += 224) { sp0[i] = 0.f; sp1[i] = 0.f; }
    float wa[9], wb[9];
#pragma unroll
    for (int i = 0; i < 9; i++) { wa[i] = w[c0 * 9 + i]; wb[i] = w[(c0 + 1) * 9 + i]; }
    float bs0 = bias[c0], bs1 = bias[c0 + 1];
    float sc0 = bng[c0] * rsqrtf(bnv[c0] + EPSf);
    float sh0 = bnb[c0] - bnm[c0] * sc0;
    float sc1 = bng[c0 + 1] * rsqrtf(bnv[c0 + 1] + EPSf);
    float sh1 = bnb[c0 + 1] - bnm[c0 + 1] * sc1;
    __syncthreads();
    for (int i = tid; i < Pn; i += 224) {
        int o = (i / 28 + 1) * 30 + (i % 28) + 1;
        float2 f = __half22float2(x0[i]);
        sp0[o] = f.x;
        sp1[o] = f.y;
    }
    __syncthreads();
    if (tid < 196) {
        int px = tid % 28, sy = (tid / 28) * 4;
        float a0[6][3], a1[6][3];
#pragma unroll
        for (int dr = 0; dr < 6; dr++) {
            int base = (sy + dr) * 30 + px;
            a0[dr][0] = sp0[base]; a0[dr][1] = sp0[base + 1]; a0[dr][2] = sp0[base + 2];
            a1[dr][0] = sp1[base]; a1[dr][1] = sp1[base + 1]; a1[dr][2] = sp1[base + 2];
        }
        __half2* ob = out2 + ((size_t)b * (CMn / 2) + mp) * Pn;
#pragma unroll
        for (int i = 0; i < 4; i++) {
            float acc0 = bs0
                + wa[0] * a0[i][0]     + wa[1] * a0[i][1]     + wa[2] * a0[i][2]
                + wa[3] * a0[i + 1][0] + wa[4] * a0[i + 1][1] + wa[5] * a0[i + 1][2]
                + wa[6] * a0[i + 2][0] + wa[7] * a0[i + 2][1] + wa[8] * a0[i + 2][2];
            float acc1 = bs1
                + wb[0] * a1[i][0]     + wb[1] * a1[i][1]     + wb[2] * a1[i][2]
                + wb[3] * a1[i + 1][0] + wb[4] * a1[i + 1][1] + wb[5] * a1[i + 1][2]
                + wb[6] * a1[i + 2][0] + wb[7] * a1[i + 2][1] + wb[8] * a1[i + 2][2];
            float y0 = gelu_f(acc0 * sc0 + sh0);
            float y1 = gelu_f(acc1 * sc1 + sh1);
            ob[(sy + i) * 28 + px] = __floats2half2_rn(y0, y1);
        }
    }
}

// ================= fp16 mma attention, 2-chunk online softmax =================
#define KP_STR 20
#define VP_STR 40

// Process NT key-tiles starting at tile TB with online softmax rescaling.
template <int NT, int TB>
__device__ __forceinline__ void attn_chunk(
    const __half2* Kp, const __half2* Vp,
    const uint32_t (&aq)[2][4],
    const float* posA, const float* posB,
    float& mA, float& mB, float& lA, float& lB,
    float (&accO)[4][4], int gid, int tq) {
    const float scale = 0.17677669529663687f;
    float accS[NT][4];
#pragma unroll
    for (int jt = 0; jt < NT; jt++)
#pragma unroll
        for (int r = 0; r < 4; r++) accS[jt][r] = 0.f;
#pragma unroll
    for (int jt = 0; jt < NT; jt++) {
        const int row = 8 * (TB + jt) + gid;
#pragma unroll
        for (int kt = 0; kt < 2; kt++) {
            uint32_t bf[2];
            bf[0] = *(uint32_t*)&Kp[row * KP_STR + 8 * kt + tq];
            bf[1] = *(uint32_t*)&Kp[row * KP_STR + 8 * kt + 4 + tq];
            mma_f16(accS[jt], aq[kt], bf);
        }
    }
    float cA = -1e30f, cB = -1e30f;
#pragma unroll
    for (int jt = 0; jt < NT; jt++) {
        int col = 8 * (TB + jt) + 2 * tq;
        if (col < NKn) {
            float2 pA = *(const float2*)(posA + col);
            float2 pB = *(const float2*)(posB + col);
            accS[jt][0] = accS[jt][0] * scale + pA.x;
            accS[jt][1] = accS[jt][1] * scale + pA.y;
            accS[jt][2] = accS[jt][2] * scale + pB.x;
            accS[jt][3] = accS[jt][3] * scale + pB.y;
            cA = fmaxf(cA, fmaxf(accS[jt][0], accS[jt][1]));
            cB = fmaxf(cB, fmaxf(accS[jt][2], accS[jt][3]));
        } else {
            accS[jt][0] = -1e30f; accS[jt][1] = -1e30f;
            accS[jt][2] = -1e30f; accS[jt][3] = -1e30f;
        }
    }
    cA = fmaxf(cA, __shfl_xor_sync(0xffffffffu, cA, 1));
    cA = fmaxf(cA, __shfl_xor_sync(0xffffffffu, cA, 2));
    cB = fmaxf(cB, __shfl_xor_sync(0xffffffffu, cB, 1));
    cB = fmaxf(cB, __shfl_xor_sync(0xffffffffu, cB, 2));
    float nA = fmaxf(mA, cA), nB = fmaxf(mB, cB);
    float corrA = __expf(mA - nA), corrB = __expf(mB - nB);
    mA = nA; mB = nB;
    float eA = 0.f, eB = 0.f;
#pragma unroll
    for (int jt = 0; jt < NT; jt++) {
        accS[jt][0] = __expf(accS[jt][0] - mA);
        accS[jt][1] = __expf(accS[jt][1] - mA);
        accS[jt][2] = __expf(accS[jt][2] - mB);
        accS[jt][3] = __expf(accS[jt][3] - mB);
        eA += accS[jt][0] + accS[jt][1];
        eB += accS[jt][2] + accS[jt][3];
    }
    lA = lA * corrA + eA;
    lB = lB * corrB + eB;
#pragma unroll
    for (int nt = 0; nt < 4; nt++) {
        accO[nt][0] *= corrA; accO[nt][1] *= corrA;
        accO[nt][2] *= corrB; accO[nt][3] *= corrB;
    }
#pragma unroll
    for (int kt = 0; kt < NT / 2; kt++) {
        const int gs = (TB >> 1) + kt;
        uint32_t pa[4];
        pa[0] = packh2(accS[2 * kt][0],     accS[2 * kt][1]);
        pa[1] = packh2(accS[2 * kt][2],     accS[2 * kt][3]);
        pa[2] = packh2(accS[2 * kt + 1][0], accS[2 * kt + 1][1]);
        pa[3] = packh2(accS[2 * kt + 1][2], accS[2 * kt + 1][3]);
#pragma unroll
        for (int nt = 0; nt < 4; nt++) {
            uint32_t bf[2];
            bf[0] = *(uint32_t*)&Vp[(8 * gs + tq) * VP_STR + 8 * nt + gid];
            bf[1] = *(uint32_t*)&Vp[(8 * gs + 4 + tq) * VP_STR + 8 * nt + gid];
            mma_f16(accO[nt], pa, bf);
        }
    }
}

__global__ void __launch_bounds__(224, 2) k_attn_mma(
    const __half* __restrict__ q, const __half* __restrict__ k,
    const __half* __restrict__ v, const float* __restrict__ pos,
    __half2* __restrict__ outT2) {
    __shared__ __half2 Kp[208 * KP_STR];
    __shared__ __half2 Vp[104 * VP_STR];
    const int tid = threadIdx.x;
    const int warp = tid >> 5, lane = tid & 31;
    const int gid = lane >> 2, tq = lane & 3;
    const int qt = blockIdx.x;
    const int h  = blockIdx.y;
    const int b  = blockIdx.z;
    const int hoff = h * DKn;

    for (int idx = tid; idx < 208 * 16; idx += 224) {
        int key = idx >> 4, e = idx & 15;
        __half2 val = __floats2half2_rn(0.f, 0.f);
        if (key < NKn)
            val = *(const __half2*)(k + ((size_t)(b * NKn + key)) * Cn + hoff + 2 * e);
        Kp[key * KP_STR + e] = val;
    }
    for (int idx = tid; idx < 104 * 32; idx += 224) {
        int kp = idx >> 5, dv = idx & 31;
        int k0 = 2 * kp, k1 = 2 * kp + 1;
        __half f0 = (k0 < NKn) ? v[((size_t)(b * NKn + k0)) * Cn + hoff + dv] : __float2half(0.f);
        __half f1 = (k1 < NKn) ? v[((size_t)(b * NKn + k1)) * Cn + hoff + dv] : __float2half(0.f);
        Vp[kp * VP_STR + dv] = __halves2half2(f0, f1);
    }
    __syncthreads();

    const int iA = qt * 112 + warp * 16 + gid;

    uint32_t aq[2][4];
    {
        const __half* q0 = q + ((size_t)(b * Pn + iA)) * Cn + hoff;
        const __half* q1 = q0 + 8 * Cn;
#pragma unroll
        for (int kt = 0; kt < 2; kt++) {
            aq[kt][0] = *(const uint32_t*)(q0 + 16 * kt + 2 * tq);
            aq[kt][1] = *(const uint32_t*)(q1 + 16 * kt + 2 * tq);
            aq[kt][2] = *(const uint32_t*)(q0 + 16 * kt + 8 + 2 * tq);
            aq[kt][3] = *(const uint32_t*)(q1 + 16 * kt + 8 + 2 * tq);
        }
    }

    const float* posA = pos + ((size_t)(h * Pn + iA)) * NKn;
    const float* posB = posA + 8 * NKn;
    float mA = -1e30f, mB = -1e30f, lA = 0.f, lB = 0.f;
    float accO[4][4];
#pragma unroll
    for (int nt = 0; nt < 4; nt++)
#pragma unroll
        for (int r = 0; r < 4; r++) accO[nt][r] = 0.f;

    attn_chunk<14, 0>(Kp, Vp, aq, posA, posB, mA, mB, lA, lB, accO, gid, tq);
    attn_chunk<12, 14>(Kp, Vp, aq, posA, posB, mA, mB, lA, lB, accO, gid, tq);

    lA += __shfl_xor_sync(0xffffffffu, lA, 1);
    lA += __shfl_xor_sync(0xffffffffu, lA, 2);
    lB += __shfl_xor_sync(0xffffffffu, lB, 1);
    lB += __shfl_xor_sync(0xffffffffu, lB, 2);

    float invA = 1.f / lA, invB = 1.f / lB;
    __half2* ob = outT2 + ((size_t)(b * (Cn / 2) + (hoff >> 1))) * Pn;
#pragma unroll
    for (int nt = 0; nt < 4; nt++) {
        int dvp = 4 * nt + tq;
        ob[(size_t)dvp * Pn + iA]     = __floats2half2_rn(accO[nt][0] * invA, accO[nt][1] * invA);
        ob[(size_t)dvp * Pn + iA + 8] = __floats2half2_rn(accO[nt][2] * invB, accO[nt][3] * invB);
    }
}

// ---------------- host launch ----------------
static void* sym_addr(const void* symbol) {
    void* p = nullptr;
    cudaGetSymbolAddress(&p, symbol);
    return p;
}

extern "C" void kernel_launch(void* const* d_in, const int* in_sizes, int n_in,
                              void* d_out, int out_size) {
    const float* x     = (const float*)d_in[0];
    const float* lpu_w = (const float*)d_in[1];
    const float* lpu_b = (const float*)d_in[2];
    const float* dw_w  = (const float*)d_in[3];
    const float* dw_b  = (const float*)d_in[4];
    const float* wq    = (const float*)d_in[5];
    const float* bq    = (const float*)d_in[6];
    const float* wk    = (const float*)d_in[7];
    const float* bk    = (const float*)d_in[8];
    const float* wv    = (const float*)d_in[9];
    const float* bv    = (const float*)d_in[10];
    const float* wo    = (const float*)d_in[11];
    const float* bo    = (const float*)d_in[12];
    const float* pos_b = (const float*)d_in[13];
    const float* c1_w  = (const float*)d_in[14];
    const float* c1_b  = (const float*)d_in[15];
    const float* bn1_g = (const float*)d_in[16];
    const float* bn1_b = (const float*)d_in[17];
    const float* bn1_m = (const float*)d_in[18];
    const float* bn1_v = (const float*)d_in[19];
    const float* dw2_w = (const float*)d_in[20];
    const float* dw2_b = (const float*)d_in[21];
    const float* bn2_g = (const float*)d_in[22];
    const float* bn2_b = (const float*)d_in[23];
    const float* bn2_m = (const float*)d_in[24];
    const float* bn2_v = (const float*)d_in[25];
    const float* c2_w  = (const float*)d_in[26];
    const float* c2_b  = (const float*)d_in[27];
    const float* bn3_g = (const float*)d_in[28];
    const float* bn3_b = (const float*)d_in[29];
    const float* bn3_m = (const float*)d_in[30];
    const float* bn3_v = (const float*)d_in[31];
    float* out = (float*)d_out;

    float*   x1    = (float*)sym_addr(g_x1);
    __half2* x1h   = (__half2*)sym_addr(g_x1h);
    __half2* kvh   = (__half2*)sym_addr(g_kvh);
    float*   x2    = (float*)sym_addr(g_x2);
    __half*  x2h   = (__half*)sym_addr(g_x2h);
    __half*  qh    = (__half*)sym_addr(g_qh);
    __half*  kh    = (__half*)sym_addr(g_kh);
    __half*  vh    = (__half*)sym_addr(g_vh);
    __half2* attTh = (__half2*)sym_addr(g_attTh);
    __half2* t1h   = (__half2*)sym_addr(g_t1h);
    __half2* t2h   = (__half2*)sym_addr(g_t2h);
    __half2* wqh   = (__half2*)sym_addr(g_wqh);
    __half2* wkh   = (__half2*)sym_addr(g_wkh);
    __half2* wvh   = (__half2*)sym_addr(g_wvh);
    __half2* woh   = (__half2*)sym_addr(g_woh);
    __half2* c1h   = (__half2*)sym_addr(g_c1h);
    __half2* c2h   = (__half2*)sym_addr(g_c2h);
    float*   sq    = (float*)sym_addr(g_sq);
    float*   sc1   = (float*)sym_addr(g_sc1);
    float2*  partl = (float2*)sym_addr(g_partl);
    float2*  parto = (float2*)sym_addr(g_parto);

    dim3 tb(32, 8);
    // 1. weight packs + rowsums (one launch)
    k_wpack_all<<<928, tb>>>(wq, wk, wv, wo, c1_w, c2_w,
                             wqh, wkh, wvh, woh, c1h, c2h, sq, sc1);
    // 2. fused pair-LPU (+KV fp16 +LN1 partials +x1h)
    k_lpu2<<<Bn * (Cn / 2), 224>>>(x, lpu_w, lpu_b, dw_w, dw_b, x1, x1h, kvh, partl);
    // 3. merged Q/K/V projections (LN1 finisher folded into Q epilogue)
    k_qkv<<<dim3(22, 1, Bn), 256, SMEM_MMA>>>(
        wqh, wkh, wvh, x1h, kvh, bq, bk, bv, partl, sq, qh, kh, vh);
    // 4. attention (2-chunk online softmax, 2 blocks/SM) -> attTh
    k_attn_mma<<<dim3(7, NH, Bn), 224>>>(qh, kh, vh, pos_b, attTh);
    // 5. O projection + flat residual -> x2 fp32 + x2h mirror (+LN2 partials)
    k_mma<1, 1><<<dim3(7, 2, Bn), 256, SMEM_MMA>>>(
        woh, attTh, bo, nullptr, nullptr, nullptr, nullptr, nullptr,
        x1, parto, x2h, x2, Cn, Cn, Pn);
    // 6. c1 + BN1 + GELU (LN2 finisher folded in; LN via rowsum fold) -> t1h
    k_mma<2, 2><<<dim3(7, 8, Bn), 256, SMEM_MMA>>>(
        c1h, x2h, c1_b, bn1_g, bn1_b, bn1_m, bn1_v, sc1,
        nullptr, parto, nullptr, t1h, CMn, Cn, Pn);
    // 7. dw2 + BN2 + GELU -> t2h
    k_dw2pair<<<Bn * (CMn / 2), 224>>>(t1h, dw2_w, dw2_b, bn2_g, bn2_b, bn2_m, bn2_v, t2h);
    // 8. c2 + BN3 + channel-major residual -> d_out
    k_mma<3, 1><<<dim3(7, 2, Bn), 256, SMEM_MMA>>>(
        c2h, t2h, c2_b, bn3_g, bn3_b, bn3_m, bn3_v, nullptr,
        x2, nullptr, nullptr, out, Cn, CMn, Pn);
}

// round 17
// speedup vs baseline: 1.2781x; 1.0351x over previous
#include <cuda_runtime.h>
#include <cuda_fp16.h>
#include <math.h>
#include <stdint.h>

// ---------------- problem constants ----------------
#define Bn   32
#define Cn   256
#define Hn   28
#define Wn   28
#define Pn   784          // H*W
#define NKn  196          // (H/2)*(W/2)
#define HKn  14
#define CMn  1024         // C * R
#define NH   8
#define DKn  32
#define EPSf 1e-5f

// ---------------- scratch (device globals; padded for unguarded tile loads) ----------------
__device__ float   g_x1 [Bn*Cn*Pn + 256];        // LPU out fp32 (O-proj flat residual)
__device__ __half2 g_x1h[Bn*(Cn/2)*Pn + 512];    // LPU out fp16 channel-paired
__device__ __half2 g_kvh[Bn*(Cn/2)*NKn + 512];   // KV downsample fp16 channel-paired
__device__ float   g_x2 [Bn*Cn*Pn + 256];        // attn residual fp32 (c2 residual, LN2)
__device__ __half  g_x2h[Bn*Cn*Pn + 1024];       // flat fp16 mirror of x2 (c1 B)
__device__ __half  g_qh [Bn*Pn*Cn + 512];        // Q fp16 row-major [p][oc]
__device__ __half  g_kh [Bn*NKn*Cn + 512];       // K fp16 [nk][256]
__device__ __half  g_vh [Bn*NKn*Cn + 512];       // V fp16 [nk][256]
__device__ __half2 g_attTh[Bn*(Cn/2)*Pn + 512];  // attn out, channel-paired
__device__ __half2 g_t1h  [Bn*(CMn/2)*Pn + 512]; // c1 out, channel-paired
__device__ __half2 g_t2h  [Bn*(CMn/2)*Pn + 512]; // dw2 out, channel-paired
__device__ __half2 g_wqh[(Cn/2)*Cn];             // weights k-paired [k/2][m]
__device__ __half2 g_wkh[(Cn/2)*Cn];
__device__ __half2 g_wvh[(Cn/2)*Cn];
__device__ __half2 g_woh[(Cn/2)*Cn];
__device__ __half2 g_c1h[(Cn/2)*CMn];
__device__ __half2 g_c2h[(CMn/2)*Cn];
__device__ float   g_sq [Cn];                    // rowsum(wq)
__device__ float   g_sc1[CMn];                   // rowsum(c1_w)
__device__ float2  g_partl[Bn*(Cn/2)];           // LN1 partials (per pair-plane)
__device__ float2  g_parto[Bn*14];               // LN2 partials

__device__ __forceinline__ float gelu_f(float v) {
    return 0.5f * v * (1.0f + erff(v * 0.7071067811865475f));
}
__device__ __forceinline__ void mma_f16(float* c, const uint32_t* a, const uint32_t* b) {
    asm volatile(
        "mma.sync.aligned.m16n8k16.row.col.f32.f16.f16.f32 "
        "{%0,%1,%2,%3}, {%4,%5,%6,%7}, {%8,%9}, {%0,%1,%2,%3};"
        : "+f"(c[0]), "+f"(c[1]), "+f"(c[2]), "+f"(c[3])
        : "r"(a[0]), "r"(a[1]), "r"(a[2]), "r"(a[3]), "r"(b[0]), "r"(b[1]));
}
__device__ __forceinline__ uint32_t packh2(float lo, float hi) {
    __half2 h = __floats2half2_rn(lo, hi);
    return *(uint32_t*)&h;
}

#define H2STR 136
#define KSTR  132
#define STAGE (32*H2STR)
#define SMEM_MMA (2*STAGE*4)   // 34816 B

// ====================== k_mma (256 thr, 128x128 — proven config) ======================
// BK 1: B = half2 k-paired [k/2][P] raw
// BK 2: B = flat __half [k][P] (channel rows), interleave via byte_perm
// MODE 1: f32 out[p*M+m] = acc + bias + res; +flat fp16 mirror xmir; LN2 partials -> pstat
// MODE 2: half2 out[(m/2)*P+p] = gelu(BN(acc*rstd + cb - mean*rstd*S)); mean/rstd reduced
//         in-kernel from pstat (14 partials per batch)
// MODE 3: f32 out[m*P+p] = BN(acc + bias) + res
template <int MODE, int BK>
__global__ void __launch_bounds__(256, 2) k_mma(
    const __half2* __restrict__ Wh, const void* __restrict__ Xv,
    const float* __restrict__ bias,
    const float* __restrict__ bng, const float* __restrict__ bnb,
    const float* __restrict__ bnm, const float* __restrict__ bnv,
    const float* __restrict__ rsum,
    const float* __restrict__ res, float2* __restrict__ pstat,
    __half* __restrict__ xmir,
    void* __restrict__ outv, int M, int K, int P) {
    extern __shared__ float sm[];
    const int tid  = threadIdx.x;
    const int warp = tid >> 5, lane = tid & 31;
    const int gid = lane >> 2, tq = lane & 3;
    const int wm = (warp & 1) * 64;
    const int wn = (warp >> 1) * 32;
    const int b  = blockIdx.z;
    const int m0 = blockIdx.y * 128;
    const int n0 = blockIdx.x * 128;
    const __half2* Xh2 = (BK == 1) ? (const __half2*)Xv + (size_t)b * (K >> 1) * P : nullptr;
    const __half*  Xhf = (BK == 2) ? (const __half*)Xv + (size_t)b * K * P : nullptr;

    float acc[4][4][4];
#pragma unroll
    for (int i = 0; i < 4; i++)
#pragma unroll
        for (int j = 0; j < 4; j++)
#pragma unroll
            for (int r = 0; r < 4; r++) acc[i][j][r] = 0.f;

    const int kk = tid >> 4;
    const int mq = (tid & 15) * 8;
    uint4 pa0, pa1, pb0, pb1;
    const int T = K >> 5;

    auto load_chunk = [&](int kc0) {
        const uint4* wr = (const uint4*)(Wh + (size_t)((kc0 >> 1) + kk) * M + m0 + mq);
        pa0 = wr[0]; pa1 = wr[1];
        if (BK == 1) {
            const uint4* xr = (const uint4*)(Xh2 + (size_t)((kc0 >> 1) + kk) * P + n0 + mq);
            pb0 = xr[0]; pb1 = xr[1];
        } else {
            const uint4 r0 = *(const uint4*)(Xhf + (size_t)(kc0 + 2 * kk) * P + n0 + mq);
            const uint4 r1 = *(const uint4*)(Xhf + (size_t)(kc0 + 2 * kk + 1) * P + n0 + mq);
            pb0 = make_uint4(__byte_perm(r0.x, r1.x, 0x5410), __byte_perm(r0.x, r1.x, 0x7632),
                             __byte_perm(r0.y, r1.y, 0x5410), __byte_perm(r0.y, r1.y, 0x7632));
            pb1 = make_uint4(__byte_perm(r0.z, r1.z, 0x5410), __byte_perm(r0.z, r1.z, 0x7632),
                             __byte_perm(r0.w, r1.w, 0x5410), __byte_perm(r0.w, r1.w, 0x7632));
        }
    };
    auto store_chunk = [&](int s) {
        __half2* As2 = (__half2*)sm + s * STAGE;
        __half2* Bs2 = As2 + 16 * H2STR;
        *(uint4*)&As2[kk * H2STR + mq]     = pa0;
        *(uint4*)&As2[kk * H2STR + mq + 4] = pa1;
        *(uint4*)&Bs2[kk * H2STR + mq]     = pb0;
        *(uint4*)&Bs2[kk * H2STR + mq + 4] = pb1;
    };

    load_chunk(0);
    store_chunk(0);
    __syncthreads();

    for (int t = 0; t < T; t++) {
        if (t + 1 < T) load_chunk((t + 1) << 5);
        const __half2* As2 = (const __half2*)sm + (t & 1) * STAGE;
        const __half2* Bs2 = As2 + 16 * H2STR;
#pragma unroll
        for (int ks = 0; ks < 2; ks++) {
            const int r0 = ks * 8;
            uint32_t af[4][4], bf[4][2];
#pragma unroll
            for (int i = 0; i < 4; i++) {
                int m = wm + i * 16 + gid;
                af[i][0] = *(uint32_t*)&As2[(r0 + tq) * H2STR + m];
                af[i][1] = *(uint32_t*)&As2[(r0 + tq) * H2STR + m + 8];
                af[i][2] = *(uint32_t*)&As2[(r0 + tq + 4) * H2STR + m];
                af[i][3] = *(uint32_t*)&As2[(r0 + tq + 4) * H2STR + m + 8];
            }
#pragma unroll
            for (int j = 0; j < 4; j++) {
                int p = wn + j * 8 + gid;
                bf[j][0] = *(uint32_t*)&Bs2[(r0 + tq) * H2STR + p];
                bf[j][1] = *(uint32_t*)&Bs2[(r0 + tq + 4) * H2STR + p];
            }
#pragma unroll
            for (int i = 0; i < 4; i++)
#pragma unroll
                for (int j = 0; j < 4; j++) mma_f16(acc[i][j], af[i], bf[j]);
        }
        if (t + 1 < T) {
            store_chunk((t + 1) & 1);
            __syncthreads();
        }
    }

    // LN scalars for MODE 2: reduce the 14 per-batch partials in-kernel (fixed tree)
    float mean = 0.f, rstd = 1.f;
    if (MODE == 2) {
        __syncthreads();
        if (tid < 32) {
            float2 p = (tid < 14) ? pstat[b * 14 + tid] : make_float2(0.f, 0.f);
#pragma unroll
            for (int o = 16; o >= 1; o >>= 1) {
                p.x += __shfl_down_sync(0xffffffffu, p.x, o);
                p.y += __shfl_down_sync(0xffffffffu, p.y, o);
            }
            if (tid == 0) {
                const float n = (float)(Cn * Pn);
                float m  = p.x / n;
                float vv = p.y / n - m * m;
                sm[0] = m;
                sm[1] = rsqrtf(vv + EPSf);
            }
        }
        __syncthreads();
        mean = sm[0]; rstd = sm[1];
    }

    // ---- epilogue: two 64-row passes staged through smem ----
    float* sD = sm;
    float*   outf  = (MODE == 1 || MODE == 3) ? (float*)outv + (size_t)b * (size_t)M * P : nullptr;
    __half2* outh2 = (MODE == 2) ? (__half2*)outv + (size_t)b * (size_t)(M >> 1) * P : nullptr;
    __half*  xmb   = (MODE == 1) ? xmir + (size_t)b * (size_t)M * P : nullptr;
    const float* resb = (MODE == 1 || MODE == 3) ? res + (size_t)b * (size_t)M * P : nullptr;
    float osum = 0.f, osq = 0.f;

#pragma unroll
    for (int pass = 0; pass < 2; pass++) {
        __syncthreads();
        if (MODE == 1) {
            if ((wn >> 6) == pass) {
#pragma unroll
                for (int i = 0; i < 4; i++) {
                    int mrow = wm + i * 16 + gid;
#pragma unroll
                    for (int j = 0; j < 4; j++) {
                        int pc = (wn & 63) + j * 8 + 2 * tq;
                        sD[pc * KSTR + mrow]           = acc[i][j][0];
                        sD[(pc + 1) * KSTR + mrow]     = acc[i][j][1];
                        sD[pc * KSTR + mrow + 8]       = acc[i][j][2];
                        sD[(pc + 1) * KSTR + mrow + 8] = acc[i][j][3];
                    }
                }
            }
        } else {
            if ((wm >> 6) == pass) {
#pragma unroll
                for (int i = 0; i < 4; i++) {
                    int ml = (wm & 63) + i * 16 + gid;
#pragma unroll
                    for (int j = 0; j < 4; j++) {
                        int pc = wn + j * 8 + 2 * tq;
                        sD[ml * KSTR + pc]           = acc[i][j][0];
                        sD[ml * KSTR + pc + 1]       = acc[i][j][1];
                        sD[(ml + 8) * KSTR + pc]     = acc[i][j][2];
                        sD[(ml + 8) * KSTR + pc + 1] = acc[i][j][3];
                    }
                }
            }
        }
        __syncthreads();
        if (MODE == 1) {
            for (int l = tid; l < 64 * 32; l += 256) {
                int rl = l >> 5, cq = (l & 31) * 4;
                int p = n0 + pass * 64 + rl;
                if (p >= P) continue;
                float4 v = *(float4*)&sD[rl * KSTR + cq];
                float4 bb = *(const float4*)(bias + m0 + cq);
                v.x += bb.x; v.y += bb.y; v.z += bb.z; v.w += bb.w;
                size_t off = (size_t)p * M + m0 + cq;
                float4 rr = *(const float4*)(resb + off);
                v.x += rr.x; v.y += rr.y; v.z += rr.z; v.w += rr.w;
                *(float4*)(outf + off) = v;
                __half2 h01 = __floats2half2_rn(v.x, v.y);
                __half2 h23 = __floats2half2_rn(v.z, v.w);
                *(uint2*)(xmb + off) = make_uint2(*(uint32_t*)&h01, *(uint32_t*)&h23);
                osum += v.x + v.y + v.z + v.w;
                osq  += v.x * v.x + v.y * v.y + v.z * v.z + v.w * v.w;
            }
        } else if (MODE == 2) {
            for (int l = tid; l < 32 * 32; l += 256) {
                int rp = l >> 5, cq = (l & 31) * 4;
                int m = m0 + pass * 64 + 2 * rp;
                int p = n0 + cq;
                if (p >= P) continue;
                float sc0 = bng[m] * rsqrtf(bnv[m] + EPSf);
                float sh0 = bnb[m] - bnm[m] * sc0
                          + (bias[m] - mean * rstd * rsum[m]) * sc0;
                float a0 = rstd * sc0;
                float sc1 = bng[m + 1] * rsqrtf(bnv[m + 1] + EPSf);
                float sh1 = bnb[m + 1] - bnm[m + 1] * sc1
                          + (bias[m + 1] - mean * rstd * rsum[m + 1]) * sc1;
                float a1 = rstd * sc1;
                float4 v0 = *(float4*)&sD[(2 * rp) * KSTR + cq];
                float4 v1 = *(float4*)&sD[(2 * rp + 1) * KSTR + cq];
                v0.x = gelu_f(v0.x * a0 + sh0); v0.y = gelu_f(v0.y * a0 + sh0);
                v0.z = gelu_f(v0.z * a0 + sh0); v0.w = gelu_f(v0.w * a0 + sh0);
                v1.x = gelu_f(v1.x * a1 + sh1); v1.y = gelu_f(v1.y * a1 + sh1);
                v1.z = gelu_f(v1.z * a1 + sh1); v1.w = gelu_f(v1.w * a1 + sh1);
                uint4 u = make_uint4(packh2(v0.x, v1.x), packh2(v0.y, v1.y),
                                     packh2(v0.z, v1.z), packh2(v0.w, v1.w));
                *(uint4*)(outh2 + (size_t)(m >> 1) * P + p) = u;
            }
        } else {
            for (int l = tid; l < 64 * 32; l += 256) {
                int rl = l >> 5, cq = (l & 31) * 4;
                int m = m0 + pass * 64 + rl;
                int p = n0 + cq;
                if (p >= P) continue;
                float scale = bng[m] * rsqrtf(bnv[m] + EPSf);
                float shift = bnb[m] - bnm[m] * scale + bias[m] * scale;
                float4 v = *(float4*)&sD[rl * KSTR + cq];
                v.x = v.x * scale + shift; v.y = v.y * scale + shift;
                v.z = v.z * scale + shift; v.w = v.w * scale + shift;
                size_t off = (size_t)m * P + p;
                float4 rr = *(const float4*)(resb + off);
                v.x += rr.x; v.y += rr.y; v.z += rr.z; v.w += rr.w;
                *(float4*)(outf + off) = v;
            }
        }
    }

    if (MODE == 1) {
        __syncthreads();
        float* r1 = sm;
        float* r2 = sm + 256;
        r1[tid] = osum; r2[tid] = osq;
        __syncthreads();
        for (int st = 128; st > 0; st >>= 1) {
            if (tid < st) { r1[tid] += r1[tid + st]; r2[tid] += r2[tid + st]; }
            __syncthreads();
        }
        if (tid == 0)
            pstat[b * 14 + blockIdx.y * gridDim.x + blockIdx.x] = make_float2(r1[0], r2[0]);
    }
}

// ====================== merged QKV (256 thr; LN1 finisher folded into Q epilogue) ======================
__global__ void __launch_bounds__(256, 2) k_qkv(
    const __half2* __restrict__ wqh, const __half2* __restrict__ wkh,
    const __half2* __restrict__ wvh,
    const __half2* __restrict__ x1h, const __half2* __restrict__ kvh,
    const float* __restrict__ bq, const float* __restrict__ bk,
    const float* __restrict__ bv, const float2* __restrict__ partl,
    const float* __restrict__ sq,
    __half* __restrict__ qh, __half* __restrict__ kh, __half* __restrict__ vh) {
    extern __shared__ float sm[];
    const int tid  = threadIdx.x;
    const int warp = tid >> 5, lane = tid & 31;
    const int gid = lane >> 2, tq = lane & 3;
    const int wm = (warp & 1) * 64;
    const int wn = (warp >> 1) * 32;
    const int b  = blockIdx.z;
    const int id = blockIdx.x;  // 0..21

    const __half2* Wh;
    const __half2* Xh2;
    const float* bias;
    __half* outp;
    int P, m0, n0;
    bool isQ = false;
    if (id < 14) {
        Wh = wqh; Xh2 = x1h + (size_t)b * (Cn / 2) * Pn; bias = bq;
        outp = qh + (size_t)b * Pn * Cn;
        P = Pn; isQ = true; m0 = (id / 7) * 128; n0 = (id % 7) * 128;
    } else if (id < 18) {
        int t = id - 14;
        Wh = wkh; Xh2 = kvh + (size_t)b * (Cn / 2) * NKn; bias = bk;
        outp = kh + (size_t)b * NKn * Cn;
        P = NKn; m0 = (t >> 1) * 128; n0 = (t & 1) * 128;
    } else {
        int t = id - 18;
        Wh = wvh; Xh2 = kvh + (size_t)b * (Cn / 2) * NKn; bias = bv;
        outp = vh + (size_t)b * NKn * Cn;
        P = NKn; m0 = (t >> 1) * 128; n0 = (t & 1) * 128;
    }

    float acc[4][4][4];
#pragma unroll
    for (int i = 0; i < 4; i++)
#pragma unroll
        for (int j = 0; j < 4; j++)
#pragma unroll
            for (int r = 0; r < 4; r++) acc[i][j][r] = 0.f;

    const int kk = tid >> 4;
    const int mq = (tid & 15) * 8;
    uint4 pa0, pa1, pb0, pb1;
    const int T = Cn >> 5;  // 8

    auto load_chunk = [&](int kp0) {
        const uint4* wr = (const uint4*)(Wh + (size_t)(kp0 + kk) * Cn + m0 + mq);
        pa0 = wr[0]; pa1 = wr[1];
        const uint4* xr = (const uint4*)(Xh2 + (size_t)(kp0 + kk) * P + n0 + mq);
        pb0 = xr[0]; pb1 = xr[1];
    };
    auto store_chunk = [&](int s) {
        __half2* As2 = (__half2*)sm + s * STAGE;
        __half2* Bs2 = As2 + 16 * H2STR;
        *(uint4*)&As2[kk * H2STR + mq]     = pa0;
        *(uint4*)&As2[kk * H2STR + mq + 4] = pa1;
        *(uint4*)&Bs2[kk * H2STR + mq]     = pb0;
        *(uint4*)&Bs2[kk * H2STR + mq + 4] = pb1;
    };

    load_chunk(0);
    store_chunk(0);
    __syncthreads();

    for (int t = 0; t < T; t++) {
        if (t + 1 < T) load_chunk((t + 1) << 4);
        const __half2* As2 = (const __half2*)sm + (t & 1) * STAGE;
        const __half2* Bs2 = As2 + 16 * H2STR;
#pragma unroll
        for (int ks = 0; ks < 2; ks++) {
            const int r0 = ks * 8;
            uint32_t af[4][4], bf[4][2];
#pragma unroll
            for (int i = 0; i < 4; i++) {
                int m = wm + i * 16 + gid;
                af[i][0] = *(uint32_t*)&As2[(r0 + tq) * H2STR + m];
                af[i][1] = *(uint32_t*)&As2[(r0 + tq) * H2STR + m + 8];
                af[i][2] = *(uint32_t*)&As2[(r0 + tq + 4) * H2STR + m];
                af[i][3] = *(uint32_t*)&As2[(r0 + tq + 4) * H2STR + m + 8];
            }
#pragma unroll
            for (int j = 0; j < 4; j++) {
                int p = wn + j * 8 + gid;
                bf[j][0] = *(uint32_t*)&Bs2[(r0 + tq) * H2STR + p];
                bf[j][1] = *(uint32_t*)&Bs2[(r0 + tq + 4) * H2STR + p];
            }
#pragma unroll
            for (int i = 0; i < 4; i++)
#pragma unroll
                for (int j = 0; j < 4; j++) mma_f16(acc[i][j], af[i], bf[j]);
        }
        if (t + 1 < T) {
            store_chunk((t + 1) & 1);
            __syncthreads();
        }
    }

    // LN1 finisher folded in: reduce 128 partials (fixed tree, deterministic)
    float scl = 1.f, moff = 0.f;
    if (isQ) {
        __syncthreads();
        if (tid < 128) {
            float2 p = partl[b * 128 + tid];
            sm[tid] = p.x;
            sm[128 + tid] = p.y;
        }
        __syncthreads();
        for (int st = 64; st > 0; st >>= 1) {
            if (tid < st) { sm[tid] += sm[tid + st]; sm[128 + tid] += sm[128 + tid + st]; }
            __syncthreads();
        }
        if (tid == 0) {
            const float n = (float)(Cn * Pn);
            float m  = sm[0] / n;
            float vv = sm[128] / n - m * m;
            sm[0] = m;
            sm[1] = rsqrtf(vv + EPSf);
        }
        __syncthreads();
        float mn = sm[0], rs = sm[1];
        scl = rs; moff = -mn * rs;
    }

    float* sD = sm;
#pragma unroll
    for (int pass = 0; pass < 2; pass++) {
        __syncthreads();
        if ((wn >> 6) == pass) {
#pragma unroll
            for (int i = 0; i < 4; i++) {
                int mrow = wm + i * 16 + gid;
#pragma unroll
                for (int j = 0; j < 4; j++) {
                    int pc = (wn & 63) + j * 8 + 2 * tq;
                    sD[pc * KSTR + mrow]           = acc[i][j][0];
                    sD[(pc + 1) * KSTR + mrow]     = acc[i][j][1];
                    sD[pc * KSTR + mrow + 8]       = acc[i][j][2];
                    sD[(pc + 1) * KSTR + mrow + 8] = acc[i][j][3];
                }
            }
        }
        __syncthreads();
        for (int l = tid; l < 64 * 32; l += 256) {
            int rl = l >> 5, cq = (l & 31) * 4;
            int p = n0 + pass * 64 + rl;
            if (p >= P) continue;
            float4 v = *(float4*)&sD[rl * KSTR + cq];
            float4 bb = *(const float4*)(bias + m0 + cq);
            if (isQ) {
                float4 ss = *(const float4*)(sq + m0 + cq);
                v.x = v.x * scl + bb.x + moff * ss.x;
                v.y = v.y * scl + bb.y + moff * ss.y;
                v.z = v.z * scl + bb.z + moff * ss.z;
                v.w = v.w * scl + bb.w + moff * ss.w;
            } else {
                v.x += bb.x; v.y += bb.y; v.z += bb.z; v.w += bb.w;
            }
            __half2 h01 = __floats2half2_rn(v.x, v.y);
            __half2 h23 = __floats2half2_rn(v.z, v.w);
            uint2 u = make_uint2(*(uint32_t*)&h01, *(uint32_t*)&h23);
            *(uint2*)(outp + (size_t)p * Cn + m0 + cq) = u;
        }
    }
}

// ---------------- merged weight pack + rowsums (one launch) ----------------
__global__ void k_wpack_all(
    const float* __restrict__ wq, const float* __restrict__ wk,
    const float* __restrict__ wv, const float* __restrict__ wo,
    const float* __restrict__ c1w, const float* __restrict__ c2w,
    __half2* __restrict__ oq, __half2* __restrict__ ok,
    __half2* __restrict__ ov, __half2* __restrict__ oo,
    __half2* __restrict__ oc1, __half2* __restrict__ oc2,
    float* __restrict__ sq, float* __restrict__ sc1) {
    __shared__ float t[32][33];
    int id = blockIdx.x;
    int tx = threadIdx.x, ty = threadIdx.y;
    if (id >= 768) {
        int tt = ty * 32 + tx;
        int w = ((id - 768) * 256 + tt) >> 5;    // 0..1279
        int lane = tt & 31;
        const float* row;
        float* outr;
        if (w < Cn) { row = wq + (size_t)w * Cn; outr = sq + w; }
        else        { row = c1w + (size_t)(w - Cn) * Cn; outr = sc1 + (w - Cn); }
        float s = 0.f;
        for (int i = lane; i < Cn; i += 32) s += row[i];
#pragma unroll
        for (int o = 16; o >= 1; o >>= 1) s += __shfl_down_sync(0xffffffffu, s, o);
        if (lane == 0) *outr = s;
        return;
    }
    const float* in;
    __half2* out;
    int M, K, tile;
    if (id < 256) {
        int w = id >> 6; tile = id & 63;
        in  = (w == 0) ? wq : (w == 1) ? wk : (w == 2) ? wv : wo;
        out = (w == 0) ? oq : (w == 1) ? ok : (w == 2) ? ov : oo;
        M = Cn; K = Cn;
    } else if (id < 512) {
        tile = id - 256;
        in = c1w; out = oc1; M = CMn; K = Cn;
    } else {
        tile = id - 512;
        in = c2w; out = oc2; M = Cn; K = CMn;
    }
    int ktiles = K >> 5;
    int m0 = (tile / ktiles) * 32, k0 = (tile % ktiles) * 32;
#pragma unroll
    for (int q = 0; q < 32; q += 8)
        t[ty + q][tx] = in[(size_t)(m0 + ty + q) * K + k0 + tx];
    __syncthreads();
#pragma unroll
    for (int q = 0; q < 2; q++) {
        int kp = ty + q * 8;
        __half2 val = __floats2half2_rn(t[tx][2 * kp], t[tx][2 * kp + 1]);
        out[(size_t)((k0 >> 1) + kp) * M + m0 + tx] = val;
    }
}

// ------- fused pair-LPU: conv+res -> x1 fp32 + x1h pairs; KV -> kvh pairs; LN1 partials -------
__global__ void __launch_bounds__(224) k_lpu2(
    const float* __restrict__ X, const float* __restrict__ w,
    const float* __restrict__ bias,
    const float* __restrict__ wkv, const float* __restrict__ bkv,
    float* __restrict__ x1, __half2* __restrict__ x1h,
    __half2* __restrict__ kvh, float2* __restrict__ partl) {
    __shared__ float sp0[900], sp1[900];
    __shared__ float so0[784], so1[784];
    __shared__ float r1[224], r2[224];
    int bc = blockIdx.x;
    int b  = bc >> 7;          // Cn/2 = 128
    int mp = bc & 127;
    int c0 = 2 * mp;
    const float* xin = X + ((size_t)b * Cn + c0) * Pn;
    int tid = threadIdx.x;
    for (int i = tid; i < 900; i += 224) { sp0[i] = 0.f; sp1[i] = 0.f; }
    float wa[9], wb[9];
#pragma unroll
    for (int i = 0; i < 9; i++) { wa[i] = w[c0 * 9 + i]; wb[i] = w[(c0 + 1) * 9 + i]; }
    float bs0 = bias[c0], bs1 = bias[c0 + 1];
    __syncthreads();
    for (int i = tid; i < Pn; i += 224) {
        int o = (i / 28 + 1) * 30 + (i % 28) + 1;
        sp0[o] = xin[i];
        sp1[o] = xin[Pn + i];
    }
    __syncthreads();
    float lsum = 0.f, lsq = 0.f;
    if (tid < 196) {
        int px = tid % 28, sy = (tid / 28) * 4;
        float a0[6][3], a1[6][3];
#pragma unroll
        for (int dr = 0; dr < 6; dr++) {
            int base = (sy + dr) * 30 + px;
            a0[dr][0] = sp0[base]; a0[dr][1] = sp0[base + 1]; a0[dr][2] = sp0[base + 2];
            a1[dr][0] = sp1[base]; a1[dr][1] = sp1[base + 1]; a1[dr][2] = sp1[base + 2];
        }
        float* ob = x1 + ((size_t)b * Cn + c0) * Pn;
        __half2* oh = x1h + ((size_t)b * (Cn / 2) + mp) * Pn;
#pragma unroll
        for (int i = 0; i < 4; i++) {
            float acc0 = bs0
                + wa[0] * a0[i][0]     + wa[1] * a0[i][1]     + wa[2] * a0[i][2]
                + wa[3] * a0[i + 1][0] + wa[4] * a0[i + 1][1] + wa[5] * a0[i + 1][2]
                + wa[6] * a0[i + 2][0] + wa[7] * a0[i + 2][1] + wa[8] * a0[i + 2][2];
            float acc1 = bs1
                + wb[0] * a1[i][0]     + wb[1] * a1[i][1]     + wb[2] * a1[i][2]
                + wb[3] * a1[i + 1][0] + wb[4] * a1[i + 1][1] + wb[5] * a1[i + 1][2]
                + wb[6] * a1[i + 2][0] + wb[7] * a1[i + 2][1] + wb[8] * a1[i + 2][2];
            float y0 = acc0 + a0[i + 1][1];
            float y1 = acc1 + a1[i + 1][1];
            int p = (sy + i) * 28 + px;
            so0[p] = y0; so1[p] = y1;
            ob[p] = y0; ob[Pn + p] = y1;
            oh[p] = __floats2half2_rn(y0, y1);
            lsum += y0 + y1; lsq += y0 * y0 + y1 * y1;
        }
    }
    r1[tid] = lsum; r2[tid] = lsq;
    __syncthreads();
    for (int st = 112; st >= 7; st >>= 1) {
        if (tid < st) { r1[tid] += r1[tid + st]; r2[tid] += r2[tid + st]; }
        __syncthreads();
    }
    if (tid == 0) {
        float s = 0.f, qv = 0.f;
#pragma unroll
        for (int i = 0; i < 7; i++) { s += r1[i]; qv += r2[i]; }
        partl[bc] = make_float2(s, qv);
    }
    if (tid < 196) {
        int oy = tid / HKn, ox = tid % HKn;
        int i00 = (2 * oy) * 28 + 2 * ox;
        float k0 = bkv[c0]
            + wkv[c0 * 4 + 0] * so0[i00]      + wkv[c0 * 4 + 1] * so0[i00 + 1]
            + wkv[c0 * 4 + 2] * so0[i00 + 28] + wkv[c0 * 4 + 3] * so0[i00 + 29];
        float k1 = bkv[c0 + 1]
            + wkv[(c0 + 1) * 4 + 0] * so1[i00]      + wkv[(c0 + 1) * 4 + 1] * so1[i00 + 1]
            + wkv[(c0 + 1) * 4 + 2] * so1[i00 + 28] + wkv[(c0 + 1) * 4 + 3] * so1[i00 + 29];
        kvh[((size_t)b * (Cn / 2) + mp) * NKn + tid] = __floats2half2_rn(k0, k1);
    }
}

// ---------------- dw2: channel-pair fp16 in/out ----------------
__global__ void __launch_bounds__(224) k_dw2pair(
    const __half2* __restrict__ X2, const float* __restrict__ w,
    const float* __restrict__ bias,
    const float* __restrict__ bng, const float* __restrict__ bnb,
    const float* __restrict__ bnm, const float* __restrict__ bnv,
    __half2* __restrict__ out2) {
    __shared__ float sp0[900], sp1[900];
    int bc = blockIdx.x;
    int b  = bc >> 9;
    int mp = bc & 511;
    int c0 = 2 * mp;
    const __half2* x0 = X2 + ((size_t)b * (CMn / 2) + mp) * Pn;
    int tid = threadIdx.x;
    for (int i = tid; i < 900; i += 224) { sp0[i] = 0.f; sp1[i] = 0.f; }
    float wa[9], wb[9];
#pragma unroll
    for (int i = 0; i < 9; i++) { wa[i] = w[c0 * 9 + i]; wb[i] = w[(c0 + 1) * 9 + i]; }
    float bs0 = bias[c0], bs1 = bias[c0 + 1];
    float sc0 = bng[c0] * rsqrtf(bnv[c0] + EPSf);
    float sh0 = bnb[c0] - bnm[c0] * sc0;
    float sc1 = bng[c0 + 1] * rsqrtf(bnv[c0 + 1] + EPSf);
    float sh1 = bnb[c0 + 1] - bnm[c0 + 1] * sc1;
    __syncthreads();
    for (int i = tid; i < Pn; i += 224) {
        int o = (i / 28 + 1) * 30 + (i % 28) + 1;
        float2 f = __half22float2(x0[i]);
        sp0[o] = f.x;
        sp1[o] = f.y;
    }
    __syncthreads();
    if (tid < 196) {
        int px = tid % 28, sy = (tid / 28) * 4;
        float a0[6][3], a1[6][3];
#pragma unroll
        for (int dr = 0; dr < 6; dr++) {
            int base = (sy + dr) * 30 + px;
            a0[dr][0] = sp0[base]; a0[dr][1] = sp0[base + 1]; a0[dr][2] = sp0[base + 2];
            a1[dr][0] = sp1[base]; a1[dr][1] = sp1[base + 1]; a1[dr][2] = sp1[base + 2];
        }
        __half2* ob = out2 + ((size_t)b * (CMn / 2) + mp) * Pn;
#pragma unroll
        for (int i = 0; i < 4; i++) {
            float acc0 = bs0
                + wa[0] * a0[i][0]     + wa[1] * a0[i][1]     + wa[2] * a0[i][2]
                + wa[3] * a0[i + 1][0] + wa[4] * a0[i + 1][1] + wa[5] * a0[i + 1][2]
                + wa[6] * a0[i + 2][0] + wa[7] * a0[i + 2][1] + wa[8] * a0[i + 2][2];
            float acc1 = bs1
                + wb[0] * a1[i][0]     + wb[1] * a1[i][1]     + wb[2] * a1[i][2]
                + wb[3] * a1[i + 1][0] + wb[4] * a1[i + 1][1] + wb[5] * a1[i + 1][2]
                + wb[6] * a1[i + 2][0] + wb[7] * a1[i + 2][1] + wb[8] * a1[i + 2][2];
            float y0 = gelu_f(acc0 * sc0 + sh0);
            float y1 = gelu_f(acc1 * sc1 + sh1);
            ob[(sy + i) * 28 + px] = __floats2half2_rn(y0, y1);
        }
    }
}

// ================= fp16 mma attention, 4-chunk online softmax (3 blocks/SM) =================
#define KP_STR 20
#define VP_STR 40

// Process NT key-tiles starting at tile TB with online softmax rescaling. TB must be even.
template <int NT, int TB>
__device__ __forceinline__ void attn_chunk(
    const __half2* Kp, const __half2* Vp,
    const uint32_t (&aq)[2][4],
    const float* posA, const float* posB,
    float& mA, float& mB, float& lA, float& lB,
    float (&accO)[4][4], int gid, int tq) {
    const float scale = 0.17677669529663687f;
    float accS[NT][4];
#pragma unroll
    for (int jt = 0; jt < NT; jt++)
#pragma unroll
        for (int r = 0; r < 4; r++) accS[jt][r] = 0.f;
#pragma unroll
    for (int jt = 0; jt < NT; jt++) {
        const int row = 8 * (TB + jt) + gid;
#pragma unroll
        for (int kt = 0; kt < 2; kt++) {
            uint32_t bf[2];
            bf[0] = *(uint32_t*)&Kp[row * KP_STR + 8 * kt + tq];
            bf[1] = *(uint32_t*)&Kp[row * KP_STR + 8 * kt + 4 + tq];
            mma_f16(accS[jt], aq[kt], bf);
        }
    }
    float cA = -1e30f, cB = -1e30f;
#pragma unroll
    for (int jt = 0; jt < NT; jt++) {
        int col = 8 * (TB + jt) + 2 * tq;
        if (col < NKn) {
            float2 pA = *(const float2*)(posA + col);
            float2 pB = *(const float2*)(posB + col);
            accS[jt][0] = accS[jt][0] * scale + pA.x;
            accS[jt][1] = accS[jt][1] * scale + pA.y;
            accS[jt][2] = accS[jt][2] * scale + pB.x;
            accS[jt][3] = accS[jt][3] * scale + pB.y;
            cA = fmaxf(cA, fmaxf(accS[jt][0], accS[jt][1]));
            cB = fmaxf(cB, fmaxf(accS[jt][2], accS[jt][3]));
        } else {
            accS[jt][0] = -1e30f; accS[jt][1] = -1e30f;
            accS[jt][2] = -1e30f; accS[jt][3] = -1e30f;
        }
    }
    cA = fmaxf(cA, __shfl_xor_sync(0xffffffffu, cA, 1));
    cA = fmaxf(cA, __shfl_xor_sync(0xffffffffu, cA, 2));
    cB = fmaxf(cB, __shfl_xor_sync(0xffffffffu, cB, 1));
    cB = fmaxf(cB, __shfl_xor_sync(0xffffffffu, cB, 2));
    float nA = fmaxf(mA, cA), nB = fmaxf(mB, cB);
    float corrA = __expf(mA - nA), corrB = __expf(mB - nB);
    mA = nA; mB = nB;
    float eA = 0.f, eB = 0.f;
#pragma unroll
    for (int jt = 0; jt < NT; jt++) {
        accS[jt][0] = __expf(accS[jt][0] - mA);
        accS[jt][1] = __expf(accS[jt][1] - mA);
        accS[jt][2] = __expf(accS[jt][2] - mB);
        accS[jt][3] = __expf(accS[jt][3] - mB);
        eA += accS[jt][0] + accS[jt][1];
        eB += accS[jt][2] + accS[jt][3];
    }
    lA = lA * corrA + eA;
    lB = lB * corrB + eB;
#pragma unroll
    for (int nt = 0; nt < 4; nt++) {
        accO[nt][0] *= corrA; accO[nt][1] *= corrA;
        accO[nt][2] *= corrB; accO[nt][3] *= corrB;
    }
#pragma unroll
    for (int kt = 0; kt < NT / 2; kt++) {
        const int gs = (TB >> 1) + kt;
        uint32_t pa[4];
        pa[0] = packh2(accS[2 * kt][0],     accS[2 * kt][1]);
        pa[1] = packh2(accS[2 * kt][2],     accS[2 * kt][3]);
        pa[2] = packh2(accS[2 * kt + 1][0], accS[2 * kt + 1][1]);
        pa[3] = packh2(accS[2 * kt + 1][2], accS[2 * kt + 1][3]);
#pragma unroll
        for (int nt = 0; nt < 4; nt++) {
            uint32_t bf[2];
            bf[0] = *(uint32_t*)&Vp[(8 * gs + tq) * VP_STR + 8 * nt + gid];
            bf[1] = *(uint32_t*)&Vp[(8 * gs + 4 + tq) * VP_STR + 8 * nt + gid];
            mma_f16(accO[nt], pa, bf);
        }
    }
}

__global__ void __launch_bounds__(224, 3) k_attn_mma(
    const __half* __restrict__ q, const __half* __restrict__ k,
    const __half* __restrict__ v, const float* __restrict__ pos,
    __half2* __restrict__ outT2) {
    __shared__ __half2 Kp[208 * KP_STR];
    __shared__ __half2 Vp[104 * VP_STR];
    const int tid = threadIdx.x;
    const int warp = tid >> 5, lane = tid & 31;
    const int gid = lane >> 2, tq = lane & 3;
    const int qt = blockIdx.x;
    const int h  = blockIdx.y;
    const int b  = blockIdx.z;
    const int hoff = h * DKn;

    for (int idx = tid; idx < 208 * 16; idx += 224) {
        int key = idx >> 4, e = idx & 15;
        __half2 val = __floats2half2_rn(0.f, 0.f);
        if (key < NKn)
            val = *(const __half2*)(k + ((size_t)(b * NKn + key)) * Cn + hoff + 2 * e);
        Kp[key * KP_STR + e] = val;
    }
    for (int idx = tid; idx < 104 * 32; idx += 224) {
        int kp = idx >> 5, dv = idx & 31;
        int k0 = 2 * kp, k1 = 2 * kp + 1;
        __half f0 = (k0 < NKn) ? v[((size_t)(b * NKn + k0)) * Cn + hoff + dv] : __float2half(0.f);
        __half f1 = (k1 < NKn) ? v[((size_t)(b * NKn + k1)) * Cn + hoff + dv] : __float2half(0.f);
        Vp[kp * VP_STR + dv] = __halves2half2(f0, f1);
    }
    __syncthreads();

    const int iA = qt * 112 + warp * 16 + gid;

    uint32_t aq[2][4];
    {
        const __half* q0 = q + ((size_t)(b * Pn + iA)) * Cn + hoff;
        const __half* q1 = q0 + 8 * Cn;
#pragma unroll
        for (int kt = 0; kt < 2; kt++) {
            aq[kt][0] = *(const uint32_t*)(q0 + 16 * kt + 2 * tq);
            aq[kt][1] = *(const uint32_t*)(q1 + 16 * kt + 2 * tq);
            aq[kt][2] = *(const uint32_t*)(q0 + 16 * kt + 8 + 2 * tq);
            aq[kt][3] = *(const uint32_t*)(q1 + 16 * kt + 8 + 2 * tq);
        }
    }

    const float* posA = pos + ((size_t)(h * Pn + iA)) * NKn;
    const float* posB = posA + 8 * NKn;
    float mA = -1e30f, mB = -1e30f, lA = 0.f, lB = 0.f;
    float accO[4][4];
#pragma unroll
    for (int nt = 0; nt < 4; nt++)
#pragma unroll
        for (int r = 0; r < 4; r++) accO[nt][r] = 0.f;

    attn_chunk<8, 0>(Kp, Vp, aq, posA, posB, mA, mB, lA, lB, accO, gid, tq);
    attn_chunk<6, 8>(Kp, Vp, aq, posA, posB, mA, mB, lA, lB, accO, gid, tq);
    attn_chunk<6, 14>(Kp, Vp, aq, posA, posB, mA, mB, lA, lB, accO, gid, tq);
    attn_chunk<6, 20>(Kp, Vp, aq, posA, posB, mA, mB, lA, lB, accO, gid, tq);

    lA += __shfl_xor_sync(0xffffffffu, lA, 1);
    lA += __shfl_xor_sync(0xffffffffu, lA, 2);
    lB += __shfl_xor_sync(0xffffffffu, lB, 1);
    lB += __shfl_xor_sync(0xffffffffu, lB, 2);

    float invA = 1.f / lA, invB = 1.f / lB;
    __half2* ob = outT2 + ((size_t)(b * (Cn / 2) + (hoff >> 1))) * Pn;
#pragma unroll
    for (int nt = 0; nt < 4; nt++) {
        int dvp = 4 * nt + tq;
        ob[(size_t)dvp * Pn + iA]     = __floats2half2_rn(accO[nt][0] * invA, accO[nt][1] * invA);
        ob[(size_t)dvp * Pn + iA + 8] = __floats2half2_rn(accO[nt][2] * invB, accO[nt][3] * invB);
    }
}

// ---------------- host launch ----------------
static void* sym_addr(const void* symbol) {
    void* p = nullptr;
    cudaGetSymbolAddress(&p, symbol);
    return p;
}

extern "C" void kernel_launch(void* const* d_in, const int* in_sizes, int n_in,
                              void* d_out, int out_size) {
    const float* x     = (const float*)d_in[0];
    const float* lpu_w = (const float*)d_in[1];
    const float* lpu_b = (const float*)d_in[2];
    const float* dw_w  = (const float*)d_in[3];
    const float* dw_b  = (const float*)d_in[4];
    const float* wq    = (const float*)d_in[5];
    const float* bq    = (const float*)d_in[6];
    const float* wk    = (const float*)d_in[7];
    const float* bk    = (const float*)d_in[8];
    const float* wv    = (const float*)d_in[9];
    const float* bv    = (const float*)d_in[10];
    const float* wo    = (const float*)d_in[11];
    const float* bo    = (const float*)d_in[12];
    const float* pos_b = (const float*)d_in[13];
    const float* c1_w  = (const float*)d_in[14];
    const float* c1_b  = (const float*)d_in[15];
    const float* bn1_g = (const float*)d_in[16];
    const float* bn1_b = (const float*)d_in[17];
    const float* bn1_m = (const float*)d_in[18];
    const float* bn1_v = (const float*)d_in[19];
    const float* dw2_w = (const float*)d_in[20];
    const float* dw2_b = (const float*)d_in[21];
    const float* bn2_g = (const float*)d_in[22];
    const float* bn2_b = (const float*)d_in[23];
    const float* bn2_m = (const float*)d_in[24];
    const float* bn2_v = (const float*)d_in[25];
    const float* c2_w  = (const float*)d_in[26];
    const float* c2_b  = (const float*)d_in[27];
    const float* bn3_g = (const float*)d_in[28];
    const float* bn3_b = (const float*)d_in[29];
    const float* bn3_m = (const float*)d_in[30];
    const float* bn3_v = (const float*)d_in[31];
    float* out = (float*)d_out;

    float*   x1    = (float*)sym_addr(g_x1);
    __half2* x1h   = (__half2*)sym_addr(g_x1h);
    __half2* kvh   = (__half2*)sym_addr(g_kvh);
    float*   x2    = (float*)sym_addr(g_x2);
    __half*  x2h   = (__half*)sym_addr(g_x2h);
    __half*  qh    = (__half*)sym_addr(g_qh);
    __half*  kh    = (__half*)sym_addr(g_kh);
    __half*  vh    = (__half*)sym_addr(g_vh);
    __half2* attTh = (__half2*)sym_addr(g_attTh);
    __half2* t1h   = (__half2*)sym_addr(g_t1h);
    __half2* t2h   = (__half2*)sym_addr(g_t2h);
    __half2* wqh   = (__half2*)sym_addr(g_wqh);
    __half2* wkh   = (__half2*)sym_addr(g_wkh);
    __half2* wvh   = (__half2*)sym_addr(g_wvh);
    __half2* woh   = (__half2*)sym_addr(g_woh);
    __half2* c1h   = (__half2*)sym_addr(g_c1h);
    __half2* c2h   = (__half2*)sym_addr(g_c2h);
    float*   sq    = (float*)sym_addr(g_sq);
    float*   sc1   = (float*)sym_addr(g_sc1);
    float2*  partl = (float2*)sym_addr(g_partl);
    float2*  parto = (float2*)sym_addr(g_parto);

    dim3 tb(32, 8);
    // 1. weight packs + rowsums (one launch)
    k_wpack_all<<<928, tb>>>(wq, wk, wv, wo, c1_w, c2_w,
                             wqh, wkh, wvh, woh, c1h, c2h, sq, sc1);
    // 2. fused pair-LPU (+KV fp16 +LN1 partials +x1h)
    k_lpu2<<<Bn * (Cn / 2), 224>>>(x, lpu_w, lpu_b, dw_w, dw_b, x1, x1h, kvh, partl);
    // 3. merged Q/K/V projections (LN1 finisher folded into Q epilogue)
    k_qkv<<<dim3(22, 1, Bn), 256, SMEM_MMA>>>(
        wqh, wkh, wvh, x1h, kvh, bq, bk, bv, partl, sq, qh, kh, vh);
    // 4. attention (4-chunk online softmax, 3 blocks/SM) -> attTh
    k_attn_mma<<<dim3(7, NH, Bn), 224>>>(qh, kh, vh, pos_b, attTh);
    // 5. O projection + flat residual -> x2 fp32 + x2h mirror (+LN2 partials)
    k_mma<1, 1><<<dim3(7, 2, Bn), 256, SMEM_MMA>>>(
        woh, attTh, bo, nullptr, nullptr, nullptr, nullptr, nullptr,
        x1, parto, x2h, x2, Cn, Cn, Pn);
    // 6. c1 + BN1 + GELU (LN2 finisher folded in; LN via rowsum fold) -> t1h
    k_mma<2, 2><<<dim3(7, 8, Bn), 256, SMEM_MMA>>>(
        c1h, x2h, c1_b, bn1_g, bn1_b, bn1_m, bn1_v, sc1,
        nullptr, parto, nullptr, t1h, CMn, Cn, Pn);
    // 7. dw2 + BN2 + GELU -> t2h
    k_dw2pair<<<Bn * (CMn / 2), 224>>>(t1h, dw2_w, dw2_b, bn2_g, bn2_b, bn2_m, bn2_v, t2h);
    // 8. c2 + BN3 + channel-major residual -> d_out
    k_mma<3, 1><<<dim3(7, 2, Bn), 256, SMEM_MMA>>>(
        c2h, t2h, c2_b, bn3_g, bn3_b, bn3_m, bn3_v, nullptr,
        x2, nullptr, nullptr, out, Cn, CMn, Pn);
}